// round 11
// baseline (speedup 1.0000x reference)
#include <cuda_runtime.h>
#include <cuda_bf16.h>
#include <math.h>
#include <stdint.h>

#define B_    8
#define C_    128
#define Hh_   128
#define Ww_   128
#define N_    16384      // H*W
#define HEADS_ 8
#define CH_   16         // C/HEADS
#define HID_  340
#define HID2_ 680
#define C2_   256
#define NCHUNK_ 16
#define CHUNKN_ (N_ / NCHUNK_)   // 1024

// ---------------- static scratch (no allocations allowed) ----------------
__device__ float g_bufCb[(size_t)B_ * C_ * N_];   // qpre path1 / conv1 out
__device__ float g_bufCc[(size_t)B_ * C_ * N_];   // qpre path2
__device__ float g_bufCd[(size_t)B_ * C_ * N_];   // qdw path1
__device__ float g_bufCe[(size_t)B_ * C_ * N_];   // qdw path2
__device__ float g_buf2Ca[(size_t)B_ * C2_ * N_]; // kvpre path1 / concat out
__device__ float g_buf2Cb[(size_t)B_ * C2_ * N_]; // kvpre path2
__device__ float g_buf2Cc[(size_t)B_ * C2_ * N_]; // kvdw path1
__device__ float g_bufHa[(size_t)B_ * HID2_ * N_];// kvdw path2 (front 2C) / ffn hidden
__device__ float g_bufHb[(size_t)B_ * HID_ * N_]; // gated
__device__ float g_xout[(size_t)B_ * C_ * N_];
__device__ float g_mu[2 * B_ * N_];
__device__ float g_inv[2 * B_ * N_];
__device__ float g_attnp[2 * B_ * HEADS_ * NCHUNK_ * 288];
__device__ float g_attnw[2 * B_ * HEADS_ * CH_ * CH_];
__device__ float g_Mw[2 * B_ * C_ * C_];
__device__ float g_pool[B_ * C_];
__device__ float g_cas[B_ * C_];

// packed f32x2 helpers (fallback path)
#define FMA2(d, a, b) asm("fma.rn.f32x2 %0, %1, %2, %0;" : "+l"(d) : "l"(a), "l"(b))
#define UNPK2(lo, hi, s) asm("mov.b64 {%0, %1}, %2;" : "=f"(lo), "=f"(hi) : "l"(s))

// ---------------- PTX helpers ----------------
__device__ __forceinline__ uint32_t smem_u32(const void* p) {
    uint32_t a;
    asm("{ .reg .u64 t; cvta.to.shared.u64 t, %1; cvt.u32.u64 %0, t; }" : "=r"(a) : "l"(p));
    return a;
}
#define SWZ(o) ((o) ^ (((o) >> 3) & 0x70))

#if defined(__CUDA_ARCH_FEAT_SM103_ALL) || !defined(__CUDA_ARCH__)
#define HAS_TC 1
#else
#define HAS_TC 0
#endif

#define MBARRIER_INIT(addr, cnt) \
    asm volatile("mbarrier.init.shared.b64 [%0], %1;" :: "r"((uint32_t)(addr)), "r"((uint32_t)(cnt)) : "memory")
#define MBARRIER_INVAL(addr) \
    asm volatile("mbarrier.inval.shared.b64 [%0];" :: "r"((uint32_t)(addr)) : "memory")
#define MBARRIER_WAIT_PARITY(mbar_smem_addr, phase_parity) do { \
    uint32_t _mbar = (uint32_t)(mbar_smem_addr); \
    uint32_t _parity = (uint32_t)(phase_parity); \
    uint32_t _done; \
    asm volatile("{\n\t.reg .pred p;\n\t" \
        "mbarrier.try_wait.parity.acquire.cta.shared::cta.b64 p, [%1], %2;\n\t" \
        "selp.b32 %0, 1, 0, p;\n\t}" : "=r"(_done) : "r"(_mbar), "r"(_parity) : "memory"); \
    if (!_done) { \
        asm volatile("{\n\t.reg .pred P1;\n\t" \
            "WAIT_LOOP_%=:\n\t" \
            "mbarrier.try_wait.parity.acquire.cta.shared::cta.b64 P1, [%0], %1, 0x989680;\n\t" \
            "@P1 bra.uni WAIT_DONE_%=;\n\t" \
            "bra.uni WAIT_LOOP_%=;\n\t" \
            "WAIT_DONE_%=:\n\t}" :: "r"(_mbar), "r"(_parity) : "memory"); \
    } \
} while (0)

#if HAS_TC
#define TCGEN05_ALLOC(smem_result_addr, nCols) \
    asm volatile("tcgen05.alloc.cta_group::1.sync.aligned.shared::cta.b32 [%0], %1;" \
        :: "r"((uint32_t)(smem_result_addr)), "r"((uint32_t)(nCols)) : "memory")
#define TCGEN05_DEALLOC(tmem_addr, nCols) \
    asm volatile("tcgen05.dealloc.cta_group::1.sync.aligned.b32 %0, %1;" :: "r"(tmem_addr), "r"((uint32_t)(nCols)))
#define TCGEN05_RELINQUISH() \
    asm volatile("tcgen05.relinquish_alloc_permit.cta_group::1.sync.aligned;")
#define TCGEN05_COMMIT(mbar_smem_addr) \
    asm volatile("tcgen05.commit.cta_group::1.mbarrier::arrive::one.shared::cluster.b64 [%0];" \
        :: "r"((uint32_t)(mbar_smem_addr)) : "memory")
#define TCGEN05_FENCE_AFTER() asm volatile("tcgen05.fence::after_thread_sync;" ::: "memory")
#define TCGEN05_FENCE_BEFORE() asm volatile("tcgen05.fence::before_thread_sync;" ::: "memory")
#define TCGEN05_WAIT_LD() asm volatile("tcgen05.wait::ld.sync.aligned;" ::: "memory")
#define FENCE_ASYNC_SHARED() asm volatile("fence.proxy.async.shared::cta;" ::: "memory")

#define TCGEN05_LD_32X32B_X32(r, tmem_addr) \
    asm volatile( \
        "tcgen05.ld.sync.aligned.32x32b.x32.b32 " \
        "{%0, %1, %2, %3, %4, %5, %6, %7, " \
        " %8, %9, %10, %11, %12, %13, %14, %15, " \
        " %16, %17, %18, %19, %20, %21, %22, %23, " \
        " %24, %25, %26, %27, %28, %29, %30, %31}, [%32];" \
        : "=r"((r)[0]),  "=r"((r)[1]),  "=r"((r)[2]),  "=r"((r)[3]), \
          "=r"((r)[4]),  "=r"((r)[5]),  "=r"((r)[6]),  "=r"((r)[7]), \
          "=r"((r)[8]),  "=r"((r)[9]),  "=r"((r)[10]), "=r"((r)[11]), \
          "=r"((r)[12]), "=r"((r)[13]), "=r"((r)[14]), "=r"((r)[15]), \
          "=r"((r)[16]), "=r"((r)[17]), "=r"((r)[18]), "=r"((r)[19]), \
          "=r"((r)[20]), "=r"((r)[21]), "=r"((r)[22]), "=r"((r)[23]), \
          "=r"((r)[24]), "=r"((r)[25]), "=r"((r)[26]), "=r"((r)[27]), \
          "=r"((r)[28]), "=r"((r)[29]), "=r"((r)[30]), "=r"((r)[31]) \
        : "r"(tmem_addr))

// SW128 SMEM descriptor (LBO=1, SBO=64, version=1, layout=SW128)
__device__ __forceinline__ uint64_t make_desc(uint32_t addr) {
    const uint64_t base = (uint64_t(2) << 61) | (uint64_t(1) << 46)
                        | (uint64_t(64) << 32) | (uint64_t(1) << 16);
    return base | ((uint64_t)(addr >> 4) & 0x3FFF);
}

// bf16 SS MMA, cg1: D[M=128, N=128] += A[M,K=16] * B[N,K=16]^T
#define MMA_IDESC 0x8200490u
__device__ __forceinline__ void mma_bf16_ss(uint32_t d, uint64_t ad, uint64_t bd, uint32_t en) {
    asm volatile(
        "{\n\t.reg .pred p;\n\tsetp.ne.u32 p, %5, 0;\n\t"
        "tcgen05.mma.cta_group::1.kind::f16 [%0], %1, %2, %3, {%4, %4, %4, %4}, p;\n\t}"
        :: "r"(d), "l"(ad), "l"(bd), "r"(MMA_IDESC), "r"(0u), "r"(en) : "memory");
}
#endif  // HAS_TC

// dynamic smem layout (bytes) — SINGLE tile buffer -> 2 CTAs/SM
#define SM_TMEM   0
#define SM_MBAR   16           // 1 mbarrier @16
#define SM_XS     64           // fp32 staging: 64 x 132 floats = 33792 B
#define SM_TILES  34816        // 1024-aligned; AHI,ALO,BHI,BLO @16KB each
#define SM_TOTAL  (SM_TILES + 65536)   // 100352 B

// truncation-based hi/lo bf16 split, packed pairs via PRMT
__device__ __forceinline__ uint32_t prmt_hi(uint32_t u0, uint32_t u1) {
    uint32_t r;
    asm("prmt.b32 %0, %1, %2, 0x7632;" : "=r"(r) : "r"(u0), "r"(u1));
    return r;
}
__device__ __forceinline__ void split2(float x0, float x1, uint32_t& hp, uint32_t& lp) {
    uint32_t u0 = __float_as_uint(x0), u1 = __float_as_uint(x1);
    hp = prmt_hi(u0, u1);
    float l0 = x0 - __uint_as_float(u0 & 0xFFFF0000u);
    float l1 = x1 - __uint_as_float(u1 & 0xFFFF0000u);
    lp = prmt_hi(__float_as_uint(l0), __float_as_uint(l1));
}

// ---------------- GEMM: Y[b, Yoff+o, p] = sum_c W[o,c] LN?(X[b,c,p]) ----------------
// flags: 1=residual add, 2=nan_to_num, 4=apply LN to X on load
__global__ void __launch_bounds__(256)
gemmtc(const float* __restrict__ W1, const float* __restrict__ X1,
       float* __restrict__ Y1, const float* __restrict__ R1,
       const float* __restrict__ W2, const float* __restrict__ X2,
       float* __restrict__ Y2, const float* __restrict__ R2,
       const float* __restrict__ lnMu, const float* __restrict__ lnInv,
       const float* __restrict__ lnW1, const float* __restrict__ lnB1,
       const float* __restrict__ lnW2, const float* __restrict__ lnB2,
       int Cout, int Cin, int XCtot, int YCtot, int Yoff1, int Yoff2,
       int flags, int WstrideB)
{
    extern __shared__ __align__(1024) char smem[];

    const int bz = blockIdx.z;
    const int pth = bz >= B_;
    const int b = pth ? bz - B_ : bz;
    const int o0 = blockIdx.y * 128;
    const int p0 = blockIdx.x * 128;
    const float* Wb = (pth ? W2 : W1) + (size_t)b * WstrideB;
    const float* Xb = (pth ? X2 : X1) + (size_t)b * XCtot * N_;
    float* Y = pth ? Y2 : Y1;
    const float* R = pth ? R2 : R1;
    const float* lnW = pth ? lnW2 : lnW1;
    const float* lnB = pth ? lnB2 : lnB1;
    const int Yoff = pth ? Yoff2 : Yoff1;
    const int lnOn = flags & 4;
    const int tid = threadIdx.x;

#if HAS_TC && defined(__CUDA_ARCH__)
    // ================= tcgen05 path (sm_103a cubin) =================
    const uint32_t sb = smem_u32(smem);
    const int wid = tid >> 5;

    if (tid == 0) MBARRIER_INIT(sb + SM_MBAR, 1);
    if (wid == 0) TCGEN05_ALLOC(sb + SM_TMEM, 128);
    __syncthreads();
    uint32_t tmem;
    asm volatile("ld.shared.b32 %0, [%1];" : "=r"(tmem) : "r"(sb + SM_TMEM));

    const int nch = (Cin + 63) >> 6;
    int ph = 0;
    uint32_t en = 0;

    float* xs = (float*)(smem + SM_XS);
    char* abase = smem + SM_TILES;
    char* albase = abase + 16384;
    char* bbase = abase + 32768;
    char* blbase = abase + 49152;

    for (int ch = 0; ch < nch; ++ch) {
        const int k0 = ch << 6;
        if (ch > 0) { MBARRIER_WAIT_PARITY(sb + SM_MBAR, ph); ph ^= 1; }

        // ---- stage A (W): 128 rows x 64 k, hi/lo bf16, SW128 ----
        {
            int r = tid >> 1;
            int kh = (tid & 1) << 5;
            int o = o0 + r;
            bool fast = (o < Cout) && (k0 + kh + 31 < Cin);
            #pragma unroll
            for (int i = 0; i < 8; ++i) {
                int kk = k0 + kh + i * 4;
                float4 v;
                if (fast) v = *(const float4*)&Wb[(size_t)o * Cin + kk];
                else {
                    v.x = (o < Cout && kk + 0 < Cin) ? Wb[(size_t)o * Cin + kk + 0] : 0.f;
                    v.y = (o < Cout && kk + 1 < Cin) ? Wb[(size_t)o * Cin + kk + 1] : 0.f;
                    v.z = (o < Cout && kk + 2 < Cin) ? Wb[(size_t)o * Cin + kk + 2] : 0.f;
                    v.w = (o < Cout && kk + 3 < Cin) ? Wb[(size_t)o * Cin + kk + 3] : 0.f;
                }
                uint32_t hp0, lp0, hp1, lp1;
                split2(v.x, v.y, hp0, lp0);
                split2(v.z, v.w, hp1, lp1);
                uint32_t off = SWZ((uint32_t)(r * 128 + (kh + i * 4) * 2));
                *(uint2*)(abase + off) = make_uint2(hp0, hp1);
                *(uint2*)(albase + off) = make_uint2(lp0, lp1);
            }
        }

        // ---- stage B phase 1: X [64 k][128 p] fp32 -> Xs (LN applied) ----
        {
            int kr = tid >> 2;
            int pc = (tid & 3) << 5;
            int kk = k0 + kr;
            float* xrow = xs + kr * 132 + pc;
            if (kk < Cin) {
                const float* src = Xb + (size_t)kk * N_ + p0 + pc;
                if (lnOn) {
                    float wv = lnW[kk], bv = lnB[kk];
                    #pragma unroll
                    for (int i = 0; i < 8; ++i) {
                        float4 v = *(const float4*)&src[i * 4];
                        float4 m  = *(const float4*)&lnMu[(size_t)bz * N_ + p0 + pc + i * 4];
                        float4 iv = *(const float4*)&lnInv[(size_t)bz * N_ + p0 + pc + i * 4];
                        v.x = (v.x - m.x) * iv.x * wv + bv;
                        v.y = (v.y - m.y) * iv.y * wv + bv;
                        v.z = (v.z - m.z) * iv.z * wv + bv;
                        v.w = (v.w - m.w) * iv.w * wv + bv;
                        *(float4*)&xrow[i * 4] = v;
                    }
                } else {
                    #pragma unroll
                    for (int i = 0; i < 8; ++i)
                        *(float4*)&xrow[i * 4] = *(const float4*)&src[i * 4];
                }
            } else {
                #pragma unroll
                for (int i = 0; i < 8; ++i)
                    *(float4*)&xrow[i * 4] = make_float4(0.f, 0.f, 0.f, 0.f);
            }
        }
        __syncthreads();

        // ---- stage B phase 2: transpose + convert -> B[n][k] hi/lo bf16 SW128 ----
        {
            int n = tid & 127;
            int half = tid >> 7;
            #pragma unroll
            for (int g = 0; g < 4; ++g) {
                uint32_t hw[4], lw[4];
                #pragma unroll
                for (int q = 0; q < 4; ++q) {
                    int k1 = half * 32 + g * 8 + q * 2;
                    split2(xs[(k1 + 0) * 132 + n], xs[(k1 + 1) * 132 + n], hw[q], lw[q]);
                }
                uint32_t off = SWZ((uint32_t)(n * 128 + half * 64 + g * 16));
                *(uint4*)(bbase + off) = make_uint4(hw[0], hw[1], hw[2], hw[3]);
                *(uint4*)(blbase + off) = make_uint4(lw[0], lw[1], lw[2], lw[3]);
            }
        }
        FENCE_ASYNC_SHARED();
        __syncthreads();

        // ---- issue MMAs for this chunk ----
        if (tid == 0) {
            uint64_t ah = make_desc(sb + SM_TILES);
            uint64_t al = ah + (16384 >> 4);
            uint64_t bh = ah + (32768 >> 4);
            uint64_t bl = ah + (49152 >> 4);
            #pragma unroll
            for (int s = 0; s < 4; ++s) {
                uint64_t ofs = s * 2;
                mma_bf16_ss(tmem, ah + ofs, bh + ofs, en); en = 1;
                mma_bf16_ss(tmem, ah + ofs, bl + ofs, 1);
                mma_bf16_ss(tmem, al + ofs, bh + ofs, 1);
            }
            TCGEN05_COMMIT(sb + SM_MBAR);
        }
    }

    // ---- drain ----
    MBARRIER_WAIT_PARITY(sb + SM_MBAR, ph);
    TCGEN05_FENCE_AFTER();

    // ---- epilogue: warps 0-3 read TMEM D and store ----
    const int doResid = flags & 1, doFinal = flags & 2;
    if (tid < 128) {
        int w = tid >> 5, l = tid & 31;
        int o = o0 + w * 32 + l;
        #pragma unroll
        for (int g = 0; g < 4; ++g) {
            uint32_t dr[32];
            TCGEN05_LD_32X32B_X32(dr, tmem + g * 32);
            TCGEN05_WAIT_LD();
            if (o < Cout) {
                size_t ybase = ((size_t)b * YCtot + Yoff + o) * N_ + p0 + g * 32;
                size_t rbase = ((size_t)b * Cout + o) * N_ + p0 + g * 32;
                #pragma unroll
                for (int q = 0; q < 8; ++q) {
                    float v0 = __uint_as_float(dr[q * 4 + 0]);
                    float v1 = __uint_as_float(dr[q * 4 + 1]);
                    float v2 = __uint_as_float(dr[q * 4 + 2]);
                    float v3 = __uint_as_float(dr[q * 4 + 3]);
                    if (doResid) {
                        float4 r4 = *(const float4*)&R[rbase + q * 4];
                        v0 += r4.x; v1 += r4.y; v2 += r4.z; v3 += r4.w;
                    }
                    if (doFinal) {
                        v0 = isfinite(v0) ? v0 : 1e-5f;
                        v1 = isfinite(v1) ? v1 : 1e-5f;
                        v2 = isfinite(v2) ? v2 : 1e-5f;
                        v3 = isfinite(v3) ? v3 : 1e-5f;
                    }
                    *(float4*)&Y[ybase + q * 4] = make_float4(v0, v1, v2, v3);
                }
            }
        }
        TCGEN05_FENCE_BEFORE();
    }

    __syncthreads();
    if (tid == 0) MBARRIER_INVAL(sb + SM_MBAR);
    __syncthreads();
    if (wid == 0) {
        TCGEN05_RELINQUISH();
        TCGEN05_DEALLOC(tmem, 128);
    }
#else
    // ================= FFMA2 fallback (compute_103 PTX pass) =================
    float2 (*Ws2)[16][128] = (float2(*)[16][128])(smem);            // 32KB
    float  (*Xs)[16][128]  = (float(*)[16][128])(smem + 32768);     // 16KB

    const int tx = tid & 15, ty = tid >> 4;
    unsigned long long acc2[8][4];
    #pragma unroll
    for (int i = 0; i < 8; ++i)
        #pragma unroll
        for (int j = 0; j < 4; ++j) acc2[i][j] = 0ULL;

    const int ktiles = (Cin + 15) >> 4;
    for (int kt = 0; kt < ktiles; ++kt) {
        int buf = kt & 1;
        int k0 = kt * 16;
        #pragma unroll
        for (int u = 0; u < 2; ++u) {
            int e4 = tid + 256 * u;
            int row = e4 & 127, kq = e4 >> 7;
            int o = o0 + row;
            #pragma unroll
            for (int t = 0; t < 4; ++t) {
                int kk = k0 + kq * 4 + t;
                float w = (o < Cout && kk < Cin) ? Wb[(size_t)o * Cin + kk] : 0.f;
                Ws2[buf][kq * 4 + t][row] = make_float2(w, w);
            }
        }
        #pragma unroll
        for (int u = 0; u < 2; ++u) {
            int e = tid + 256 * u;
            int row = e >> 5, cq = e & 31;
            int kk = k0 + row;
            float4 v = (kk < Cin) ? *(const float4*)&Xb[(size_t)kk * N_ + p0 + cq * 4]
                                  : make_float4(0.f, 0.f, 0.f, 0.f);
            if (lnOn && kk < Cin) {
                int pix = p0 + cq * 4;
                float4 m  = *(const float4*)&lnMu[(size_t)bz * N_ + pix];
                float4 iv = *(const float4*)&lnInv[(size_t)bz * N_ + pix];
                float wv = lnW[kk], bv = lnB[kk];
                v.x = (v.x - m.x) * iv.x * wv + bv;
                v.y = (v.y - m.y) * iv.y * wv + bv;
                v.z = (v.z - m.z) * iv.z * wv + bv;
                v.w = (v.w - m.w) * iv.w * wv + bv;
            }
            *(float4*)&Xs[buf][row][cq * 4] = v;
        }
        __syncthreads();
        #pragma unroll
        for (int k = 0; k < 16; ++k) {
            ulonglong2 q0 = *(const ulonglong2*)&Xs[buf][k][tx * 4];
            ulonglong2 q1 = *(const ulonglong2*)&Xs[buf][k][64 + tx * 4];
            unsigned long long bb0 = q0.x, bb1 = q0.y, bb2 = q1.x, bb3 = q1.y;
            const ulonglong2* wrow = (const ulonglong2*)&Ws2[buf][k][ty * 8];
            ulonglong2 w01 = wrow[0], w23 = wrow[1], w45 = wrow[2], w67 = wrow[3];
            unsigned long long av[8] = {w01.x, w01.y, w23.x, w23.y,
                                        w45.x, w45.y, w67.x, w67.y};
            #pragma unroll
            for (int i = 0; i < 8; ++i) {
                FMA2(acc2[i][0], av[i], bb0);
                FMA2(acc2[i][1], av[i], bb1);
                FMA2(acc2[i][2], av[i], bb2);
                FMA2(acc2[i][3], av[i], bb3);
            }
        }
        __syncthreads();
    }

    const int doResid = flags & 1, doFinal = flags & 2;
    #pragma unroll
    for (int i = 0; i < 8; ++i) {
        int o = o0 + ty * 8 + i;
        if (o >= Cout) continue;
        size_t ybase0 = ((size_t)b * YCtot + Yoff + o) * N_ + p0 + tx * 4;
        float v[8];
        #pragma unroll
        for (int j = 0; j < 4; ++j) UNPK2(v[2 * j], v[2 * j + 1], acc2[i][j]);
        if (doResid) {
            size_t rbase = ((size_t)b * Cout + o) * N_ + p0 + tx * 4;
            float4 r0 = *(const float4*)&R[rbase];
            float4 r1 = *(const float4*)&R[rbase + 64];
            v[0] += r0.x; v[1] += r0.y; v[2] += r0.z; v[3] += r0.w;
            v[4] += r1.x; v[5] += r1.y; v[6] += r1.z; v[7] += r1.w;
        }
        if (doFinal) {
            #pragma unroll
            for (int j = 0; j < 8; ++j) v[j] = isfinite(v[j]) ? v[j] : 1e-5f;
        }
        *(float4*)&Y[ybase0]      = make_float4(v[0], v[1], v[2], v[3]);
        *(float4*)&Y[ybase0 + 64] = make_float4(v[4], v[5], v[6], v[7]);
    }
#endif
}

// ---------------- per-pixel LN stats, both paths in one launch ----------------
__global__ void lnstats2k(const float* __restrict__ X1, const float* __restrict__ X2,
                          float* __restrict__ mu, float* __restrict__ inv)
{
    int p = blockIdx.x * 256 + threadIdx.x;
    int zc = blockIdx.y;
    int pth = zc >= B_;
    int b = pth ? zc - B_ : zc;
    const float* xb = (pth ? X2 : X1) + (size_t)b * C_ * N_ + p;
    float s = 0.f, ss = 0.f;
    #pragma unroll 4
    for (int c = 0; c < C_; ++c) {
        float v = xb[(size_t)c * N_];
        s += v; ss += v * v;
    }
    float m = s * (1.f / C_);
    float var = ss * (1.f / C_) - m * m;
    mu[(size_t)zc * N_ + p] = m;
    inv[(size_t)zc * N_ + p] = rsqrtf(var + 1e-5f);
}

// ---------------- fused: x_out = fuse*ca + origin ; write x_out + LN stats ----------------
__global__ void scaleaddstatsk(const float* __restrict__ fuse, const float* __restrict__ cas,
                               const float* __restrict__ origin, float* __restrict__ Y,
                               float* __restrict__ mu, float* __restrict__ inv)
{
    int p = blockIdx.x * 256 + threadIdx.x;
    int b = blockIdx.y;
    __shared__ float sc[C_];
    for (int i = threadIdx.x; i < C_; i += 256) sc[i] = cas[b * C_ + i];
    __syncthreads();
    const size_t base = (size_t)b * C_ * N_ + p;
    float s = 0.f, ss = 0.f;
    #pragma unroll 4
    for (int c = 0; c < C_; ++c) {
        float v = fuse[base + (size_t)c * N_] * sc[c] + origin[base + (size_t)c * N_];
        Y[base + (size_t)c * N_] = v;
        s += v; ss += v * v;
    }
    float m = s * (1.f / C_);
    float var = ss * (1.f / C_) - m * m;
    mu[b * N_ + p] = m;
    inv[b * N_ + p] = rsqrtf(var + 1e-5f);
}

// ---------------- ALL depthwise 3x3 for both paths (q: C ch, kv: 2C ch) ----------------
__global__ void dwallk(const float* __restrict__ qX1, const float* __restrict__ qX2,
                       const float* __restrict__ qW1, const float* __restrict__ qW2,
                       float* __restrict__ qY1, float* __restrict__ qY2,
                       const float* __restrict__ kX1, const float* __restrict__ kX2,
                       const float* __restrict__ kW1, const float* __restrict__ kW2,
                       float* __restrict__ kY1, float* __restrict__ kY2)
{
    int cidx = blockIdx.y;
    int zc = blockIdx.z;
    int pth = zc >= B_;
    int b = pth ? zc - B_ : zc;
    const float* xb; const float* Wd; float* yb; int c;
    if (cidx < C_) {
        c = cidx;
        xb = (pth ? qX2 : qX1) + ((size_t)b * C_ + c) * N_;
        Wd = (pth ? qW2 : qW1);
        yb = (pth ? qY2 : qY1) + ((size_t)b * C_ + c) * N_;
    } else {
        c = cidx - C_;
        xb = (pth ? kX2 : kX1) + ((size_t)b * C2_ + c) * N_;
        Wd = (pth ? kW2 : kW1);
        yb = (pth ? kY2 : kY1) + ((size_t)b * C2_ + c) * N_;
    }
    int y0 = blockIdx.x * 8;
    int tid = threadIdx.x;
    __shared__ float t[10][128];
    for (int i = tid; i < 320; i += 256) {
        int r = i >> 5, xq = i & 31;
        int yy = y0 - 1 + r;
        float4 v = make_float4(0.f, 0.f, 0.f, 0.f);
        if (yy >= 0 && yy < Hh_) v = *(const float4*)&xb[yy * 128 + xq * 4];
        *(float4*)&t[r][xq * 4] = v;
    }
    float w[9];
    #pragma unroll
    for (int q = 0; q < 9; ++q) w[q] = Wd[c * 9 + q];
    __syncthreads();
    int r = tid >> 5;
    int lx = tid & 31;
    float* yo = yb + (y0 + r) * 128;
    #pragma unroll
    for (int u = 0; u < 4; ++u) {
        int x = u * 32 + lx;
        float s = 0.f;
        #pragma unroll
        for (int dy = 0; dy < 3; ++dy) {
            const float* row = t[r + dy];
            float m  = row[x];
            float l  = (x > 0)   ? row[x - 1] : 0.f;
            float rr = (x < 127) ? row[x + 1] : 0.f;
            s += l * w[dy * 3] + m * w[dy * 3 + 1] + rr * w[dy * 3 + 2];
        }
        yo[x] = s;
    }
}

// ---------------- fused FFN dwconv(680) + gelu-gate -> 340 (smem-tiled) ----------------
__global__ void dwgatek(const float* __restrict__ X, const float* __restrict__ Wd,
                        float* __restrict__ Y)
{
    int c = blockIdx.y, b = blockIdx.z;
    int y0 = blockIdx.x * 8;
    int tid = threadIdx.x;
    const float* x1b = X + ((size_t)b * HID2_ + c) * N_;
    const float* x2b = X + ((size_t)b * HID2_ + c + HID_) * N_;
    __shared__ float t1[10][128];
    __shared__ float t2[10][128];
    for (int i = tid; i < 320; i += 256) {
        int r = i >> 5, xq = i & 31;
        int yy = y0 - 1 + r;
        float4 v1 = make_float4(0.f, 0.f, 0.f, 0.f);
        float4 v2 = v1;
        if (yy >= 0 && yy < Hh_) {
            v1 = *(const float4*)&x1b[yy * 128 + xq * 4];
            v2 = *(const float4*)&x2b[yy * 128 + xq * 4];
        }
        *(float4*)&t1[r][xq * 4] = v1;
        *(float4*)&t2[r][xq * 4] = v2;
    }
    float w1[9], w2[9];
    #pragma unroll
    for (int q = 0; q < 9; ++q) { w1[q] = Wd[c * 9 + q]; w2[q] = Wd[(c + HID_) * 9 + q]; }
    __syncthreads();
    int r = tid >> 5;
    int lx = tid & 31;
    float* yo = Y + ((size_t)b * HID_ + c) * N_ + (y0 + r) * 128;
    #pragma unroll
    for (int u = 0; u < 4; ++u) {
        int x = u * 32 + lx;
        float s1 = 0.f, s2 = 0.f;
        #pragma unroll
        for (int dy = 0; dy < 3; ++dy) {
            const float* r1 = t1[r + dy];
            const float* r2 = t2[r + dy];
            float m1  = r1[x],  m2  = r2[x];
            float l1  = (x > 0)   ? r1[x - 1] : 0.f;
            float l2  = (x > 0)   ? r2[x - 1] : 0.f;
            float rr1 = (x < 127) ? r1[x + 1] : 0.f;
            float rr2 = (x < 127) ? r2[x + 1] : 0.f;
            s1 += l1 * w1[dy * 3] + m1 * w1[dy * 3 + 1] + rr1 * w1[dy * 3 + 2];
            s2 += l2 * w2[dy * 3] + m2 * w2[dy * 3 + 1] + rr2 * w2[dy * 3 + 2];
        }
        float ge = 0.5f * s1 * (1.f + erff(s1 * 0.70710678118654752f));
        yo[x] = ge * s2;
    }
}

// ---------------- attention partials, both paths ----------------
__global__ void attnpartk(const float* __restrict__ Q1, const float* __restrict__ Q2,
                          const float* __restrict__ KV1, const float* __restrict__ KV2,
                          float* __restrict__ part)
{
    int chunk = blockIdx.x, h = blockIdx.y;
    int zc = blockIdx.z;
    int pth = zc >= B_;
    int b = pth ? zc - B_ : zc;
    const float* qb = (pth ? Q2 : Q1)  + ((size_t)b * C_  + h * CH_) * N_;
    const float* kb = (pth ? KV2 : KV1) + ((size_t)b * C2_ + h * CH_) * N_;

    __shared__ float sm[16 * 16 * 16];
    __shared__ float qqp[256], kkp[256];
    float* qs = sm;
    float* ks = sm + 1024;

    int tid = threadIdx.x;
    int i = tid & 15, s = tid >> 4;
    float acc[16];
    #pragma unroll
    for (int j = 0; j < 16; ++j) acc[j] = 0.f;
    float qq = 0.f, kk = 0.f;

    int nbeg = chunk * CHUNKN_;
    for (int n0 = nbeg; n0 < nbeg + CHUNKN_; n0 += 64) {
        #pragma unroll
        for (int u = 0; u < 4; ++u) {
            int e = tid + 256 * u;
            int r = e >> 6, cc = e & 63;
            qs[r * 64 + cc] = qb[(size_t)r * N_ + n0 + cc];
            ks[r * 64 + cc] = kb[(size_t)r * N_ + n0 + cc];
        }
        __syncthreads();
        #pragma unroll
        for (int t = 0; t < 4; ++t) {
            float qv = qs[i * 64 + s * 4 + t];
            float kv = ks[i * 64 + s * 4 + t];
            qq += qv * qv;
            kk += kv * kv;
            #pragma unroll
            for (int j = 0; j < 16; ++j) acc[j] += qv * ks[j * 64 + s * 4 + t];
        }
        __syncthreads();
    }
    qqp[s * 16 + i] = qq;
    kkp[s * 16 + i] = kk;
    #pragma unroll
    for (int j = 0; j < 16; ++j) sm[s * 256 + i * 16 + j] = acc[j];
    __syncthreads();

    float* pb = part + (((size_t)zc * HEADS_ + h) * NCHUNK_ + chunk) * 288;
    int i2 = tid >> 4, j2 = tid & 15;
    float a = 0.f;
    #pragma unroll
    for (int s2 = 0; s2 < 16; ++s2) a += sm[s2 * 256 + i2 * 16 + j2];
    pb[i2 * 16 + j2] = a;
    if (tid < 16) {
        float t0 = 0.f;
        #pragma unroll
        for (int s2 = 0; s2 < 16; ++s2) t0 += qqp[s2 * 16 + tid];
        pb[256 + tid] = t0;
    } else if (tid < 32) {
        int j = tid - 16;
        float t0 = 0.f;
        #pragma unroll
        for (int s2 = 0; s2 < 16; ++s2) t0 += kkp[s2 * 16 + j];
        pb[272 + j] = t0;
    }
}

// ---------------- attention finalize, both paths ----------------
__global__ void attnfink(const float* __restrict__ part, const float* __restrict__ temp1,
                         const float* __restrict__ temp2, float* __restrict__ attnOut)
{
    int h = blockIdx.x;
    int zc = blockIdx.y;
    int pth = zc >= B_;
    const float* temp = pth ? temp2 : temp1;
    const float* pb = part + ((size_t)zc * HEADS_ + h) * NCHUNK_ * 288;
    __shared__ float qqs[16], kks[16];
    int tid = threadIdx.x;

    float a = 0.f;
    #pragma unroll
    for (int c = 0; c < NCHUNK_; ++c) a += pb[c * 288 + tid];

    if (tid < 16) {
        float t0 = 0.f;
        #pragma unroll
        for (int c = 0; c < NCHUNK_; ++c) t0 += pb[c * 288 + 256 + tid];
        qqs[tid] = fmaxf(sqrtf(t0), 1e-12f);
    } else if (tid < 32) {
        int j = tid - 16;
        float t0 = 0.f;
        #pragma unroll
        for (int c = 0; c < NCHUNK_; ++c) t0 += pb[c * 288 + 272 + j];
        kks[j] = fmaxf(sqrtf(t0), 1e-12f);
    }
    __syncthreads();

    int i2 = tid >> 4, j2 = tid & 15;
    a = a / (qqs[i2] * kks[j2]) * temp[h];

    unsigned mask = 0xFFFFFFFFu;
    float mx = a;
    for (int w = 8; w > 0; w >>= 1) mx = fmaxf(mx, __shfl_xor_sync(mask, mx, w, 16));
    float e = expf(a - mx);
    float ssum = e;
    for (int w = 8; w > 0; w >>= 1) ssum += __shfl_xor_sync(mask, ssum, w, 16);
    attnOut[((size_t)zc * HEADS_ + h) * 256 + i2 * 16 + j2] = e / ssum;
}

// ---------------- M[zc] = po @ blockdiag(attn[zc]) : [C_, C_], both paths ----------------
__global__ void poattnk(const float* __restrict__ po1, const float* __restrict__ po2,
                        const float* __restrict__ attn, float* __restrict__ M)
{
    int zc = blockIdx.x;
    const float* po = (zc >= B_) ? po2 : po1;
    __shared__ float at[HEADS_ * 256];
    for (int i = threadIdx.x; i < HEADS_ * 256; i += 256)
        at[i] = attn[(size_t)zc * HEADS_ * 256 + i];
    __syncthreads();
    for (int idx = threadIdx.x; idx < C_ * C_; idx += 256) {
        int o = idx >> 7, cj = idx & 127;
        int h = cj >> 4, j = cj & 15;
        float s = 0.f;
        #pragma unroll
        for (int i = 0; i < 16; ++i) s += po[o * C_ + h * 16 + i] * at[h * 256 + i * 16 + j];
        M[((size_t)zc * C_ + o) * C_ + cj] = s;
    }
}

// ---------------- global average pool per (b,c) ----------------
__global__ void capoolk(const float* __restrict__ X, float* __restrict__ pool)
{
    int c = blockIdx.x, b = blockIdx.y;
    const float* xb = X + ((size_t)b * C_ + c) * N_;
    float s = 0.f;
    for (int n = threadIdx.x * 4; n < N_; n += 1024) {
        float4 v = *(const float4*)&xb[n];
        s += v.x + v.y + v.z + v.w;
    }
    __shared__ float red[256];
    red[threadIdx.x] = s; __syncthreads();
    for (int st = 128; st > 0; st >>= 1) {
        if (threadIdx.x < st) red[threadIdx.x] += red[threadIdx.x + st];
        __syncthreads();
    }
    if (threadIdx.x == 0) pool[b * C_ + c] = red[0] * (1.f / N_);
}

// ---------------- CA: relu FC (128->8) + sigmoid FC (8->128) ----------------
__global__ void cafck(const float* __restrict__ pool,
                      const float* __restrict__ w1, const float* __restrict__ b1,
                      const float* __restrict__ w2, const float* __restrict__ b2,
                      float* __restrict__ cas)
{
    int b = blockIdx.x, t = threadIdx.x;
    __shared__ float pl[C_];
    __shared__ float hid[8];
    pl[t] = pool[b * C_ + t];
    __syncthreads();
    if (t < 8) {
        float s = b1[t];
        #pragma unroll 4
        for (int c = 0; c < C_; ++c) s += w1[t * C_ + c] * pl[c];
        hid[t] = fmaxf(s, 0.f);
    }
    __syncthreads();
    float s = b2[t];
    #pragma unroll
    for (int r = 0; r < 8; ++r) s += w2[t * 8 + r] * hid[r];
    cas[b * C_ + t] = 1.f / (1.f + expf(-s));
}

// ---------------- host ----------------
extern "C" void kernel_launch(void* const* d_in, const int* in_sizes, int n_in,
                              void* d_out, int out_size)
{
    (void)in_sizes; (void)n_in; (void)out_size;
    const float* origin  = (const float*)d_in[0];
    const float* low     = (const float*)d_in[1];
    const float* high    = (const float*)d_in[2];
    const float* norm1_w = (const float*)d_in[3];
    const float* norm1_b = (const float*)d_in[4];
    const float* norm_1_w= (const float*)d_in[5];
    const float* norm_1_b= (const float*)d_in[6];
    const float* norm2_w = (const float*)d_in[7];
    const float* norm2_b = (const float*)d_in[8];
    const float* a1_q    = (const float*)d_in[9];
    const float* a1_qdw  = (const float*)d_in[10];
    const float* a1_kv   = (const float*)d_in[11];
    const float* a1_kvdw = (const float*)d_in[12];
    const float* a1_po   = (const float*)d_in[13];
    const float* a1_temp = (const float*)d_in[14];
    const float* a2_q    = (const float*)d_in[15];
    const float* a2_qdw  = (const float*)d_in[16];
    const float* a2_kv   = (const float*)d_in[17];
    const float* a2_kvdw = (const float*)d_in[18];
    const float* a2_po   = (const float*)d_in[19];
    const float* a2_temp = (const float*)d_in[20];
    const float* conv1_w = (const float*)d_in[21];
    const float* ca1_w   = (const float*)d_in[22];
    const float* ca1_b   = (const float*)d_in[23];
    const float* ca2_w   = (const float*)d_in[24];
    const float* ca2_b   = (const float*)d_in[25];
    const float* ffn_pi  = (const float*)d_in[26];
    const float* ffn_dw  = (const float*)d_in[27];
    const float* ffn_po  = (const float*)d_in[28];
    float* out = (float*)d_out;

    float *bufCb, *bufCc, *bufCd, *bufCe, *buf2Ca, *buf2Cb, *buf2Cc, *bufHa, *bufHb, *xout;
    float *mu, *inv, *attnp, *attnw, *Mw, *pool, *cas;
    cudaGetSymbolAddress((void**)&bufCb, g_bufCb);
    cudaGetSymbolAddress((void**)&bufCc, g_bufCc);
    cudaGetSymbolAddress((void**)&bufCd, g_bufCd);
    cudaGetSymbolAddress((void**)&bufCe, g_bufCe);
    cudaGetSymbolAddress((void**)&buf2Ca, g_buf2Ca);
    cudaGetSymbolAddress((void**)&buf2Cb, g_buf2Cb);
    cudaGetSymbolAddress((void**)&buf2Cc, g_buf2Cc);
    cudaGetSymbolAddress((void**)&bufHa, g_bufHa);
    cudaGetSymbolAddress((void**)&bufHb, g_bufHb);
    cudaGetSymbolAddress((void**)&xout, g_xout);
    cudaGetSymbolAddress((void**)&mu, g_mu);
    cudaGetSymbolAddress((void**)&inv, g_inv);
    cudaGetSymbolAddress((void**)&attnp, g_attnp);
    cudaGetSymbolAddress((void**)&attnw, g_attnw);
    cudaGetSymbolAddress((void**)&Mw, g_Mw);
    cudaGetSymbolAddress((void**)&pool, g_pool);
    cudaGetSymbolAddress((void**)&cas, g_cas);

    static int smem_set = 0;
    if (!smem_set) {
        cudaFuncSetAttribute(gemmtc, cudaFuncAttributeMaxDynamicSharedMemorySize, SM_TOTAL);
        smem_set = 1;
    }

    dim3 tb(256);
    dim3 gLN2(N_ / 256, 2 * B_);
    dim3 gLN(N_ / 256, B_);
    dim3 gQ(N_ / 128, 1, 2 * B_);
    dim3 gKV(N_ / 128, 2, 2 * B_);
    dim3 gMv(N_ / 128, 1, 2 * B_);
    dim3 gG_C(N_ / 128, 1, B_);
    dim3 gG_H(N_ / 128, (HID2_ + 127) / 128, B_);
    dim3 gRow(C_, B_);
    dim3 gAttnP(NCHUNK_, HEADS_, 2 * B_);
    dim3 gAttnF(HEADS_, 2 * B_);
    dim3 gDWall(Hh_ / 8, C_ + C2_, 2 * B_);
    dim3 gDW_H(Hh_ / 8, HID_, B_);

    // ===== both attention paths, merged launches =====
    gemmtc<<<gQ, tb, SM_TOTAL>>>(a1_q, high, bufCb, nullptr,
                                 a2_q, low, bufCc, nullptr,
                                 nullptr, nullptr, nullptr, nullptr, nullptr, nullptr,
                                 C_, C_, C_, C_, 0, 0, 0, 0);
    lnstats2k<<<gLN2, tb>>>(low, high, mu, inv);
    gemmtc<<<gKV, tb, SM_TOTAL>>>(a1_kv, low, buf2Ca, nullptr,
                                  a2_kv, high, buf2Cb, nullptr,
                                  mu, inv, norm1_w, norm1_b, norm_1_w, norm_1_b,
                                  C2_, C_, C_, C2_, 0, 0, 4, 0);
    dwallk<<<gDWall, tb>>>(bufCb, bufCc, a1_qdw, a2_qdw, bufCd, bufCe,
                           buf2Ca, buf2Cb, a1_kvdw, a2_kvdw, buf2Cc, bufHa);
    attnpartk<<<gAttnP, tb>>>(bufCd, bufCe, buf2Cc, bufHa, attnp);
    attnfink<<<gAttnF, tb>>>(attnp, a1_temp, a2_temp, attnw);
    poattnk<<<dim3(2 * B_), tb>>>(a1_po, a2_po, attnw, Mw);
    gemmtc<<<gMv, tb, SM_TOTAL>>>(Mw, buf2Cc + (size_t)C_ * N_, buf2Ca, low,
                                  Mw + (size_t)B_ * C_ * C_, bufHa + (size_t)C_ * N_, buf2Ca, high,
                                  nullptr, nullptr, nullptr, nullptr, nullptr, nullptr,
                                  C_, C_, C2_, C2_, 0, C_, 1, C_ * C_);

    // ===== fuse: conv1(concat) -> CA -> + origin, fused with norm2 stats =====
    gemmtc<<<gG_C, tb, SM_TOTAL>>>(conv1_w, buf2Ca, bufCb, nullptr,
                                   conv1_w, buf2Ca, bufCb, nullptr,
                                   nullptr, nullptr, nullptr, nullptr, nullptr, nullptr,
                                   C_, C2_, C2_, C_, 0, 0, 0, 0);
    capoolk<<<gRow, tb>>>(bufCb, pool);
    cafck<<<dim3(B_), dim3(128)>>>(pool, ca1_w, ca1_b, ca2_w, ca2_b, cas);
    scaleaddstatsk<<<gLN, tb>>>(bufCb, cas, origin, xout, mu, inv);

    // ===== FFN with residual =====
    gemmtc<<<gG_H, tb, SM_TOTAL>>>(ffn_pi, xout, bufHa, nullptr,
                                   ffn_pi, xout, bufHa, nullptr,
                                   mu, inv, norm2_w, norm2_b, norm2_w, norm2_b,
                                   HID2_, C_, C_, HID2_, 0, 0, 4, 0);
    dwgatek<<<gDW_H, tb>>>(bufHa, ffn_dw, bufHb);
    gemmtc<<<gG_C, tb, SM_TOTAL>>>(ffn_po, bufHb, out, xout,
                                   ffn_po, bufHb, out, xout,
                                   nullptr, nullptr, nullptr, nullptr, nullptr, nullptr,
                                   C_, HID_, HID_, C_, 0, 0, 3, 0);
}

// round 12
// speedup vs baseline: 1.2417x; 1.2417x over previous
#include <cuda_runtime.h>
#include <cuda_bf16.h>
#include <math.h>
#include <stdint.h>

#define B_    8
#define C_    128
#define Hh_   128
#define Ww_   128
#define N_    16384      // H*W
#define HEADS_ 8
#define CH_   16         // C/HEADS
#define HID_  340
#define HID2_ 680
#define C2_   256
#define NCHUNK_ 16
#define CHUNKN_ (N_ / NCHUNK_)   // 1024
#define TILE_B 32768             // one pre-swizzled W tile: 16KB hi + 16KB lo

// ---------------- static scratch (no allocations allowed) ----------------
__device__ float g_bufCb[(size_t)B_ * C_ * N_];   // qpre path1 / conv1 out
__device__ float g_bufCc[(size_t)B_ * C_ * N_];   // qpre path2
__device__ float g_bufCd[(size_t)B_ * C_ * N_];   // qdw path1
__device__ float g_bufCe[(size_t)B_ * C_ * N_];   // qdw path2
__device__ float g_buf2Ca[(size_t)B_ * C2_ * N_]; // kvpre path1 / concat out
__device__ float g_buf2Cb[(size_t)B_ * C2_ * N_]; // kvpre path2
__device__ float g_buf2Cc[(size_t)B_ * C2_ * N_]; // kvdw path1
__device__ float g_bufHa[(size_t)B_ * HID2_ * N_];// kvdw path2 (front 2C) / ffn hidden
__device__ float g_bufHb[(size_t)B_ * HID_ * N_]; // gated
__device__ float g_xout[(size_t)B_ * C_ * N_];
__device__ float g_mu[2 * B_ * N_];
__device__ float g_inv[2 * B_ * N_];
__device__ float g_attnp[2 * B_ * HEADS_ * NCHUNK_ * 288];
__device__ float g_attnw[2 * B_ * HEADS_ * CH_ * CH_];
__device__ float g_Mw[2 * B_ * C_ * C_];
__device__ float g_pool[B_ * C_];
__device__ float g_cas[B_ * C_];
// pre-swizzled weight tiles: 34 static + 32 for Mw
__device__ __align__(16) uint8_t g_wt[34 * TILE_B];
__device__ __align__(16) uint8_t g_MwT[32 * TILE_B];

// packed f32x2 helpers (fallback path)
#define FMA2(d, a, b) asm("fma.rn.f32x2 %0, %1, %2, %0;" : "+l"(d) : "l"(a), "l"(b))
#define UNPK2(lo, hi, s) asm("mov.b64 {%0, %1}, %2;" : "=f"(lo), "=f"(hi) : "l"(s))

// ---------------- PTX helpers ----------------
__device__ __forceinline__ uint32_t smem_u32(const void* p) {
    uint32_t a;
    asm("{ .reg .u64 t; cvta.to.shared.u64 t, %1; cvt.u32.u64 %0, t; }" : "=r"(a) : "l"(p));
    return a;
}
#define SWZ(o) ((o) ^ (((o) >> 3) & 0x70))

#if defined(__CUDA_ARCH_FEAT_SM103_ALL) || !defined(__CUDA_ARCH__)
#define HAS_TC 1
#else
#define HAS_TC 0
#endif

#define MBARRIER_INIT(addr, cnt) \
    asm volatile("mbarrier.init.shared.b64 [%0], %1;" :: "r"((uint32_t)(addr)), "r"((uint32_t)(cnt)) : "memory")
#define MBARRIER_INVAL(addr) \
    asm volatile("mbarrier.inval.shared.b64 [%0];" :: "r"((uint32_t)(addr)) : "memory")
#define MBARRIER_WAIT_PARITY(mbar_smem_addr, phase_parity) do { \
    uint32_t _mbar = (uint32_t)(mbar_smem_addr); \
    uint32_t _parity = (uint32_t)(phase_parity); \
    uint32_t _done; \
    asm volatile("{\n\t.reg .pred p;\n\t" \
        "mbarrier.try_wait.parity.acquire.cta.shared::cta.b64 p, [%1], %2;\n\t" \
        "selp.b32 %0, 1, 0, p;\n\t}" : "=r"(_done) : "r"(_mbar), "r"(_parity) : "memory"); \
    if (!_done) { \
        asm volatile("{\n\t.reg .pred P1;\n\t" \
            "WAIT_LOOP_%=:\n\t" \
            "mbarrier.try_wait.parity.acquire.cta.shared::cta.b64 P1, [%0], %1, 0x989680;\n\t" \
            "@P1 bra.uni WAIT_DONE_%=;\n\t" \
            "bra.uni WAIT_LOOP_%=;\n\t" \
            "WAIT_DONE_%=:\n\t}" :: "r"(_mbar), "r"(_parity) : "memory"); \
    } \
} while (0)

#if HAS_TC
#define TCGEN05_ALLOC(smem_result_addr, nCols) \
    asm volatile("tcgen05.alloc.cta_group::1.sync.aligned.shared::cta.b32 [%0], %1;" \
        :: "r"((uint32_t)(smem_result_addr)), "r"((uint32_t)(nCols)) : "memory")
#define TCGEN05_DEALLOC(tmem_addr, nCols) \
    asm volatile("tcgen05.dealloc.cta_group::1.sync.aligned.b32 %0, %1;" :: "r"(tmem_addr), "r"((uint32_t)(nCols)))
#define TCGEN05_RELINQUISH() \
    asm volatile("tcgen05.relinquish_alloc_permit.cta_group::1.sync.aligned;")
#define TCGEN05_COMMIT(mbar_smem_addr) \
    asm volatile("tcgen05.commit.cta_group::1.mbarrier::arrive::one.shared::cluster.b64 [%0];" \
        :: "r"((uint32_t)(mbar_smem_addr)) : "memory")
#define TCGEN05_FENCE_AFTER() asm volatile("tcgen05.fence::after_thread_sync;" ::: "memory")
#define TCGEN05_FENCE_BEFORE() asm volatile("tcgen05.fence::before_thread_sync;" ::: "memory")
#define TCGEN05_WAIT_LD() asm volatile("tcgen05.wait::ld.sync.aligned;" ::: "memory")
#define FENCE_ASYNC_SHARED() asm volatile("fence.proxy.async.shared::cta;" ::: "memory")

#define TCGEN05_LD_32X32B_X32(r, tmem_addr) \
    asm volatile( \
        "tcgen05.ld.sync.aligned.32x32b.x32.b32 " \
        "{%0, %1, %2, %3, %4, %5, %6, %7, " \
        " %8, %9, %10, %11, %12, %13, %14, %15, " \
        " %16, %17, %18, %19, %20, %21, %22, %23, " \
        " %24, %25, %26, %27, %28, %29, %30, %31}, [%32];" \
        : "=r"((r)[0]),  "=r"((r)[1]),  "=r"((r)[2]),  "=r"((r)[3]), \
          "=r"((r)[4]),  "=r"((r)[5]),  "=r"((r)[6]),  "=r"((r)[7]), \
          "=r"((r)[8]),  "=r"((r)[9]),  "=r"((r)[10]), "=r"((r)[11]), \
          "=r"((r)[12]), "=r"((r)[13]), "=r"((r)[14]), "=r"((r)[15]), \
          "=r"((r)[16]), "=r"((r)[17]), "=r"((r)[18]), "=r"((r)[19]), \
          "=r"((r)[20]), "=r"((r)[21]), "=r"((r)[22]), "=r"((r)[23]), \
          "=r"((r)[24]), "=r"((r)[25]), "=r"((r)[26]), "=r"((r)[27]), \
          "=r"((r)[28]), "=r"((r)[29]), "=r"((r)[30]), "=r"((r)[31]) \
        : "r"(tmem_addr))

// SW128 SMEM descriptor (LBO=1, SBO=64, version=1, layout=SW128)
__device__ __forceinline__ uint64_t make_desc(uint32_t addr) {
    const uint64_t base = (uint64_t(2) << 61) | (uint64_t(1) << 46)
                        | (uint64_t(64) << 32) | (uint64_t(1) << 16);
    return base | ((uint64_t)(addr >> 4) & 0x3FFF);
}

// bf16 SS MMA, cg1: D[M=128, N=128] += A[M,K=16] * B[N,K=16]^T
#define MMA_IDESC 0x8200490u
__device__ __forceinline__ void mma_bf16_ss(uint32_t d, uint64_t ad, uint64_t bd, uint32_t en) {
    asm volatile(
        "{\n\t.reg .pred p;\n\tsetp.ne.u32 p, %5, 0;\n\t"
        "tcgen05.mma.cta_group::1.kind::f16 [%0], %1, %2, %3, {%4, %4, %4, %4}, p;\n\t}"
        :: "r"(d), "l"(ad), "l"(bd), "r"(MMA_IDESC), "r"(0u), "r"(en) : "memory");
}
#endif  // HAS_TC

// dynamic smem layout (bytes) — DOUBLE-buffered (R9-proven)
#define SM_TMEM   0
#define SM_MBAR   16           // 2 mbarriers @16, @24
#define SM_XS     64           // fp32 staging: 64 x 132 floats = 33792 B
#define SM_TILES  34816        // 1024-aligned; per buffer: AHI,ALO,BHI,BLO @16KB
#define SM_BUFSZ  65536
#define SM_TOTAL  (SM_TILES + 2 * SM_BUFSZ)   // 165888 B

// truncation-based hi/lo bf16 split, packed pairs via PRMT
__device__ __forceinline__ uint32_t prmt_hi(uint32_t u0, uint32_t u1) {
    uint32_t r;
    asm("prmt.b32 %0, %1, %2, 0x7632;" : "=r"(r) : "r"(u0), "r"(u1));
    return r;
}
__device__ __forceinline__ void split2(float x0, float x1, uint32_t& hp, uint32_t& lp) {
    uint32_t u0 = __float_as_uint(x0), u1 = __float_as_uint(x1);
    hp = prmt_hi(u0, u1);
    float l0 = x0 - __uint_as_float(u0 & 0xFFFF0000u);
    float l1 = x1 - __uint_as_float(u1 & 0xFFFF0000u);
    lp = prmt_hi(__float_as_uint(l0), __float_as_uint(l1));
}

// ---------------- weight pre-tiler: fp32 W[Cout,Cin] -> SW128 hi/lo bf16 tiles ----------------
__global__ void wtilek(const float* __restrict__ W, uint8_t* __restrict__ tiles,
                       int Cout, int Cin)
{
    const int KchT = (Cin + 63) >> 6;
    uint8_t* tb = tiles + ((size_t)blockIdx.y * KchT + blockIdx.x) * TILE_B;
    const int tid = threadIdx.x;
    int r = tid >> 1;
    int kh = (tid & 1) << 5;
    int o = blockIdx.y * 128 + r;
    #pragma unroll
    for (int i = 0; i < 8; ++i) {
        int kk = blockIdx.x * 64 + kh + i * 4;
        float4 v;
        v.x = (o < Cout && kk + 0 < Cin) ? W[(size_t)o * Cin + kk + 0] : 0.f;
        v.y = (o < Cout && kk + 1 < Cin) ? W[(size_t)o * Cin + kk + 1] : 0.f;
        v.z = (o < Cout && kk + 2 < Cin) ? W[(size_t)o * Cin + kk + 2] : 0.f;
        v.w = (o < Cout && kk + 3 < Cin) ? W[(size_t)o * Cin + kk + 3] : 0.f;
        uint32_t hp0, lp0, hp1, lp1;
        split2(v.x, v.y, hp0, lp0);
        split2(v.z, v.w, hp1, lp1);
        uint32_t off = SWZ((uint32_t)(r * 128 + (kh + i * 4) * 2));
        *(uint2*)(tb + off) = make_uint2(hp0, hp1);
        *(uint2*)(tb + 16384 + off) = make_uint2(lp0, lp1);
    }
}

// ---------------- GEMM: Y[b, Yoff+o, p] = sum_c W[o,c] LN?(X[b,c,p]) ----------------
// flags: 1=residual add, 2=nan_to_num, 4=apply LN to X on load
__global__ void __launch_bounds__(256, 1)
gemmtc(const uint8_t* __restrict__ Wt1, const float* __restrict__ X1,
       float* __restrict__ Y1, const float* __restrict__ R1,
       const uint8_t* __restrict__ Wt2, const float* __restrict__ X2,
       float* __restrict__ Y2, const float* __restrict__ R2,
       const float* __restrict__ W1, const float* __restrict__ W2,
       const float* __restrict__ lnMu, const float* __restrict__ lnInv,
       const float* __restrict__ lnW1, const float* __restrict__ lnB1,
       const float* __restrict__ lnW2, const float* __restrict__ lnB2,
       int Cout, int Cin, int XCtot, int YCtot, int Yoff1, int Yoff2,
       int flags, int WtTilesPerB, int WstrideB)
{
    extern __shared__ __align__(1024) char smem[];

    const int bz = blockIdx.z;
    const int pth = bz >= B_;
    const int b = pth ? bz - B_ : bz;
    const int o0 = blockIdx.y * 128;
    const int p0 = blockIdx.x * 128;
    const float* Xb = (pth ? X2 : X1) + (size_t)b * XCtot * N_;
    float* Y = pth ? Y2 : Y1;
    const float* R = pth ? R2 : R1;
    const float* lnW = pth ? lnW2 : lnW1;
    const float* lnB = pth ? lnB2 : lnB1;
    const int Yoff = pth ? Yoff2 : Yoff1;
    const int lnOn = flags & 4;
    const int tid = threadIdx.x;
    const int nch = (Cin + 63) >> 6;   // == KchT

#if HAS_TC && defined(__CUDA_ARCH__)
    // ================= tcgen05 path (sm_103a cubin) =================
    const uint8_t* Wtb = (pth ? Wt2 : Wt1) + (size_t)b * WtTilesPerB * TILE_B;
    const uint32_t sb = smem_u32(smem);
    const int wid = tid >> 5;

    if (tid == 0) {
        MBARRIER_INIT(sb + SM_MBAR, 1);
        MBARRIER_INIT(sb + SM_MBAR + 8, 1);
    }
    if (wid == 0) TCGEN05_ALLOC(sb + SM_TMEM, 128);
    __syncthreads();
    uint32_t tmem;
    asm volatile("ld.shared.b32 %0, [%1];" : "=r"(tmem) : "r"(sb + SM_TMEM));

    int ph0 = 0, ph1 = 0;
    uint32_t en = 0;
    float* xs = (float*)(smem + SM_XS);

    for (int ch = 0; ch < nch; ++ch) {
        const int bf = ch & 1;
        const int k0 = ch << 6;
        if (ch >= 2) {
            if (bf == 0) { MBARRIER_WAIT_PARITY(sb + SM_MBAR, ph0); ph0 ^= 1; }
            else         { MBARRIER_WAIT_PARITY(sb + SM_MBAR + 8, ph1); ph1 ^= 1; }
        }
        char* abase = smem + SM_TILES + bf * SM_BUFSZ;   // AHI (+16K ALO)
        char* bbase = abase + 32768;                     // BHI
        char* blbase = abase + 49152;                    // BLO

        // ---- stage A: straight copy of pre-swizzled hi/lo tile (32KB) ----
        {
            const uint4* src = (const uint4*)(Wtb + ((size_t)(blockIdx.y * nch + ch)) * TILE_B);
            uint4* dst = (uint4*)abase;
            #pragma unroll
            for (int i = 0; i < 8; ++i)
                dst[tid + 256 * i] = src[tid + 256 * i];
        }

        // ---- stage B phase 1: X [64 k][128 p] fp32 -> Xs (LN applied) ----
        {
            int kr = tid >> 2;
            int pc = (tid & 3) << 5;
            int kk = k0 + kr;
            float* xrow = xs + kr * 132 + pc;
            if (kk < Cin) {
                const float* src = Xb + (size_t)kk * N_ + p0 + pc;
                if (lnOn) {
                    float wv = lnW[kk], bv = lnB[kk];
                    #pragma unroll
                    for (int i = 0; i < 8; ++i) {
                        float4 v = *(const float4*)&src[i * 4];
                        float4 m  = *(const float4*)&lnMu[(size_t)bz * N_ + p0 + pc + i * 4];
                        float4 iv = *(const float4*)&lnInv[(size_t)bz * N_ + p0 + pc + i * 4];
                        v.x = (v.x - m.x) * iv.x * wv + bv;
                        v.y = (v.y - m.y) * iv.y * wv + bv;
                        v.z = (v.z - m.z) * iv.z * wv + bv;
                        v.w = (v.w - m.w) * iv.w * wv + bv;
                        *(float4*)&xrow[i * 4] = v;
                    }
                } else {
                    #pragma unroll
                    for (int i = 0; i < 8; ++i)
                        *(float4*)&xrow[i * 4] = *(const float4*)&src[i * 4];
                }
            } else {
                #pragma unroll
                for (int i = 0; i < 8; ++i)
                    *(float4*)&xrow[i * 4] = make_float4(0.f, 0.f, 0.f, 0.f);
            }
        }
        __syncthreads();

        // ---- stage B phase 2: transpose + convert -> B[n][k] hi/lo bf16 SW128 ----
        {
            int n = tid & 127;
            int half = tid >> 7;
            #pragma unroll
            for (int g = 0; g < 4; ++g) {
                uint32_t hw[4], lw[4];
                #pragma unroll
                for (int q = 0; q < 4; ++q) {
                    int k1 = half * 32 + g * 8 + q * 2;
                    split2(xs[(k1 + 0) * 132 + n], xs[(k1 + 1) * 132 + n], hw[q], lw[q]);
                }
                uint32_t off = SWZ((uint32_t)(n * 128 + half * 64 + g * 16));
                *(uint4*)(bbase + off) = make_uint4(hw[0], hw[1], hw[2], hw[3]);
                *(uint4*)(blbase + off) = make_uint4(lw[0], lw[1], lw[2], lw[3]);
            }
        }
        FENCE_ASYNC_SHARED();
        __syncthreads();

        // ---- issue MMAs for this chunk ----
        if (tid == 0) {
            uint64_t ah = make_desc(sb + SM_TILES + bf * SM_BUFSZ);
            uint64_t al = ah + (16384 >> 4);
            uint64_t bh = ah + (32768 >> 4);
            uint64_t bl = ah + (49152 >> 4);
            #pragma unroll
            for (int s = 0; s < 4; ++s) {
                uint64_t ofs = s * 2;
                mma_bf16_ss(tmem, ah + ofs, bh + ofs, en); en = 1;
                mma_bf16_ss(tmem, ah + ofs, bl + ofs, 1);
                mma_bf16_ss(tmem, al + ofs, bh + ofs, 1);
            }
            TCGEN05_COMMIT(sb + SM_MBAR + bf * 8);
        }
    }

    // ---- drain ----
    { MBARRIER_WAIT_PARITY(sb + SM_MBAR, ph0); }
    if (nch >= 2) { MBARRIER_WAIT_PARITY(sb + SM_MBAR + 8, ph1); }
    TCGEN05_FENCE_AFTER();

    // ---- epilogue: warps 0-3 read TMEM D and store ----
    const int doResid = flags & 1, doFinal = flags & 2;
    if (tid < 128) {
        int w = tid >> 5, l = tid & 31;
        int o = o0 + w * 32 + l;
        #pragma unroll
        for (int g = 0; g < 4; ++g) {
            uint32_t dr[32];
            TCGEN05_LD_32X32B_X32(dr, tmem + g * 32);
            TCGEN05_WAIT_LD();
            if (o < Cout) {
                size_t ybase = ((size_t)b * YCtot + Yoff + o) * N_ + p0 + g * 32;
                size_t rbase = ((size_t)b * Cout + o) * N_ + p0 + g * 32;
                #pragma unroll
                for (int q = 0; q < 8; ++q) {
                    float v0 = __uint_as_float(dr[q * 4 + 0]);
                    float v1 = __uint_as_float(dr[q * 4 + 1]);
                    float v2 = __uint_as_float(dr[q * 4 + 2]);
                    float v3 = __uint_as_float(dr[q * 4 + 3]);
                    if (doResid) {
                        float4 r4 = *(const float4*)&R[rbase + q * 4];
                        v0 += r4.x; v1 += r4.y; v2 += r4.z; v3 += r4.w;
                    }
                    if (doFinal) {
                        v0 = isfinite(v0) ? v0 : 1e-5f;
                        v1 = isfinite(v1) ? v1 : 1e-5f;
                        v2 = isfinite(v2) ? v2 : 1e-5f;
                        v3 = isfinite(v3) ? v3 : 1e-5f;
                    }
                    *(float4*)&Y[ybase + q * 4] = make_float4(v0, v1, v2, v3);
                }
            }
        }
        TCGEN05_FENCE_BEFORE();
    }

    __syncthreads();
    if (tid == 0) { MBARRIER_INVAL(sb + SM_MBAR); MBARRIER_INVAL(sb + SM_MBAR + 8); }
    __syncthreads();
    if (wid == 0) {
        TCGEN05_RELINQUISH();
        TCGEN05_DEALLOC(tmem, 128);
    }
#else
    // ================= FFMA2 fallback (compute_103 PTX pass) =================
    const float* Wb = (pth ? W2 : W1) + (size_t)b * WstrideB;
    float2 (*Ws2)[16][128] = (float2(*)[16][128])(smem);            // 32KB
    float  (*Xs)[16][128]  = (float(*)[16][128])(smem + 32768);     // 16KB

    const int tx = tid & 15, ty = tid >> 4;
    unsigned long long acc2[8][4];
    #pragma unroll
    for (int i = 0; i < 8; ++i)
        #pragma unroll
        for (int j = 0; j < 4; ++j) acc2[i][j] = 0ULL;

    const int ktiles = (Cin + 15) >> 4;
    for (int kt = 0; kt < ktiles; ++kt) {
        int buf = kt & 1;
        int k0 = kt * 16;
        #pragma unroll
        for (int u = 0; u < 2; ++u) {
            int e4 = tid + 256 * u;
            int row = e4 & 127, kq = e4 >> 7;
            int o = o0 + row;
            #pragma unroll
            for (int t = 0; t < 4; ++t) {
                int kk = k0 + kq * 4 + t;
                float w = (o < Cout && kk < Cin) ? Wb[(size_t)o * Cin + kk] : 0.f;
                Ws2[buf][kq * 4 + t][row] = make_float2(w, w);
            }
        }
        #pragma unroll
        for (int u = 0; u < 2; ++u) {
            int e = tid + 256 * u;
            int row = e >> 5, cq = e & 31;
            int kk = k0 + row;
            float4 v = (kk < Cin) ? *(const float4*)&Xb[(size_t)kk * N_ + p0 + cq * 4]
                                  : make_float4(0.f, 0.f, 0.f, 0.f);
            if (lnOn && kk < Cin) {
                int pix = p0 + cq * 4;
                float4 m  = *(const float4*)&lnMu[(size_t)bz * N_ + pix];
                float4 iv = *(const float4*)&lnInv[(size_t)bz * N_ + pix];
                float wv = lnW[kk], bv = lnB[kk];
                v.x = (v.x - m.x) * iv.x * wv + bv;
                v.y = (v.y - m.y) * iv.y * wv + bv;
                v.z = (v.z - m.z) * iv.z * wv + bv;
                v.w = (v.w - m.w) * iv.w * wv + bv;
            }
            *(float4*)&Xs[buf][row][cq * 4] = v;
        }
        __syncthreads();
        #pragma unroll
        for (int k = 0; k < 16; ++k) {
            ulonglong2 q0 = *(const ulonglong2*)&Xs[buf][k][tx * 4];
            ulonglong2 q1 = *(const ulonglong2*)&Xs[buf][k][64 + tx * 4];
            unsigned long long bb0 = q0.x, bb1 = q0.y, bb2 = q1.x, bb3 = q1.y;
            const ulonglong2* wrow = (const ulonglong2*)&Ws2[buf][k][ty * 8];
            ulonglong2 w01 = wrow[0], w23 = wrow[1], w45 = wrow[2], w67 = wrow[3];
            unsigned long long av[8] = {w01.x, w01.y, w23.x, w23.y,
                                        w45.x, w45.y, w67.x, w67.y};
            #pragma unroll
            for (int i = 0; i < 8; ++i) {
                FMA2(acc2[i][0], av[i], bb0);
                FMA2(acc2[i][1], av[i], bb1);
                FMA2(acc2[i][2], av[i], bb2);
                FMA2(acc2[i][3], av[i], bb3);
            }
        }
        __syncthreads();
    }

    const int doResid = flags & 1, doFinal = flags & 2;
    #pragma unroll
    for (int i = 0; i < 8; ++i) {
        int o = o0 + ty * 8 + i;
        if (o >= Cout) continue;
        size_t ybase0 = ((size_t)b * YCtot + Yoff + o) * N_ + p0 + tx * 4;
        float v[8];
        #pragma unroll
        for (int j = 0; j < 4; ++j) UNPK2(v[2 * j], v[2 * j + 1], acc2[i][j]);
        if (doResid) {
            size_t rbase = ((size_t)b * Cout + o) * N_ + p0 + tx * 4;
            float4 r0 = *(const float4*)&R[rbase];
            float4 r1 = *(const float4*)&R[rbase + 64];
            v[0] += r0.x; v[1] += r0.y; v[2] += r0.z; v[3] += r0.w;
            v[4] += r1.x; v[5] += r1.y; v[6] += r1.z; v[7] += r1.w;
        }
        if (doFinal) {
            #pragma unroll
            for (int j = 0; j < 8; ++j) v[j] = isfinite(v[j]) ? v[j] : 1e-5f;
        }
        *(float4*)&Y[ybase0]      = make_float4(v[0], v[1], v[2], v[3]);
        *(float4*)&Y[ybase0 + 64] = make_float4(v[4], v[5], v[6], v[7]);
    }
#endif
}

// ---------------- per-pixel LN stats, both paths in one launch ----------------
__global__ void lnstats2k(const float* __restrict__ X1, const float* __restrict__ X2,
                          float* __restrict__ mu, float* __restrict__ inv)
{
    int p = blockIdx.x * 256 + threadIdx.x;
    int zc = blockIdx.y;
    int pth = zc >= B_;
    int b = pth ? zc - B_ : zc;
    const float* xb = (pth ? X2 : X1) + (size_t)b * C_ * N_ + p;
    float s = 0.f, ss = 0.f;
    #pragma unroll 4
    for (int c = 0; c < C_; ++c) {
        float v = xb[(size_t)c * N_];
        s += v; ss += v * v;
    }
    float m = s * (1.f / C_);
    float var = ss * (1.f / C_) - m * m;
    mu[(size_t)zc * N_ + p] = m;
    inv[(size_t)zc * N_ + p] = rsqrtf(var + 1e-5f);
}

// ---------------- fused: x_out = fuse*ca + origin ; write x_out + LN stats ----------------
__global__ void scaleaddstatsk(const float* __restrict__ fuse, const float* __restrict__ cas,
                               const float* __restrict__ origin, float* __restrict__ Y,
                               float* __restrict__ mu, float* __restrict__ inv)
{
    int p = blockIdx.x * 256 + threadIdx.x;
    int b = blockIdx.y;
    __shared__ float sc[C_];
    for (int i = threadIdx.x; i < C_; i += 256) sc[i] = cas[b * C_ + i];
    __syncthreads();
    const size_t base = (size_t)b * C_ * N_ + p;
    float s = 0.f, ss = 0.f;
    #pragma unroll 4
    for (int c = 0; c < C_; ++c) {
        float v = fuse[base + (size_t)c * N_] * sc[c] + origin[base + (size_t)c * N_];
        Y[base + (size_t)c * N_] = v;
        s += v; ss += v * v;
    }
    float m = s * (1.f / C_);
    float var = ss * (1.f / C_) - m * m;
    mu[b * N_ + p] = m;
    inv[b * N_ + p] = rsqrtf(var + 1e-5f);
}

// ---------------- ALL depthwise 3x3 for both paths (q: C ch, kv: 2C ch) ----------------
__global__ void dwallk(const float* __restrict__ qX1, const float* __restrict__ qX2,
                       const float* __restrict__ qW1, const float* __restrict__ qW2,
                       float* __restrict__ qY1, float* __restrict__ qY2,
                       const float* __restrict__ kX1, const float* __restrict__ kX2,
                       const float* __restrict__ kW1, const float* __restrict__ kW2,
                       float* __restrict__ kY1, float* __restrict__ kY2)
{
    int cidx = blockIdx.y;
    int zc = blockIdx.z;
    int pth = zc >= B_;
    int b = pth ? zc - B_ : zc;
    const float* xb; const float* Wd; float* yb; int c;
    if (cidx < C_) {
        c = cidx;
        xb = (pth ? qX2 : qX1) + ((size_t)b * C_ + c) * N_;
        Wd = (pth ? qW2 : qW1);
        yb = (pth ? qY2 : qY1) + ((size_t)b * C_ + c) * N_;
    } else {
        c = cidx - C_;
        xb = (pth ? kX2 : kX1) + ((size_t)b * C2_ + c) * N_;
        Wd = (pth ? kW2 : kW1);
        yb = (pth ? kY2 : kY1) + ((size_t)b * C2_ + c) * N_;
    }
    int y0 = blockIdx.x * 8;
    int tid = threadIdx.x;
    __shared__ float t[10][128];
    for (int i = tid; i < 320; i += 256) {
        int r = i >> 5, xq = i & 31;
        int yy = y0 - 1 + r;
        float4 v = make_float4(0.f, 0.f, 0.f, 0.f);
        if (yy >= 0 && yy < Hh_) v = *(const float4*)&xb[yy * 128 + xq * 4];
        *(float4*)&t[r][xq * 4] = v;
    }
    float w[9];
    #pragma unroll
    for (int q = 0; q < 9; ++q) w[q] = Wd[c * 9 + q];
    __syncthreads();
    int r = tid >> 5;
    int lx = tid & 31;
    float* yo = yb + (y0 + r) * 128;
    #pragma unroll
    for (int u = 0; u < 4; ++u) {
        int x = u * 32 + lx;
        float s = 0.f;
        #pragma unroll
        for (int dy = 0; dy < 3; ++dy) {
            const float* row = t[r + dy];
            float m  = row[x];
            float l  = (x > 0)   ? row[x - 1] : 0.f;
            float rr = (x < 127) ? row[x + 1] : 0.f;
            s += l * w[dy * 3] + m * w[dy * 3 + 1] + rr * w[dy * 3 + 2];
        }
        yo[x] = s;
    }
}

// ---------------- fused FFN dwconv(680) + gelu-gate -> 340 (smem-tiled) ----------------
__global__ void dwgatek(const float* __restrict__ X, const float* __restrict__ Wd,
                        float* __restrict__ Y)
{
    int c = blockIdx.y, b = blockIdx.z;
    int y0 = blockIdx.x * 8;
    int tid = threadIdx.x;
    const float* x1b = X + ((size_t)b * HID2_ + c) * N_;
    const float* x2b = X + ((size_t)b * HID2_ + c + HID_) * N_;
    __shared__ float t1[10][128];
    __shared__ float t2[10][128];
    for (int i = tid; i < 320; i += 256) {
        int r = i >> 5, xq = i & 31;
        int yy = y0 - 1 + r;
        float4 v1 = make_float4(0.f, 0.f, 0.f, 0.f);
        float4 v2 = v1;
        if (yy >= 0 && yy < Hh_) {
            v1 = *(const float4*)&x1b[yy * 128 + xq * 4];
            v2 = *(const float4*)&x2b[yy * 128 + xq * 4];
        }
        *(float4*)&t1[r][xq * 4] = v1;
        *(float4*)&t2[r][xq * 4] = v2;
    }
    float w1[9], w2[9];
    #pragma unroll
    for (int q = 0; q < 9; ++q) { w1[q] = Wd[c * 9 + q]; w2[q] = Wd[(c + HID_) * 9 + q]; }
    __syncthreads();
    int r = tid >> 5;
    int lx = tid & 31;
    float* yo = Y + ((size_t)b * HID_ + c) * N_ + (y0 + r) * 128;
    #pragma unroll
    for (int u = 0; u < 4; ++u) {
        int x = u * 32 + lx;
        float s1 = 0.f, s2 = 0.f;
        #pragma unroll
        for (int dy = 0; dy < 3; ++dy) {
            const float* r1 = t1[r + dy];
            const float* r2 = t2[r + dy];
            float m1  = r1[x],  m2  = r2[x];
            float l1  = (x > 0)   ? r1[x - 1] : 0.f;
            float l2  = (x > 0)   ? r2[x - 1] : 0.f;
            float rr1 = (x < 127) ? r1[x + 1] : 0.f;
            float rr2 = (x < 127) ? r2[x + 1] : 0.f;
            s1 += l1 * w1[dy * 3] + m1 * w1[dy * 3 + 1] + rr1 * w1[dy * 3 + 2];
            s2 += l2 * w2[dy * 3] + m2 * w2[dy * 3 + 1] + rr2 * w2[dy * 3 + 2];
        }
        float ge = 0.5f * s1 * (1.f + erff(s1 * 0.70710678118654752f));
        yo[x] = ge * s2;
    }
}

// ---------------- attention partials, both paths ----------------
__global__ void attnpartk(const float* __restrict__ Q1, const float* __restrict__ Q2,
                          const float* __restrict__ KV1, const float* __restrict__ KV2,
                          float* __restrict__ part)
{
    int chunk = blockIdx.x, h = blockIdx.y;
    int zc = blockIdx.z;
    int pth = zc >= B_;
    int b = pth ? zc - B_ : zc;
    const float* qb = (pth ? Q2 : Q1)  + ((size_t)b * C_  + h * CH_) * N_;
    const float* kb = (pth ? KV2 : KV1) + ((size_t)b * C2_ + h * CH_) * N_;

    __shared__ float sm[16 * 16 * 16];
    __shared__ float qqp[256], kkp[256];
    float* qs = sm;
    float* ks = sm + 1024;

    int tid = threadIdx.x;
    int i = tid & 15, s = tid >> 4;
    float acc[16];
    #pragma unroll
    for (int j = 0; j < 16; ++j) acc[j] = 0.f;
    float qq = 0.f, kk = 0.f;

    int nbeg = chunk * CHUNKN_;
    for (int n0 = nbeg; n0 < nbeg + CHUNKN_; n0 += 64) {
        #pragma unroll
        for (int u = 0; u < 4; ++u) {
            int e = tid + 256 * u;
            int r = e >> 6, cc = e & 63;
            qs[r * 64 + cc] = qb[(size_t)r * N_ + n0 + cc];
            ks[r * 64 + cc] = kb[(size_t)r * N_ + n0 + cc];
        }
        __syncthreads();
        #pragma unroll
        for (int t = 0; t < 4; ++t) {
            float qv = qs[i * 64 + s * 4 + t];
            float kv = ks[i * 64 + s * 4 + t];
            qq += qv * qv;
            kk += kv * kv;
            #pragma unroll
            for (int j = 0; j < 16; ++j) acc[j] += qv * ks[j * 64 + s * 4 + t];
        }
        __syncthreads();
    }
    qqp[s * 16 + i] = qq;
    kkp[s * 16 + i] = kk;
    #pragma unroll
    for (int j = 0; j < 16; ++j) sm[s * 256 + i * 16 + j] = acc[j];
    __syncthreads();

    float* pb = part + (((size_t)zc * HEADS_ + h) * NCHUNK_ + chunk) * 288;
    int i2 = tid >> 4, j2 = tid & 15;
    float a = 0.f;
    #pragma unroll
    for (int s2 = 0; s2 < 16; ++s2) a += sm[s2 * 256 + i2 * 16 + j2];
    pb[i2 * 16 + j2] = a;
    if (tid < 16) {
        float t0 = 0.f;
        #pragma unroll
        for (int s2 = 0; s2 < 16; ++s2) t0 += qqp[s2 * 16 + tid];
        pb[256 + tid] = t0;
    } else if (tid < 32) {
        int j = tid - 16;
        float t0 = 0.f;
        #pragma unroll
        for (int s2 = 0; s2 < 16; ++s2) t0 += kkp[s2 * 16 + j];
        pb[272 + j] = t0;
    }
}

// ---------------- attention finalize, both paths ----------------
__global__ void attnfink(const float* __restrict__ part, const float* __restrict__ temp1,
                         const float* __restrict__ temp2, float* __restrict__ attnOut)
{
    int h = blockIdx.x;
    int zc = blockIdx.y;
    int pth = zc >= B_;
    const float* temp = pth ? temp2 : temp1;
    const float* pb = part + ((size_t)zc * HEADS_ + h) * NCHUNK_ * 288;
    __shared__ float qqs[16], kks[16];
    int tid = threadIdx.x;

    float a = 0.f;
    #pragma unroll
    for (int c = 0; c < NCHUNK_; ++c) a += pb[c * 288 + tid];

    if (tid < 16) {
        float t0 = 0.f;
        #pragma unroll
        for (int c = 0; c < NCHUNK_; ++c) t0 += pb[c * 288 + 256 + tid];
        qqs[tid] = fmaxf(sqrtf(t0), 1e-12f);
    } else if (tid < 32) {
        int j = tid - 16;
        float t0 = 0.f;
        #pragma unroll
        for (int c = 0; c < NCHUNK_; ++c) t0 += pb[c * 288 + 272 + j];
        kks[j] = fmaxf(sqrtf(t0), 1e-12f);
    }
    __syncthreads();

    int i2 = tid >> 4, j2 = tid & 15;
    a = a / (qqs[i2] * kks[j2]) * temp[h];

    unsigned mask = 0xFFFFFFFFu;
    float mx = a;
    for (int w = 8; w > 0; w >>= 1) mx = fmaxf(mx, __shfl_xor_sync(mask, mx, w, 16));
    float e = expf(a - mx);
    float ssum = e;
    for (int w = 8; w > 0; w >>= 1) ssum += __shfl_xor_sync(mask, ssum, w, 16);
    attnOut[((size_t)zc * HEADS_ + h) * 256 + i2 * 16 + j2] = e / ssum;
}

// ---------------- M[zc] = po @ blockdiag(attn[zc]); fp32 + pre-swizzled tiles ----------------
__global__ void poattnk(const float* __restrict__ po1, const float* __restrict__ po2,
                        const float* __restrict__ attn, float* __restrict__ M,
                        uint8_t* __restrict__ MT)
{
    int zc = blockIdx.x;
    const float* po = (zc >= B_) ? po2 : po1;
    uint8_t* mt = MT + (size_t)zc * 2 * TILE_B;
    __shared__ float at[HEADS_ * 256];
    for (int i = threadIdx.x; i < HEADS_ * 256; i += 256)
        at[i] = attn[(size_t)zc * HEADS_ * 256 + i];
    __syncthreads();
    // each thread computes an adjacent (cj, cj+1) pair -> fp32 M + hi/lo tile words
    for (int idx2 = threadIdx.x; idx2 < C_ * 64; idx2 += 256) {
        int o = idx2 >> 6, j2 = idx2 & 63;
        int cj = 2 * j2;
        int h = cj >> 4;
        int jj = cj & 15;
        float s0 = 0.f, s1 = 0.f;
        #pragma unroll
        for (int i = 0; i < 16; ++i) {
            float pv = po[o * C_ + h * 16 + i];
            s0 += pv * at[h * 256 + i * 16 + jj];
            s1 += pv * at[h * 256 + i * 16 + jj + 1];
        }
        M[((size_t)zc * C_ + o) * C_ + cj] = s0;
        M[((size_t)zc * C_ + o) * C_ + cj + 1] = s1;
        uint32_t hp, lp;
        split2(s0, s1, hp, lp);
        int chk = cj >> 6;
        uint32_t off = SWZ((uint32_t)(o * 128 + (cj & 63) * 2));
        *(uint32_t*)(mt + chk * TILE_B + off) = hp;
        *(uint32_t*)(mt + chk * TILE_B + 16384 + off) = lp;
    }
}

// ---------------- global average pool per (b,c) ----------------
__global__ void capoolk(const float* __restrict__ X, float* __restrict__ pool)
{
    int c = blockIdx.x, b = blockIdx.y;
    const float* xb = X + ((size_t)b * C_ + c) * N_;
    float s = 0.f;
    for (int n = threadIdx.x * 4; n < N_; n += 1024) {
        float4 v = *(const float4*)&xb[n];
        s += v.x + v.y + v.z + v.w;
    }
    __shared__ float red[256];
    red[threadIdx.x] = s; __syncthreads();
    for (int st = 128; st > 0; st >>= 1) {
        if (threadIdx.x < st) red[threadIdx.x] += red[threadIdx.x + st];
        __syncthreads();
    }
    if (threadIdx.x == 0) pool[b * C_ + c] = red[0] * (1.f / N_);
}

// ---------------- CA: relu FC (128->8) + sigmoid FC (8->128) ----------------
__global__ void cafck(const float* __restrict__ pool,
                      const float* __restrict__ w1, const float* __restrict__ b1,
                      const float* __restrict__ w2, const float* __restrict__ b2,
                      float* __restrict__ cas)
{
    int b = blockIdx.x, t = threadIdx.x;
    __shared__ float pl[C_];
    __shared__ float hid[8];
    pl[t] = pool[b * C_ + t];
    __syncthreads();
    if (t < 8) {
        float s = b1[t];
        #pragma unroll 4
        for (int c = 0; c < C_; ++c) s += w1[t * C_ + c] * pl[c];
        hid[t] = fmaxf(s, 0.f);
    }
    __syncthreads();
    float s = b2[t];
    #pragma unroll
    for (int r = 0; r < 8; ++r) s += w2[t * 8 + r] * hid[r];
    cas[b * C_ + t] = 1.f / (1.f + expf(-s));
}

// ---------------- host ----------------
extern "C" void kernel_launch(void* const* d_in, const int* in_sizes, int n_in,
                              void* d_out, int out_size)
{
    (void)in_sizes; (void)n_in; (void)out_size;
    const float* origin  = (const float*)d_in[0];
    const float* low     = (const float*)d_in[1];
    const float* high    = (const float*)d_in[2];
    const float* norm1_w = (const float*)d_in[3];
    const float* norm1_b = (const float*)d_in[4];
    const float* norm_1_w= (const float*)d_in[5];
    const float* norm_1_b= (const float*)d_in[6];
    const float* norm2_w = (const float*)d_in[7];
    const float* norm2_b = (const float*)d_in[8];
    const float* a1_q    = (const float*)d_in[9];
    const float* a1_qdw  = (const float*)d_in[10];
    const float* a1_kv   = (const float*)d_in[11];
    const float* a1_kvdw = (const float*)d_in[12];
    const float* a1_po   = (const float*)d_in[13];
    const float* a1_temp = (const float*)d_in[14];
    const float* a2_q    = (const float*)d_in[15];
    const float* a2_qdw  = (const float*)d_in[16];
    const float* a2_kv   = (const float*)d_in[17];
    const float* a2_kvdw = (const float*)d_in[18];
    const float* a2_po   = (const float*)d_in[19];
    const float* a2_temp = (const float*)d_in[20];
    const float* conv1_w = (const float*)d_in[21];
    const float* ca1_w   = (const float*)d_in[22];
    const float* ca1_b   = (const float*)d_in[23];
    const float* ca2_w   = (const float*)d_in[24];
    const float* ca2_b   = (const float*)d_in[25];
    const float* ffn_pi  = (const float*)d_in[26];
    const float* ffn_dw  = (const float*)d_in[27];
    const float* ffn_po  = (const float*)d_in[28];
    float* out = (float*)d_out;

    float *bufCb, *bufCc, *bufCd, *bufCe, *buf2Ca, *buf2Cb, *buf2Cc, *bufHa, *bufHb, *xout;
    float *mu, *inv, *attnp, *attnw, *Mw, *pool, *cas;
    uint8_t *wt, *MwT;
    cudaGetSymbolAddress((void**)&bufCb, g_bufCb);
    cudaGetSymbolAddress((void**)&bufCc, g_bufCc);
    cudaGetSymbolAddress((void**)&bufCd, g_bufCd);
    cudaGetSymbolAddress((void**)&bufCe, g_bufCe);
    cudaGetSymbolAddress((void**)&buf2Ca, g_buf2Ca);
    cudaGetSymbolAddress((void**)&buf2Cb, g_buf2Cb);
    cudaGetSymbolAddress((void**)&buf2Cc, g_buf2Cc);
    cudaGetSymbolAddress((void**)&bufHa, g_bufHa);
    cudaGetSymbolAddress((void**)&bufHb, g_bufHb);
    cudaGetSymbolAddress((void**)&xout, g_xout);
    cudaGetSymbolAddress((void**)&mu, g_mu);
    cudaGetSymbolAddress((void**)&inv, g_inv);
    cudaGetSymbolAddress((void**)&attnp, g_attnp);
    cudaGetSymbolAddress((void**)&attnw, g_attnw);
    cudaGetSymbolAddress((void**)&Mw, g_Mw);
    cudaGetSymbolAddress((void**)&pool, g_pool);
    cudaGetSymbolAddress((void**)&cas, g_cas);
    cudaGetSymbolAddress((void**)&wt, g_wt);
    cudaGetSymbolAddress((void**)&MwT, g_MwT);

    static int smem_set = 0;
    if (!smem_set) {
        cudaFuncSetAttribute(gemmtc, cudaFuncAttributeMaxDynamicSharedMemorySize, SM_TOTAL);
        smem_set = 1;
    }

    // tile offsets (in tiles of TILE_B bytes)
    uint8_t* t_a1q  = wt;                 // 1x2 = 2 tiles
    uint8_t* t_a2q  = wt + 2  * TILE_B;   // 2
    uint8_t* t_a1kv = wt + 4  * TILE_B;   // 2x2 = 4
    uint8_t* t_a2kv = wt + 8  * TILE_B;   // 4
    uint8_t* t_cv1  = wt + 12 * TILE_B;   // 1x4 = 4
    uint8_t* t_fpi  = wt + 16 * TILE_B;   // 6x2 = 12
    uint8_t* t_fpo  = wt + 28 * TILE_B;   // 1x6 = 6

    dim3 tb(256);
    // ===== weight pre-tiling (tiny) =====
    wtilek<<<dim3(2, 1), tb>>>(a1_q, t_a1q, C_, C_);
    wtilek<<<dim3(2, 1), tb>>>(a2_q, t_a2q, C_, C_);
    wtilek<<<dim3(2, 2), tb>>>(a1_kv, t_a1kv, C2_, C_);
    wtilek<<<dim3(2, 2), tb>>>(a2_kv, t_a2kv, C2_, C_);
    wtilek<<<dim3(4, 1), tb>>>(conv1_w, t_cv1, C_, C2_);
    wtilek<<<dim3(2, 6), tb>>>(ffn_pi, t_fpi, HID2_, C_);
    wtilek<<<dim3(6, 1), tb>>>(ffn_po, t_fpo, C_, HID_);

    dim3 gLN2(N_ / 256, 2 * B_);
    dim3 gLN(N_ / 256, B_);
    dim3 gQ(N_ / 128, 1, 2 * B_);
    dim3 gKV(N_ / 128, 2, 2 * B_);
    dim3 gMv(N_ / 128, 1, 2 * B_);
    dim3 gG_C(N_ / 128, 1, B_);
    dim3 gG_H(N_ / 128, (HID2_ + 127) / 128, B_);
    dim3 gRow(C_, B_);
    dim3 gAttnP(NCHUNK_, HEADS_, 2 * B_);
    dim3 gAttnF(HEADS_, 2 * B_);
    dim3 gDWall(Hh_ / 8, C_ + C2_, 2 * B_);
    dim3 gDW_H(Hh_ / 8, HID_, B_);

    // ===== both attention paths, merged launches =====
    gemmtc<<<gQ, tb, SM_TOTAL>>>(t_a1q, high, bufCb, nullptr,
                                 t_a2q, low, bufCc, nullptr,
                                 a1_q, a2_q,
                                 nullptr, nullptr, nullptr, nullptr, nullptr, nullptr,
                                 C_, C_, C_, C_, 0, 0, 0, 0, 0);
    lnstats2k<<<gLN2, tb>>>(low, high, mu, inv);
    gemmtc<<<gKV, tb, SM_TOTAL>>>(t_a1kv, low, buf2Ca, nullptr,
                                  t_a2kv, high, buf2Cb, nullptr,
                                  a1_kv, a2_kv,
                                  mu, inv, norm1_w, norm1_b, norm_1_w, norm_1_b,
                                  C2_, C_, C_, C2_, 0, 0, 4, 0, 0);
    dwallk<<<gDWall, tb>>>(bufCb, bufCc, a1_qdw, a2_qdw, bufCd, bufCe,
                           buf2Ca, buf2Cb, a1_kvdw, a2_kvdw, buf2Cc, bufHa);
    attnpartk<<<gAttnP, tb>>>(bufCd, bufCe, buf2Cc, bufHa, attnp);
    attnfink<<<gAttnF, tb>>>(attnp, a1_temp, a2_temp, attnw);
    poattnk<<<dim3(2 * B_), tb>>>(a1_po, a2_po, attnw, Mw, MwT);
    gemmtc<<<gMv, tb, SM_TOTAL>>>(MwT, buf2Cc + (size_t)C_ * N_, buf2Ca, low,
                                  MwT + (size_t)B_ * 2 * TILE_B, bufHa + (size_t)C_ * N_, buf2Ca, high,
                                  Mw, Mw + (size_t)B_ * C_ * C_,
                                  nullptr, nullptr, nullptr, nullptr, nullptr, nullptr,
                                  C_, C_, C2_, C2_, 0, C_, 1, 2, C_ * C_);

    // ===== fuse: conv1(concat) -> CA -> + origin, fused with norm2 stats =====
    gemmtc<<<gG_C, tb, SM_TOTAL>>>(t_cv1, buf2Ca, bufCb, nullptr,
                                   t_cv1, buf2Ca, bufCb, nullptr,
                                   conv1_w, conv1_w,
                                   nullptr, nullptr, nullptr, nullptr, nullptr, nullptr,
                                   C_, C2_, C2_, C_, 0, 0, 0, 0, 0);
    capoolk<<<gRow, tb>>>(bufCb, pool);
    cafck<<<dim3(B_), dim3(128)>>>(pool, ca1_w, ca1_b, ca2_w, ca2_b, cas);
    scaleaddstatsk<<<gLN, tb>>>(bufCb, cas, origin, xout, mu, inv);

    // ===== FFN with residual =====
    gemmtc<<<gG_H, tb, SM_TOTAL>>>(t_fpi, xout, bufHa, nullptr,
                                   t_fpi, xout, bufHa, nullptr,
                                   ffn_pi, ffn_pi,
                                   mu, inv, norm2_w, norm2_b, norm2_w, norm2_b,
                                   HID2_, C_, C_, HID2_, 0, 0, 4, 0, 0);
    dwgatek<<<gDW_H, tb>>>(bufHa, ffn_dw, bufHb);
    gemmtc<<<gG_C, tb, SM_TOTAL>>>(t_fpo, bufHb, out, xout,
                                   t_fpo, bufHb, out, xout,
                                   ffn_po, ffn_po,
                                   nullptr, nullptr, nullptr, nullptr, nullptr, nullptr,
                                   C_, HID_, HID_, C_, 0, 0, 3, 0, 0);
}

// round 13
// speedup vs baseline: 1.2823x; 1.0327x over previous
#include <cuda_runtime.h>
#include <cuda_bf16.h>
#include <math.h>
#include <stdint.h>

#define B_    8
#define C_    128
#define Hh_   128
#define Ww_   128
#define N_    16384      // H*W
#define HEADS_ 8
#define CH_   16         // C/HEADS
#define HID_  340
#define HID2_ 680
#define C2_   256
#define NCHUNK_ 16
#define CHUNKN_ (N_ / NCHUNK_)   // 1024
#define TILE_B 32768             // one pre-swizzled W tile: 16KB hi + 16KB lo

// ---------------- static scratch (no allocations allowed) ----------------
__device__ float g_bufCb[(size_t)B_ * C_ * N_];   // qpre path1 / conv1 out
__device__ float g_bufCc[(size_t)B_ * C_ * N_];   // qpre path2
__device__ float g_buf2Ca[(size_t)B_ * C2_ * N_]; // kvpre path1 / concat out
__device__ float g_buf2Cb[(size_t)B_ * C2_ * N_]; // kvpre path2
__device__ float g_buf2Cc[(size_t)B_ * C2_ * N_]; // kvdw path1
__device__ float g_bufHa[(size_t)B_ * HID2_ * N_];// kvdw path2 (front 2C) / ffn hidden
__device__ float g_bufHb[(size_t)B_ * HID_ * N_]; // gated
__device__ float g_xout[(size_t)B_ * C_ * N_];
__device__ float g_mu[2 * B_ * N_];
__device__ float g_inv[2 * B_ * N_];
__device__ float g_attnp[2 * B_ * HEADS_ * NCHUNK_ * 288];
__device__ float g_attnw[2 * B_ * HEADS_ * CH_ * CH_];
__device__ float g_Mw[2 * B_ * C_ * C_];
__device__ float g_pool[B_ * C_];
__device__ float g_cas[B_ * C_];
// pre-swizzled weight tiles: 34 static + 32 for Mw
__device__ __align__(16) uint8_t g_wt[34 * TILE_B];
__device__ __align__(16) uint8_t g_MwT[32 * TILE_B];

// packed f32x2 helpers (fallback path)
#define FMA2(d, a, b) asm("fma.rn.f32x2 %0, %1, %2, %0;" : "+l"(d) : "l"(a), "l"(b))
#define UNPK2(lo, hi, s) asm("mov.b64 {%0, %1}, %2;" : "=f"(lo), "=f"(hi) : "l"(s))

// ---------------- PTX helpers ----------------
__device__ __forceinline__ uint32_t smem_u32(const void* p) {
    uint32_t a;
    asm("{ .reg .u64 t; cvta.to.shared.u64 t, %1; cvt.u32.u64 %0, t; }" : "=r"(a) : "l"(p));
    return a;
}
#define SWZ(o) ((o) ^ (((o) >> 3) & 0x70))

#if defined(__CUDA_ARCH_FEAT_SM103_ALL) || !defined(__CUDA_ARCH__)
#define HAS_TC 1
#else
#define HAS_TC 0
#endif

#define MBARRIER_INIT(addr, cnt) \
    asm volatile("mbarrier.init.shared.b64 [%0], %1;" :: "r"((uint32_t)(addr)), "r"((uint32_t)(cnt)) : "memory")
#define MBARRIER_INVAL(addr) \
    asm volatile("mbarrier.inval.shared.b64 [%0];" :: "r"((uint32_t)(addr)) : "memory")
#define MBARRIER_WAIT_PARITY(mbar_smem_addr, phase_parity) do { \
    uint32_t _mbar = (uint32_t)(mbar_smem_addr); \
    uint32_t _parity = (uint32_t)(phase_parity); \
    uint32_t _done; \
    asm volatile("{\n\t.reg .pred p;\n\t" \
        "mbarrier.try_wait.parity.acquire.cta.shared::cta.b64 p, [%1], %2;\n\t" \
        "selp.b32 %0, 1, 0, p;\n\t}" : "=r"(_done) : "r"(_mbar), "r"(_parity) : "memory"); \
    if (!_done) { \
        asm volatile("{\n\t.reg .pred P1;\n\t" \
            "WAIT_LOOP_%=:\n\t" \
            "mbarrier.try_wait.parity.acquire.cta.shared::cta.b64 P1, [%0], %1, 0x989680;\n\t" \
            "@P1 bra.uni WAIT_DONE_%=;\n\t" \
            "bra.uni WAIT_LOOP_%=;\n\t" \
            "WAIT_DONE_%=:\n\t}" :: "r"(_mbar), "r"(_parity) : "memory"); \
    } \
} while (0)

#if HAS_TC
#define TCGEN05_ALLOC(smem_result_addr, nCols) \
    asm volatile("tcgen05.alloc.cta_group::1.sync.aligned.shared::cta.b32 [%0], %1;" \
        :: "r"((uint32_t)(smem_result_addr)), "r"((uint32_t)(nCols)) : "memory")
#define TCGEN05_DEALLOC(tmem_addr, nCols) \
    asm volatile("tcgen05.dealloc.cta_group::1.sync.aligned.b32 %0, %1;" :: "r"(tmem_addr), "r"((uint32_t)(nCols)))
#define TCGEN05_RELINQUISH() \
    asm volatile("tcgen05.relinquish_alloc_permit.cta_group::1.sync.aligned;")
#define TCGEN05_COMMIT(mbar_smem_addr) \
    asm volatile("tcgen05.commit.cta_group::1.mbarrier::arrive::one.shared::cluster.b64 [%0];" \
        :: "r"((uint32_t)(mbar_smem_addr)) : "memory")
#define TCGEN05_FENCE_AFTER() asm volatile("tcgen05.fence::after_thread_sync;" ::: "memory")
#define TCGEN05_FENCE_BEFORE() asm volatile("tcgen05.fence::before_thread_sync;" ::: "memory")
#define TCGEN05_WAIT_LD() asm volatile("tcgen05.wait::ld.sync.aligned;" ::: "memory")
#define FENCE_ASYNC_SHARED() asm volatile("fence.proxy.async.shared::cta;" ::: "memory")

#define TCGEN05_LD_32X32B_X32(r, tmem_addr) \
    asm volatile( \
        "tcgen05.ld.sync.aligned.32x32b.x32.b32 " \
        "{%0, %1, %2, %3, %4, %5, %6, %7, " \
        " %8, %9, %10, %11, %12, %13, %14, %15, " \
        " %16, %17, %18, %19, %20, %21, %22, %23, " \
        " %24, %25, %26, %27, %28, %29, %30, %31}, [%32];" \
        : "=r"((r)[0]),  "=r"((r)[1]),  "=r"((r)[2]),  "=r"((r)[3]), \
          "=r"((r)[4]),  "=r"((r)[5]),  "=r"((r)[6]),  "=r"((r)[7]), \
          "=r"((r)[8]),  "=r"((r)[9]),  "=r"((r)[10]), "=r"((r)[11]), \
          "=r"((r)[12]), "=r"((r)[13]), "=r"((r)[14]), "=r"((r)[15]), \
          "=r"((r)[16]), "=r"((r)[17]), "=r"((r)[18]), "=r"((r)[19]), \
          "=r"((r)[20]), "=r"((r)[21]), "=r"((r)[22]), "=r"((r)[23]), \
          "=r"((r)[24]), "=r"((r)[25]), "=r"((r)[26]), "=r"((r)[27]), \
          "=r"((r)[28]), "=r"((r)[29]), "=r"((r)[30]), "=r"((r)[31]) \
        : "r"(tmem_addr))

// SW128 SMEM descriptor (LBO=1, SBO=64, version=1, layout=SW128)
__device__ __forceinline__ uint64_t make_desc(uint32_t addr) {
    const uint64_t base = (uint64_t(2) << 61) | (uint64_t(1) << 46)
                        | (uint64_t(64) << 32) | (uint64_t(1) << 16);
    return base | ((uint64_t)(addr >> 4) & 0x3FFF);
}

// bf16 SS MMA, cg1: D[M=128, N=128] += A[M,K=16] * B[N,K=16]^T
#define MMA_IDESC 0x8200490u
__device__ __forceinline__ void mma_bf16_ss(uint32_t d, uint64_t ad, uint64_t bd, uint32_t en) {
    asm volatile(
        "{\n\t.reg .pred p;\n\tsetp.ne.u32 p, %5, 0;\n\t"
        "tcgen05.mma.cta_group::1.kind::f16 [%0], %1, %2, %3, {%4, %4, %4, %4}, p;\n\t}"
        :: "r"(d), "l"(ad), "l"(bd), "r"(MMA_IDESC), "r"(0u), "r"(en) : "memory");
}
#endif  // HAS_TC

// dynamic smem layout (bytes) — DOUBLE-buffered (R9-proven)
#define SM_TMEM   0
#define SM_MBAR   16           // 2 mbarriers @16, @24
#define SM_XS     64           // fp32 staging: 64 x 132 floats = 33792 B
#define SM_TILES  34816        // 1024-aligned; per buffer: AHI,ALO,BHI,BLO @16KB
#define SM_BUFSZ  65536
#define SM_TOTAL  (SM_TILES + 2 * SM_BUFSZ)   // 165888 B

// truncation-based hi/lo bf16 split, packed pairs via PRMT
__device__ __forceinline__ uint32_t prmt_hi(uint32_t u0, uint32_t u1) {
    uint32_t r;
    asm("prmt.b32 %0, %1, %2, 0x7632;" : "=r"(r) : "r"(u0), "r"(u1));
    return r;
}
__device__ __forceinline__ void split2(float x0, float x1, uint32_t& hp, uint32_t& lp) {
    uint32_t u0 = __float_as_uint(x0), u1 = __float_as_uint(x1);
    hp = prmt_hi(u0, u1);
    float l0 = x0 - __uint_as_float(u0 & 0xFFFF0000u);
    float l1 = x1 - __uint_as_float(u1 & 0xFFFF0000u);
    lp = prmt_hi(__float_as_uint(l0), __float_as_uint(l1));
}

// ---------------- merged weight pre-tiler: all 7 weights in ONE launch ----------------
__global__ void wtileall(const float* __restrict__ a1q, const float* __restrict__ a2q,
                         const float* __restrict__ a1kv, const float* __restrict__ a2kv,
                         const float* __restrict__ cv1, const float* __restrict__ fpi,
                         const float* __restrict__ fpo, uint8_t* __restrict__ tiles)
{
    int t = blockIdx.x;   // 0..33
    const float* W; int Cout, Cin, base;
    if (t < 2)       { W = a1q;  Cout = C_;    Cin = C_;   base = 0;  }
    else if (t < 4)  { W = a2q;  Cout = C_;    Cin = C_;   base = 2;  }
    else if (t < 8)  { W = a1kv; Cout = C2_;   Cin = C_;   base = 4;  }
    else if (t < 12) { W = a2kv; Cout = C2_;   Cin = C_;   base = 8;  }
    else if (t < 16) { W = cv1;  Cout = C_;    Cin = C2_;  base = 12; }
    else if (t < 28) { W = fpi;  Cout = HID2_; Cin = C_;   base = 16; }
    else             { W = fpo;  Cout = C_;    Cin = HID_; base = 28; }
    int lt = t - base;
    int KchT = (Cin + 63) >> 6;
    int kt = lt % KchT, ot = lt / KchT;
    uint8_t* tb = tiles + (size_t)t * TILE_B;

    const int tid = threadIdx.x;
    int r = tid >> 1;
    int kh = (tid & 1) << 5;
    int o = ot * 128 + r;
    #pragma unroll
    for (int i = 0; i < 8; ++i) {
        int kk = kt * 64 + kh + i * 4;
        float4 v;
        v.x = (o < Cout && kk + 0 < Cin) ? W[(size_t)o * Cin + kk + 0] : 0.f;
        v.y = (o < Cout && kk + 1 < Cin) ? W[(size_t)o * Cin + kk + 1] : 0.f;
        v.z = (o < Cout && kk + 2 < Cin) ? W[(size_t)o * Cin + kk + 2] : 0.f;
        v.w = (o < Cout && kk + 3 < Cin) ? W[(size_t)o * Cin + kk + 3] : 0.f;
        uint32_t hp0, lp0, hp1, lp1;
        split2(v.x, v.y, hp0, lp0);
        split2(v.z, v.w, hp1, lp1);
        uint32_t off = SWZ((uint32_t)(r * 128 + (kh + i * 4) * 2));
        *(uint2*)(tb + off) = make_uint2(hp0, hp1);
        *(uint2*)(tb + 16384 + off) = make_uint2(lp0, lp1);
    }
}

// ---------------- GEMM: Y[b, Yoff+o, p] = sum_c W[o,c] LN?(X[b,c,p]) ----------------
// flags: 1=residual add, 2=nan_to_num, 4=apply LN to X on load
__global__ void __launch_bounds__(256, 1)
gemmtc(const uint8_t* __restrict__ Wt1, const float* __restrict__ X1,
       float* __restrict__ Y1, const float* __restrict__ R1,
       const uint8_t* __restrict__ Wt2, const float* __restrict__ X2,
       float* __restrict__ Y2, const float* __restrict__ R2,
       const float* __restrict__ W1, const float* __restrict__ W2,
       const float* __restrict__ lnMu, const float* __restrict__ lnInv,
       const float* __restrict__ lnW1, const float* __restrict__ lnB1,
       const float* __restrict__ lnW2, const float* __restrict__ lnB2,
       int Cout, int Cin, int XCtot, int YCtot, int Yoff1, int Yoff2,
       int flags, int WtTilesPerB, int WstrideB)
{
    extern __shared__ __align__(1024) char smem[];

    const int bz = blockIdx.z;
    const int pth = bz >= B_;
    const int b = pth ? bz - B_ : bz;
    const int o0 = blockIdx.y * 128;
    const int p0 = blockIdx.x * 128;
    const float* Xb = (pth ? X2 : X1) + (size_t)b * XCtot * N_;
    float* Y = pth ? Y2 : Y1;
    const float* R = pth ? R2 : R1;
    const float* lnW = pth ? lnW2 : lnW1;
    const float* lnB = pth ? lnB2 : lnB1;
    const int Yoff = pth ? Yoff2 : Yoff1;
    const int lnOn = flags & 4;
    const int tid = threadIdx.x;
    const int nch = (Cin + 63) >> 6;   // == KchT

#if HAS_TC && defined(__CUDA_ARCH__)
    // ================= tcgen05 path (sm_103a cubin) =================
    const uint8_t* Wtb = (pth ? Wt2 : Wt1) + (size_t)b * WtTilesPerB * TILE_B;
    const uint32_t sb = smem_u32(smem);
    const int wid = tid >> 5;

    if (tid == 0) {
        MBARRIER_INIT(sb + SM_MBAR, 1);
        MBARRIER_INIT(sb + SM_MBAR + 8, 1);
    }
    if (wid == 0) TCGEN05_ALLOC(sb + SM_TMEM, 128);
    __syncthreads();
    uint32_t tmem;
    asm volatile("ld.shared.b32 %0, [%1];" : "=r"(tmem) : "r"(sb + SM_TMEM));

    int ph0 = 0, ph1 = 0;
    uint32_t en = 0;
    float* xs = (float*)(smem + SM_XS);

    for (int ch = 0; ch < nch; ++ch) {
        const int bf = ch & 1;
        const int k0 = ch << 6;
        if (ch >= 2) {
            if (bf == 0) { MBARRIER_WAIT_PARITY(sb + SM_MBAR, ph0); ph0 ^= 1; }
            else         { MBARRIER_WAIT_PARITY(sb + SM_MBAR + 8, ph1); ph1 ^= 1; }
        }
        char* abase = smem + SM_TILES + bf * SM_BUFSZ;   // AHI (+16K ALO)
        char* bbase = abase + 32768;                     // BHI
        char* blbase = abase + 49152;                    // BLO

        // ---- stage A: straight copy of pre-swizzled hi/lo tile (32KB) ----
        {
            const uint4* src = (const uint4*)(Wtb + ((size_t)(blockIdx.y * nch + ch)) * TILE_B);
            uint4* dst = (uint4*)abase;
            #pragma unroll
            for (int i = 0; i < 8; ++i)
                dst[tid + 256 * i] = src[tid + 256 * i];
        }

        // ---- stage B phase 1: X [64 k][128 p] fp32 -> Xs (LN applied) ----
        {
            int kr = tid >> 2;
            int pc = (tid & 3) << 5;
            int kk = k0 + kr;
            float* xrow = xs + kr * 132 + pc;
            if (kk < Cin) {
                const float* src = Xb + (size_t)kk * N_ + p0 + pc;
                if (lnOn) {
                    float wv = lnW[kk], bv = lnB[kk];
                    #pragma unroll
                    for (int i = 0; i < 8; ++i) {
                        float4 v = *(const float4*)&src[i * 4];
                        float4 m  = *(const float4*)&lnMu[(size_t)bz * N_ + p0 + pc + i * 4];
                        float4 iv = *(const float4*)&lnInv[(size_t)bz * N_ + p0 + pc + i * 4];
                        v.x = (v.x - m.x) * iv.x * wv + bv;
                        v.y = (v.y - m.y) * iv.y * wv + bv;
                        v.z = (v.z - m.z) * iv.z * wv + bv;
                        v.w = (v.w - m.w) * iv.w * wv + bv;
                        *(float4*)&xrow[i * 4] = v;
                    }
                } else {
                    #pragma unroll
                    for (int i = 0; i < 8; ++i)
                        *(float4*)&xrow[i * 4] = *(const float4*)&src[i * 4];
                }
            } else {
                #pragma unroll
                for (int i = 0; i < 8; ++i)
                    *(float4*)&xrow[i * 4] = make_float4(0.f, 0.f, 0.f, 0.f);
            }
        }
        __syncthreads();

        // ---- stage B phase 2: transpose + convert -> B[n][k] hi/lo bf16 SW128 ----
        {
            int n = tid & 127;
            int half = tid >> 7;
            #pragma unroll
            for (int g = 0; g < 4; ++g) {
                uint32_t hw[4], lw[4];
                #pragma unroll
                for (int q = 0; q < 4; ++q) {
                    int k1 = half * 32 + g * 8 + q * 2;
                    split2(xs[(k1 + 0) * 132 + n], xs[(k1 + 1) * 132 + n], hw[q], lw[q]);
                }
                uint32_t off = SWZ((uint32_t)(n * 128 + half * 64 + g * 16));
                *(uint4*)(bbase + off) = make_uint4(hw[0], hw[1], hw[2], hw[3]);
                *(uint4*)(blbase + off) = make_uint4(lw[0], lw[1], lw[2], lw[3]);
            }
        }
        FENCE_ASYNC_SHARED();
        __syncthreads();

        // ---- issue MMAs for this chunk ----
        if (tid == 0) {
            uint64_t ah = make_desc(sb + SM_TILES + bf * SM_BUFSZ);
            uint64_t al = ah + (16384 >> 4);
            uint64_t bh = ah + (32768 >> 4);
            uint64_t bl = ah + (49152 >> 4);
            #pragma unroll
            for (int s = 0; s < 4; ++s) {
                uint64_t ofs = s * 2;
                mma_bf16_ss(tmem, ah + ofs, bh + ofs, en); en = 1;
                mma_bf16_ss(tmem, ah + ofs, bl + ofs, 1);
                mma_bf16_ss(tmem, al + ofs, bh + ofs, 1);
            }
            TCGEN05_COMMIT(sb + SM_MBAR + bf * 8);
        }
    }

    // ---- drain ----
    { MBARRIER_WAIT_PARITY(sb + SM_MBAR, ph0); }
    if (nch >= 2) { MBARRIER_WAIT_PARITY(sb + SM_MBAR + 8, ph1); }
    TCGEN05_FENCE_AFTER();

    // ---- epilogue: warps 0-3 read TMEM D and store ----
    const int doResid = flags & 1, doFinal = flags & 2;
    if (tid < 128) {
        int w = tid >> 5, l = tid & 31;
        int o = o0 + w * 32 + l;
        #pragma unroll
        for (int g = 0; g < 4; ++g) {
            uint32_t dr[32];
            TCGEN05_LD_32X32B_X32(dr, tmem + g * 32);
            TCGEN05_WAIT_LD();
            if (o < Cout) {
                size_t ybase = ((size_t)b * YCtot + Yoff + o) * N_ + p0 + g * 32;
                size_t rbase = ((size_t)b * Cout + o) * N_ + p0 + g * 32;
                #pragma unroll
                for (int q = 0; q < 8; ++q) {
                    float v0 = __uint_as_float(dr[q * 4 + 0]);
                    float v1 = __uint_as_float(dr[q * 4 + 1]);
                    float v2 = __uint_as_float(dr[q * 4 + 2]);
                    float v3 = __uint_as_float(dr[q * 4 + 3]);
                    if (doResid) {
                        float4 r4 = *(const float4*)&R[rbase + q * 4];
                        v0 += r4.x; v1 += r4.y; v2 += r4.z; v3 += r4.w;
                    }
                    if (doFinal) {
                        v0 = isfinite(v0) ? v0 : 1e-5f;
                        v1 = isfinite(v1) ? v1 : 1e-5f;
                        v2 = isfinite(v2) ? v2 : 1e-5f;
                        v3 = isfinite(v3) ? v3 : 1e-5f;
                    }
                    *(float4*)&Y[ybase + q * 4] = make_float4(v0, v1, v2, v3);
                }
            }
        }
        TCGEN05_FENCE_BEFORE();
    }

    __syncthreads();
    if (tid == 0) { MBARRIER_INVAL(sb + SM_MBAR); MBARRIER_INVAL(sb + SM_MBAR + 8); }
    __syncthreads();
    if (wid == 0) {
        TCGEN05_RELINQUISH();
        TCGEN05_DEALLOC(tmem, 128);
    }
#else
    // ================= FFMA2 fallback (compute_103 PTX pass) =================
    const float* Wb = (pth ? W2 : W1) + (size_t)b * WstrideB;
    float2 (*Ws2)[16][128] = (float2(*)[16][128])(smem);            // 32KB
    float  (*Xs)[16][128]  = (float(*)[16][128])(smem + 32768);     // 16KB

    const int tx = tid & 15, ty = tid >> 4;
    unsigned long long acc2[8][4];
    #pragma unroll
    for (int i = 0; i < 8; ++i)
        #pragma unroll
        for (int j = 0; j < 4; ++j) acc2[i][j] = 0ULL;

    const int ktiles = (Cin + 15) >> 4;
    for (int kt = 0; kt < ktiles; ++kt) {
        int buf = kt & 1;
        int k0 = kt * 16;
        #pragma unroll
        for (int u = 0; u < 2; ++u) {
            int e4 = tid + 256 * u;
            int row = e4 & 127, kq = e4 >> 7;
            int o = o0 + row;
            #pragma unroll
            for (int t = 0; t < 4; ++t) {
                int kk = k0 + kq * 4 + t;
                float w = (o < Cout && kk < Cin) ? Wb[(size_t)o * Cin + kk] : 0.f;
                Ws2[buf][kq * 4 + t][row] = make_float2(w, w);
            }
        }
        #pragma unroll
        for (int u = 0; u < 2; ++u) {
            int e = tid + 256 * u;
            int row = e >> 5, cq = e & 31;
            int kk = k0 + row;
            float4 v = (kk < Cin) ? *(const float4*)&Xb[(size_t)kk * N_ + p0 + cq * 4]
                                  : make_float4(0.f, 0.f, 0.f, 0.f);
            if (lnOn && kk < Cin) {
                int pix = p0 + cq * 4;
                float4 m  = *(const float4*)&lnMu[(size_t)bz * N_ + pix];
                float4 iv = *(const float4*)&lnInv[(size_t)bz * N_ + pix];
                float wv = lnW[kk], bv = lnB[kk];
                v.x = (v.x - m.x) * iv.x * wv + bv;
                v.y = (v.y - m.y) * iv.y * wv + bv;
                v.z = (v.z - m.z) * iv.z * wv + bv;
                v.w = (v.w - m.w) * iv.w * wv + bv;
            }
            *(float4*)&Xs[buf][row][cq * 4] = v;
        }
        __syncthreads();
        #pragma unroll
        for (int k = 0; k < 16; ++k) {
            ulonglong2 q0 = *(const ulonglong2*)&Xs[buf][k][tx * 4];
            ulonglong2 q1 = *(const ulonglong2*)&Xs[buf][k][64 + tx * 4];
            unsigned long long bb0 = q0.x, bb1 = q0.y, bb2 = q1.x, bb3 = q1.y;
            const ulonglong2* wrow = (const ulonglong2*)&Ws2[buf][k][ty * 8];
            ulonglong2 w01 = wrow[0], w23 = wrow[1], w45 = wrow[2], w67 = wrow[3];
            unsigned long long av[8] = {w01.x, w01.y, w23.x, w23.y,
                                        w45.x, w45.y, w67.x, w67.y};
            #pragma unroll
            for (int i = 0; i < 8; ++i) {
                FMA2(acc2[i][0], av[i], bb0);
                FMA2(acc2[i][1], av[i], bb1);
                FMA2(acc2[i][2], av[i], bb2);
                FMA2(acc2[i][3], av[i], bb3);
            }
        }
        __syncthreads();
    }

    const int doResid = flags & 1, doFinal = flags & 2;
    #pragma unroll
    for (int i = 0; i < 8; ++i) {
        int o = o0 + ty * 8 + i;
        if (o >= Cout) continue;
        size_t ybase0 = ((size_t)b * YCtot + Yoff + o) * N_ + p0 + tx * 4;
        float v[8];
        #pragma unroll
        for (int j = 0; j < 4; ++j) UNPK2(v[2 * j], v[2 * j + 1], acc2[i][j]);
        if (doResid) {
            size_t rbase = ((size_t)b * Cout + o) * N_ + p0 + tx * 4;
            float4 r0 = *(const float4*)&R[rbase];
            float4 r1 = *(const float4*)&R[rbase + 64];
            v[0] += r0.x; v[1] += r0.y; v[2] += r0.z; v[3] += r0.w;
            v[4] += r1.x; v[5] += r1.y; v[6] += r1.z; v[7] += r1.w;
        }
        if (doFinal) {
            #pragma unroll
            for (int j = 0; j < 8; ++j) v[j] = isfinite(v[j]) ? v[j] : 1e-5f;
        }
        *(float4*)&Y[ybase0]      = make_float4(v[0], v[1], v[2], v[3]);
        *(float4*)&Y[ybase0 + 64] = make_float4(v[4], v[5], v[6], v[7]);
    }
#endif
}

// ---------------- per-pixel LN stats, both paths in one launch ----------------
__global__ void lnstats2k(const float* __restrict__ X1, const float* __restrict__ X2,
                          float* __restrict__ mu, float* __restrict__ inv)
{
    int p = blockIdx.x * 256 + threadIdx.x;
    int zc = blockIdx.y;
    int pth = zc >= B_;
    int b = pth ? zc - B_ : zc;
    const float* xb = (pth ? X2 : X1) + (size_t)b * C_ * N_ + p;
    float s = 0.f, ss = 0.f;
    #pragma unroll 4
    for (int c = 0; c < C_; ++c) {
        float v = xb[(size_t)c * N_];
        s += v; ss += v * v;
    }
    float m = s * (1.f / C_);
    float var = ss * (1.f / C_) - m * m;
    mu[(size_t)zc * N_ + p] = m;
    inv[(size_t)zc * N_ + p] = rsqrtf(var + 1e-5f);
}

// ---------------- fused: x_out = fuse*ca + origin ; write x_out + LN stats ----------------
__global__ void scaleaddstatsk(const float* __restrict__ fuse, const float* __restrict__ cas,
                               const float* __restrict__ origin, float* __restrict__ Y,
                               float* __restrict__ mu, float* __restrict__ inv)
{
    int p = blockIdx.x * 256 + threadIdx.x;
    int b = blockIdx.y;
    __shared__ float sc[C_];
    for (int i = threadIdx.x; i < C_; i += 256) sc[i] = cas[b * C_ + i];
    __syncthreads();
    const size_t base = (size_t)b * C_ * N_ + p;
    float s = 0.f, ss = 0.f;
    #pragma unroll 4
    for (int c = 0; c < C_; ++c) {
        float v = fuse[base + (size_t)c * N_] * sc[c] + origin[base + (size_t)c * N_];
        Y[base + (size_t)c * N_] = v;
        s += v; ss += v * v;
    }
    float m = s * (1.f / C_);
    float var = ss * (1.f / C_) - m * m;
    mu[b * N_ + p] = m;
    inv[b * N_ + p] = rsqrtf(var + 1e-5f);
}

// ---------------- depthwise 3x3 for kv only (2C channels), both paths ----------------
__global__ void dwkvk(const float* __restrict__ kX1, const float* __restrict__ kX2,
                      const float* __restrict__ kW1, const float* __restrict__ kW2,
                      float* __restrict__ kY1, float* __restrict__ kY2)
{
    int c = blockIdx.y;
    int zc = blockIdx.z;
    int pth = zc >= B_;
    int b = pth ? zc - B_ : zc;
    const float* xb = (pth ? kX2 : kX1) + ((size_t)b * C2_ + c) * N_;
    const float* Wd = (pth ? kW2 : kW1);
    float* yb = (pth ? kY2 : kY1) + ((size_t)b * C2_ + c) * N_;

    int y0 = blockIdx.x * 8;
    int tid = threadIdx.x;
    __shared__ float t[10][128];
    for (int i = tid; i < 320; i += 256) {
        int r = i >> 5, xq = i & 31;
        int yy = y0 - 1 + r;
        float4 v = make_float4(0.f, 0.f, 0.f, 0.f);
        if (yy >= 0 && yy < Hh_) v = *(const float4*)&xb[yy * 128 + xq * 4];
        *(float4*)&t[r][xq * 4] = v;
    }
    float w[9];
    #pragma unroll
    for (int q = 0; q < 9; ++q) w[q] = Wd[c * 9 + q];
    __syncthreads();
    int r = tid >> 5;
    int lx = tid & 31;
    float* yo = yb + (y0 + r) * 128;
    #pragma unroll
    for (int u = 0; u < 4; ++u) {
        int x = u * 32 + lx;
        float s = 0.f;
        #pragma unroll
        for (int dy = 0; dy < 3; ++dy) {
            const float* row = t[r + dy];
            float m  = row[x];
            float l  = (x > 0)   ? row[x - 1] : 0.f;
            float rr = (x < 127) ? row[x + 1] : 0.f;
            s += l * w[dy * 3] + m * w[dy * 3 + 1] + rr * w[dy * 3 + 2];
        }
        yo[x] = s;
    }
}

// ---------------- fused FFN dwconv(680) + gelu-gate -> 340 (smem-tiled) ----------------
__global__ void dwgatek(const float* __restrict__ X, const float* __restrict__ Wd,
                        float* __restrict__ Y)
{
    int c = blockIdx.y, b = blockIdx.z;
    int y0 = blockIdx.x * 8;
    int tid = threadIdx.x;
    const float* x1b = X + ((size_t)b * HID2_ + c) * N_;
    const float* x2b = X + ((size_t)b * HID2_ + c + HID_) * N_;
    __shared__ float t1[10][128];
    __shared__ float t2[10][128];
    for (int i = tid; i < 320; i += 256) {
        int r = i >> 5, xq = i & 31;
        int yy = y0 - 1 + r;
        float4 v1 = make_float4(0.f, 0.f, 0.f, 0.f);
        float4 v2 = v1;
        if (yy >= 0 && yy < Hh_) {
            v1 = *(const float4*)&x1b[yy * 128 + xq * 4];
            v2 = *(const float4*)&x2b[yy * 128 + xq * 4];
        }
        *(float4*)&t1[r][xq * 4] = v1;
        *(float4*)&t2[r][xq * 4] = v2;
    }
    float w1[9], w2[9];
    #pragma unroll
    for (int q = 0; q < 9; ++q) { w1[q] = Wd[c * 9 + q]; w2[q] = Wd[(c + HID_) * 9 + q]; }
    __syncthreads();
    int r = tid >> 5;
    int lx = tid & 31;
    float* yo = Y + ((size_t)b * HID_ + c) * N_ + (y0 + r) * 128;
    #pragma unroll
    for (int u = 0; u < 4; ++u) {
        int x = u * 32 + lx;
        float s1 = 0.f, s2 = 0.f;
        #pragma unroll
        for (int dy = 0; dy < 3; ++dy) {
            const float* r1 = t1[r + dy];
            const float* r2 = t2[r + dy];
            float m1  = r1[x],  m2  = r2[x];
            float l1  = (x > 0)   ? r1[x - 1] : 0.f;
            float l2  = (x > 0)   ? r2[x - 1] : 0.f;
            float rr1 = (x < 127) ? r1[x + 1] : 0.f;
            float rr2 = (x < 127) ? r2[x + 1] : 0.f;
            s1 += l1 * w1[dy * 3] + m1 * w1[dy * 3 + 1] + rr1 * w1[dy * 3 + 2];
            s2 += l2 * w2[dy * 3] + m2 * w2[dy * 3 + 1] + rr2 * w2[dy * 3 + 2];
        }
        float ge = 0.5f * s1 * (1.f + erff(s1 * 0.70710678118654752f));
        yo[x] = ge * s2;
    }
}

// ---------------- FUSED q-dwconv + attention partials (per chunk of 8 image rows) ---------
// q = dwconv3(qpre) computed inline; k read from materialized kvdw output.
__global__ void attnfusek(const float* __restrict__ Q1, const float* __restrict__ Q2,
                          const float* __restrict__ dw1, const float* __restrict__ dw2,
                          const float* __restrict__ KV1, const float* __restrict__ KV2,
                          float* __restrict__ part)
{
    int chunk = blockIdx.x, h = blockIdx.y;
    int zc = blockIdx.z;
    int pth = zc >= B_;
    int b = pth ? zc - B_ : zc;
    const float* qb = (pth ? Q2 : Q1)  + ((size_t)b * C_  + h * CH_) * N_;
    const float* kb = (pth ? KV2 : KV1) + ((size_t)b * C2_ + h * CH_) * N_;
    const float* wd = (pth ? dw2 : dw1) + h * CH_ * 9;

    __shared__ float qrow[3][16][132];   // rolling qpre rows (25344 B)
    __shared__ float qs[16][132];        // conv output row
    __shared__ float ks[16][132];        // k row
    __shared__ float wdw[16][9];
    __shared__ float qqp[256], kkp[256];

    int tid = threadIdx.x;
    if (tid < 144) wdw[tid / 9][tid % 9] = wd[tid];

    const int ch = tid >> 4;       // conv mapping: channel
    const int grp = tid & 15;      // pixel group (8 px)
    const int x0 = grp * 8;
    const int y0 = chunk * 8;

    // preload rows y0-1, y0 into slots (g+1)%3
    #pragma unroll
    for (int pr = 0; pr < 2; ++pr) {
        int g = y0 - 1 + pr;
        int slot = (g + 1) % 3;
        float4 v0 = make_float4(0.f, 0.f, 0.f, 0.f), v1 = v0;
        if (g >= 0 && g < Hh_) {
            v0 = *(const float4*)&qb[(size_t)ch * N_ + g * 128 + x0];
            v1 = *(const float4*)&qb[(size_t)ch * N_ + g * 128 + x0 + 4];
        }
        *(float4*)&qrow[slot][ch][x0] = v0;
        *(float4*)&qrow[slot][ch][x0 + 4] = v1;
    }

    float acc[16];
    #pragma unroll
    for (int j = 0; j < 16; ++j) acc[j] = 0.f;
    float qq = 0.f, kk = 0.f;

    for (int r = 0; r < 8; ++r) {
        int y = y0 + r;
        // load next row (y+1) and k row (y)
        {
            int g = y + 1;
            int slot = (g + 1) % 3;
            float4 v0 = make_float4(0.f, 0.f, 0.f, 0.f), v1 = v0;
            if (g < Hh_) {
                v0 = *(const float4*)&qb[(size_t)ch * N_ + g * 128 + x0];
                v1 = *(const float4*)&qb[(size_t)ch * N_ + g * 128 + x0 + 4];
            }
            *(float4*)&qrow[slot][ch][x0] = v0;
            *(float4*)&qrow[slot][ch][x0 + 4] = v1;
            float4 k0 = *(const float4*)&kb[(size_t)ch * N_ + y * 128 + x0];
            float4 k1 = *(const float4*)&kb[(size_t)ch * N_ + y * 128 + x0 + 4];
            *(float4*)&ks[ch][x0] = k0;
            *(float4*)&ks[ch][x0 + 4] = k1;
            kk += k0.x * k0.x + k0.y * k0.y + k0.z * k0.z + k0.w * k0.w;
            kk += k1.x * k1.x + k1.y * k1.y + k1.z * k1.z + k1.w * k1.w;
        }
        __syncthreads();

        // conv for row y (reads slots (y)%3, (y+1)%3, (y+2)%3 = rows y-1, y, y+1)
        {
            const float* r0 = qrow[(y)     % 3][ch];
            const float* r1 = qrow[(y + 1) % 3][ch];
            const float* r2 = qrow[(y + 2) % 3][ch];
            const float* w = wdw[ch];
            #pragma unroll
            for (int t = 0; t < 8; ++t) {
                int x = x0 + t;
                float l0 = (x > 0)   ? r0[x - 1] : 0.f;
                float l1 = (x > 0)   ? r1[x - 1] : 0.f;
                float l2 = (x > 0)   ? r2[x - 1] : 0.f;
                float rr0 = (x < 127) ? r0[x + 1] : 0.f;
                float rr1 = (x < 127) ? r1[x + 1] : 0.f;
                float rr2 = (x < 127) ? r2[x + 1] : 0.f;
                float o = l0 * w[0] + r0[x] * w[1] + rr0 * w[2]
                        + l1 * w[3] + r1[x] * w[4] + rr1 * w[5]
                        + l2 * w[6] + r2[x] * w[7] + rr2 * w[8];
                qs[ch][x] = o;
                qq += o * o;
            }
        }
        __syncthreads();

        // Gram accumulate: i = q channel, s = pixel group
        {
            int i = tid & 15, s = tid >> 4;
            #pragma unroll
            for (int t = 0; t < 8; ++t) {
                float qv = qs[i][s * 8 + t];
                #pragma unroll
                for (int j = 0; j < 16; ++j) acc[j] += qv * ks[j][s * 8 + t];
            }
        }
        __syncthreads();
    }

    qqp[tid] = qq;   // keyed [ch*16 + grp]
    kkp[tid] = kk;
    float* smg = &qrow[0][0][0];   // reuse qrow for 4096-float Gram reduce
    {
        int i = tid & 15, s = tid >> 4;
        #pragma unroll
        for (int j = 0; j < 16; ++j) smg[s * 256 + i * 16 + j] = acc[j];
    }
    __syncthreads();

    float* pb = part + (((size_t)zc * HEADS_ + h) * NCHUNK_ + chunk) * 288;
    int i2 = tid >> 4, j2 = tid & 15;
    float a = 0.f;
    #pragma unroll
    for (int s2 = 0; s2 < 16; ++s2) a += smg[s2 * 256 + i2 * 16 + j2];
    pb[i2 * 16 + j2] = a;
    if (tid < 16) {
        float t0 = 0.f;
        #pragma unroll
        for (int g = 0; g < 16; ++g) t0 += qqp[tid * 16 + g];
        pb[256 + tid] = t0;
    } else if (tid < 32) {
        int j = tid - 16;
        float t0 = 0.f;
        #pragma unroll
        for (int g = 0; g < 16; ++g) t0 += kkp[j * 16 + g];
        pb[272 + j] = t0;
    }
}

// ---------------- attention finalize, both paths ----------------
__global__ void attnfink(const float* __restrict__ part, const float* __restrict__ temp1,
                         const float* __restrict__ temp2, float* __restrict__ attnOut)
{
    int h = blockIdx.x;
    int zc = blockIdx.y;
    int pth = zc >= B_;
    const float* temp = pth ? temp2 : temp1;
    const float* pb = part + ((size_t)zc * HEADS_ + h) * NCHUNK_ * 288;
    __shared__ float qqs[16], kks[16];
    int tid = threadIdx.x;

    float a = 0.f;
    #pragma unroll
    for (int c = 0; c < NCHUNK_; ++c) a += pb[c * 288 + tid];

    if (tid < 16) {
        float t0 = 0.f;
        #pragma unroll
        for (int c = 0; c < NCHUNK_; ++c) t0 += pb[c * 288 + 256 + tid];
        qqs[tid] = fmaxf(sqrtf(t0), 1e-12f);
    } else if (tid < 32) {
        int j = tid - 16;
        float t0 = 0.f;
        #pragma unroll
        for (int c = 0; c < NCHUNK_; ++c) t0 += pb[c * 288 + 272 + j];
        kks[j] = fmaxf(sqrtf(t0), 1e-12f);
    }
    __syncthreads();

    int i2 = tid >> 4, j2 = tid & 15;
    a = a / (qqs[i2] * kks[j2]) * temp[h];

    unsigned mask = 0xFFFFFFFFu;
    float mx = a;
    for (int w = 8; w > 0; w >>= 1) mx = fmaxf(mx, __shfl_xor_sync(mask, mx, w, 16));
    float e = expf(a - mx);
    float ssum = e;
    for (int w = 8; w > 0; w >>= 1) ssum += __shfl_xor_sync(mask, ssum, w, 16);
    attnOut[((size_t)zc * HEADS_ + h) * 256 + i2 * 16 + j2] = e / ssum;
}

// ---------------- M[zc] = po @ blockdiag(attn[zc]); fp32 + pre-swizzled tiles ----------------
__global__ void poattnk(const float* __restrict__ po1, const float* __restrict__ po2,
                        const float* __restrict__ attn, float* __restrict__ M,
                        uint8_t* __restrict__ MT)
{
    int zc = blockIdx.x;
    const float* po = (zc >= B_) ? po2 : po1;
    uint8_t* mt = MT + (size_t)zc * 2 * TILE_B;
    __shared__ float at[HEADS_ * 256];
    for (int i = threadIdx.x; i < HEADS_ * 256; i += 256)
        at[i] = attn[(size_t)zc * HEADS_ * 256 + i];
    __syncthreads();
    for (int idx2 = threadIdx.x; idx2 < C_ * 64; idx2 += 256) {
        int o = idx2 >> 6, j2 = idx2 & 63;
        int cj = 2 * j2;
        int h = cj >> 4;
        int jj = cj & 15;
        float s0 = 0.f, s1 = 0.f;
        #pragma unroll
        for (int i = 0; i < 16; ++i) {
            float pv = po[o * C_ + h * 16 + i];
            s0 += pv * at[h * 256 + i * 16 + jj];
            s1 += pv * at[h * 256 + i * 16 + jj + 1];
        }
        M[((size_t)zc * C_ + o) * C_ + cj] = s0;
        M[((size_t)zc * C_ + o) * C_ + cj + 1] = s1;
        uint32_t hp, lp;
        split2(s0, s1, hp, lp);
        int chk = cj >> 6;
        uint32_t off = SWZ((uint32_t)(o * 128 + (cj & 63) * 2));
        *(uint32_t*)(mt + chk * TILE_B + off) = hp;
        *(uint32_t*)(mt + chk * TILE_B + 16384 + off) = lp;
    }
}

// ---------------- global average pool per (b,c) ----------------
__global__ void capoolk(const float* __restrict__ X, float* __restrict__ pool)
{
    int c = blockIdx.x, b = blockIdx.y;
    const float* xb = X + ((size_t)b * C_ + c) * N_;
    float s = 0.f;
    for (int n = threadIdx.x * 4; n < N_; n += 1024) {
        float4 v = *(const float4*)&xb[n];
        s += v.x + v.y + v.z + v.w;
    }
    __shared__ float red[256];
    red[threadIdx.x] = s; __syncthreads();
    for (int st = 128; st > 0; st >>= 1) {
        if (threadIdx.x < st) red[threadIdx.x] += red[threadIdx.x + st];
        __syncthreads();
    }
    if (threadIdx.x == 0) pool[b * C_ + c] = red[0] * (1.f / N_);
}

// ---------------- CA: relu FC (128->8) + sigmoid FC (8->128) ----------------
__global__ void cafck(const float* __restrict__ pool,
                      const float* __restrict__ w1, const float* __restrict__ b1,
                      const float* __restrict__ w2, const float* __restrict__ b2,
                      float* __restrict__ cas)
{
    int b = blockIdx.x, t = threadIdx.x;
    __shared__ float pl[C_];
    __shared__ float hid[8];
    pl[t] = pool[b * C_ + t];
    __syncthreads();
    if (t < 8) {
        float s = b1[t];
        #pragma unroll 4
        for (int c = 0; c < C_; ++c) s += w1[t * C_ + c] * pl[c];
        hid[t] = fmaxf(s, 0.f);
    }
    __syncthreads();
    float s = b2[t];
    #pragma unroll
    for (int r = 0; r < 8; ++r) s += w2[t * 8 + r] * hid[r];
    cas[b * C_ + t] = 1.f / (1.f + expf(-s));
}

// ---------------- host ----------------
extern "C" void kernel_launch(void* const* d_in, const int* in_sizes, int n_in,
                              void* d_out, int out_size)
{
    (void)in_sizes; (void)n_in; (void)out_size;
    const float* origin  = (const float*)d_in[0];
    const float* low     = (const float*)d_in[1];
    const float* high    = (const float*)d_in[2];
    const float* norm1_w = (const float*)d_in[3];
    const float* norm1_b = (const float*)d_in[4];
    const float* norm_1_w= (const float*)d_in[5];
    const float* norm_1_b= (const float*)d_in[6];
    const float* norm2_w = (const float*)d_in[7];
    const float* norm2_b = (const float*)d_in[8];
    const float* a1_q    = (const float*)d_in[9];
    const float* a1_qdw  = (const float*)d_in[10];
    const float* a1_kv   = (const float*)d_in[11];
    const float* a1_kvdw = (const float*)d_in[12];
    const float* a1_po   = (const float*)d_in[13];
    const float* a1_temp = (const float*)d_in[14];
    const float* a2_q    = (const float*)d_in[15];
    const float* a2_qdw  = (const float*)d_in[16];
    const float* a2_kv   = (const float*)d_in[17];
    const float* a2_kvdw = (const float*)d_in[18];
    const float* a2_po   = (const float*)d_in[19];
    const float* a2_temp = (const float*)d_in[20];
    const float* conv1_w = (const float*)d_in[21];
    const float* ca1_w   = (const float*)d_in[22];
    const float* ca1_b   = (const float*)d_in[23];
    const float* ca2_w   = (const float*)d_in[24];
    const float* ca2_b   = (const float*)d_in[25];
    const float* ffn_pi  = (const float*)d_in[26];
    const float* ffn_dw  = (const float*)d_in[27];
    const float* ffn_po  = (const float*)d_in[28];
    float* out = (float*)d_out;

    float *bufCb, *bufCc, *buf2Ca, *buf2Cb, *buf2Cc, *bufHa, *bufHb, *xout;
    float *mu, *inv, *attnp, *attnw, *Mw, *pool, *cas;
    uint8_t *wt, *MwT;
    cudaGetSymbolAddress((void**)&bufCb, g_bufCb);
    cudaGetSymbolAddress((void**)&bufCc, g_bufCc);
    cudaGetSymbolAddress((void**)&buf2Ca, g_buf2Ca);
    cudaGetSymbolAddress((void**)&buf2Cb, g_buf2Cb);
    cudaGetSymbolAddress((void**)&buf2Cc, g_buf2Cc);
    cudaGetSymbolAddress((void**)&bufHa, g_bufHa);
    cudaGetSymbolAddress((void**)&bufHb, g_bufHb);
    cudaGetSymbolAddress((void**)&xout, g_xout);
    cudaGetSymbolAddress((void**)&mu, g_mu);
    cudaGetSymbolAddress((void**)&inv, g_inv);
    cudaGetSymbolAddress((void**)&attnp, g_attnp);
    cudaGetSymbolAddress((void**)&attnw, g_attnw);
    cudaGetSymbolAddress((void**)&Mw, g_Mw);
    cudaGetSymbolAddress((void**)&pool, g_pool);
    cudaGetSymbolAddress((void**)&cas, g_cas);
    cudaGetSymbolAddress((void**)&wt, g_wt);
    cudaGetSymbolAddress((void**)&MwT, g_MwT);

    static int smem_set = 0;
    if (!smem_set) {
        cudaFuncSetAttribute(gemmtc, cudaFuncAttributeMaxDynamicSharedMemorySize, SM_TOTAL);
        smem_set = 1;
    }

    // tile offsets (in tiles of TILE_B bytes) — must match wtileall bases
    uint8_t* t_a1q  = wt;                 // 2 tiles
    uint8_t* t_a2q  = wt + 2  * TILE_B;   // 2
    uint8_t* t_a1kv = wt + 4  * TILE_B;   // 4
    uint8_t* t_a2kv = wt + 8  * TILE_B;   // 4
    uint8_t* t_cv1  = wt + 12 * TILE_B;   // 4
    uint8_t* t_fpi  = wt + 16 * TILE_B;   // 12
    uint8_t* t_fpo  = wt + 28 * TILE_B;   // 6

    dim3 tb(256);
    // ===== weight pre-tiling: ONE launch =====
    wtileall<<<dim3(34), tb>>>(a1_q, a2_q, a1_kv, a2_kv, conv1_w, ffn_pi, ffn_po, wt);

    dim3 gLN2(N_ / 256, 2 * B_);
    dim3 gLN(N_ / 256, B_);
    dim3 gQ(N_ / 128, 1, 2 * B_);
    dim3 gKV(N_ / 128, 2, 2 * B_);
    dim3 gMv(N_ / 128, 1, 2 * B_);
    dim3 gG_C(N_ / 128, 1, B_);
    dim3 gG_H(N_ / 128, (HID2_ + 127) / 128, B_);
    dim3 gRow(C_, B_);
    dim3 gAttnP(NCHUNK_, HEADS_, 2 * B_);
    dim3 gAttnF(HEADS_, 2 * B_);
    dim3 gDWkv(Hh_ / 8, C2_, 2 * B_);
    dim3 gDW_H(Hh_ / 8, HID_, B_);

    // ===== both attention paths, merged launches =====
    gemmtc<<<gQ, tb, SM_TOTAL>>>(t_a1q, high, bufCb, nullptr,
                                 t_a2q, low, bufCc, nullptr,
                                 a1_q, a2_q,
                                 nullptr, nullptr, nullptr, nullptr, nullptr, nullptr,
                                 C_, C_, C_, C_, 0, 0, 0, 0, 0);
    lnstats2k<<<gLN2, tb>>>(low, high, mu, inv);
    gemmtc<<<gKV, tb, SM_TOTAL>>>(t_a1kv, low, buf2Ca, nullptr,
                                  t_a2kv, high, buf2Cb, nullptr,
                                  a1_kv, a2_kv,
                                  mu, inv, norm1_w, norm1_b, norm_1_w, norm_1_b,
                                  C2_, C_, C_, C2_, 0, 0, 4, 0, 0);
    dwkvk<<<gDWkv, tb>>>(buf2Ca, buf2Cb, a1_kvdw, a2_kvdw, buf2Cc, bufHa);
    attnfusek<<<gAttnP, tb>>>(bufCb, bufCc, a1_qdw, a2_qdw, buf2Cc, bufHa, attnp);
    attnfink<<<gAttnF, tb>>>(attnp, a1_temp, a2_temp, attnw);
    poattnk<<<dim3(2 * B_), tb>>>(a1_po, a2_po, attnw, Mw, MwT);
    gemmtc<<<gMv, tb, SM_TOTAL>>>(MwT, buf2Cc + (size_t)C_ * N_, buf2Ca, low,
                                  MwT + (size_t)B_ * 2 * TILE_B, bufHa + (size_t)C_ * N_, buf2Ca, high,
                                  Mw, Mw + (size_t)B_ * C_ * C_,
                                  nullptr, nullptr, nullptr, nullptr, nullptr, nullptr,
                                  C_, C_, C2_, C2_, 0, C_, 1, 2, C_ * C_);

    // ===== fuse: conv1(concat) -> CA -> + origin, fused with norm2 stats =====
    gemmtc<<<gG_C, tb, SM_TOTAL>>>(t_cv1, buf2Ca, bufCb, nullptr,
                                   t_cv1, buf2Ca, bufCb, nullptr,
                                   conv1_w, conv1_w,
                                   nullptr, nullptr, nullptr, nullptr, nullptr, nullptr,
                                   C_, C2_, C2_, C_, 0, 0, 0, 0, 0);
    capoolk<<<gRow, tb>>>(bufCb, pool);
    cafck<<<dim3(B_), dim3(128)>>>(pool, ca1_w, ca1_b, ca2_w, ca2_b, cas);
    scaleaddstatsk<<<gLN, tb>>>(bufCb, cas, origin, xout, mu, inv);

    // ===== FFN with residual =====
    gemmtc<<<gG_H, tb, SM_TOTAL>>>(t_fpi, xout, bufHa, nullptr,
                                   t_fpi, xout, bufHa, nullptr,
                                   ffn_pi, ffn_pi,
                                   mu, inv, norm2_w, norm2_b, norm2_w, norm2_b,
                                   HID2_, C_, C_, HID2_, 0, 0, 4, 0, 0);
    dwgatek<<<gDW_H, tb>>>(bufHa, ffn_dw, bufHb);
    gemmtc<<<gG_C, tb, SM_TOTAL>>>(t_fpo, bufHb, out, xout,
                                   t_fpo, bufHb, out, xout,
                                   ffn_po, ffn_po,
                                   nullptr, nullptr, nullptr, nullptr, nullptr, nullptr,
                                   C_, HID_, HID_, C_, 0, 0, 3, 0, 0);
}

// round 14
// speedup vs baseline: 1.5124x; 1.1794x over previous
#include <cuda_runtime.h>
#include <cuda_bf16.h>
#include <math.h>
#include <stdint.h>

#define B_    8
#define C_    128
#define Hh_   128
#define Ww_   128
#define N_    16384      // H*W
#define HEADS_ 8
#define CH_   16         // C/HEADS
#define HID_  340
#define HID2_ 680
#define C2_   256
#define NCHUNK_ 16
#define CHUNKN_ (N_ / NCHUNK_)   // 1024
#define TILE_B 32768             // one pre-swizzled W tile: 16KB hi + 16KB lo

// ---------------- static scratch (no allocations allowed) ----------------
__device__ float g_bufCb[(size_t)B_ * C_ * N_];   // qpre path1 / conv1 out
__device__ float g_bufCc[(size_t)B_ * C_ * N_];   // qpre path2
__device__ float g_buf2Ca[(size_t)B_ * C2_ * N_]; // kvpre path1 / concat out
__device__ float g_buf2Cb[(size_t)B_ * C2_ * N_]; // kvpre path2
__device__ float g_buf2Cc[(size_t)B_ * C2_ * N_]; // kvdw path1
__device__ float g_bufHa[(size_t)B_ * HID2_ * N_];// kvdw path2 (front 2C) / ffn hidden
__device__ float g_bufHb[(size_t)B_ * HID_ * N_]; // gated
__device__ float g_xout[(size_t)B_ * C_ * N_];
__device__ float g_mu[2 * B_ * N_];
__device__ float g_inv[2 * B_ * N_];
__device__ float g_attnp[2 * B_ * HEADS_ * NCHUNK_ * 288];
__device__ float g_attnw[2 * B_ * HEADS_ * CH_ * CH_];
__device__ float g_Mw[2 * B_ * C_ * C_];
__device__ float g_pool[B_ * C_];
__device__ float g_cas[B_ * C_];
// pre-swizzled weight tiles: 34 static + 32 for Mw
__device__ __align__(16) uint8_t g_wt[34 * TILE_B];
__device__ __align__(16) uint8_t g_MwT[32 * TILE_B];

// packed f32x2 helpers (fallback path)
#define FMA2(d, a, b) asm("fma.rn.f32x2 %0, %1, %2, %0;" : "+l"(d) : "l"(a), "l"(b))
#define UNPK2(lo, hi, s) asm("mov.b64 {%0, %1}, %2;" : "=f"(lo), "=f"(hi) : "l"(s))

// ---------------- PTX helpers ----------------
__device__ __forceinline__ uint32_t smem_u32(const void* p) {
    uint32_t a;
    asm("{ .reg .u64 t; cvta.to.shared.u64 t, %1; cvt.u32.u64 %0, t; }" : "=r"(a) : "l"(p));
    return a;
}
#define SWZ(o) ((o) ^ (((o) >> 3) & 0x70))

#if defined(__CUDA_ARCH_FEAT_SM103_ALL) || !defined(__CUDA_ARCH__)
#define HAS_TC 1
#else
#define HAS_TC 0
#endif

#define MBARRIER_INIT(addr, cnt) \
    asm volatile("mbarrier.init.shared.b64 [%0], %1;" :: "r"((uint32_t)(addr)), "r"((uint32_t)(cnt)) : "memory")
#define MBARRIER_INVAL(addr) \
    asm volatile("mbarrier.inval.shared.b64 [%0];" :: "r"((uint32_t)(addr)) : "memory")
#define MBARRIER_WAIT_PARITY(mbar_smem_addr, phase_parity) do { \
    uint32_t _mbar = (uint32_t)(mbar_smem_addr); \
    uint32_t _parity = (uint32_t)(phase_parity); \
    uint32_t _done; \
    asm volatile("{\n\t.reg .pred p;\n\t" \
        "mbarrier.try_wait.parity.acquire.cta.shared::cta.b64 p, [%1], %2;\n\t" \
        "selp.b32 %0, 1, 0, p;\n\t}" : "=r"(_done) : "r"(_mbar), "r"(_parity) : "memory"); \
    if (!_done) { \
        asm volatile("{\n\t.reg .pred P1;\n\t" \
            "WAIT_LOOP_%=:\n\t" \
            "mbarrier.try_wait.parity.acquire.cta.shared::cta.b64 P1, [%0], %1, 0x989680;\n\t" \
            "@P1 bra.uni WAIT_DONE_%=;\n\t" \
            "bra.uni WAIT_LOOP_%=;\n\t" \
            "WAIT_DONE_%=:\n\t}" :: "r"(_mbar), "r"(_parity) : "memory"); \
    } \
} while (0)

#if HAS_TC
#define TCGEN05_ALLOC(smem_result_addr, nCols) \
    asm volatile("tcgen05.alloc.cta_group::1.sync.aligned.shared::cta.b32 [%0], %1;" \
        :: "r"((uint32_t)(smem_result_addr)), "r"((uint32_t)(nCols)) : "memory")
#define TCGEN05_DEALLOC(tmem_addr, nCols) \
    asm volatile("tcgen05.dealloc.cta_group::1.sync.aligned.b32 %0, %1;" :: "r"(tmem_addr), "r"((uint32_t)(nCols)))
#define TCGEN05_RELINQUISH() \
    asm volatile("tcgen05.relinquish_alloc_permit.cta_group::1.sync.aligned;")
#define TCGEN05_COMMIT(mbar_smem_addr) \
    asm volatile("tcgen05.commit.cta_group::1.mbarrier::arrive::one.shared::cluster.b64 [%0];" \
        :: "r"((uint32_t)(mbar_smem_addr)) : "memory")
#define TCGEN05_FENCE_AFTER() asm volatile("tcgen05.fence::after_thread_sync;" ::: "memory")
#define TCGEN05_FENCE_BEFORE() asm volatile("tcgen05.fence::before_thread_sync;" ::: "memory")
#define TCGEN05_WAIT_LD() asm volatile("tcgen05.wait::ld.sync.aligned;" ::: "memory")
#define FENCE_ASYNC_SHARED() asm volatile("fence.proxy.async.shared::cta;" ::: "memory")

#define TCGEN05_LD_32X32B_X32(r, tmem_addr) \
    asm volatile( \
        "tcgen05.ld.sync.aligned.32x32b.x32.b32 " \
        "{%0, %1, %2, %3, %4, %5, %6, %7, " \
        " %8, %9, %10, %11, %12, %13, %14, %15, " \
        " %16, %17, %18, %19, %20, %21, %22, %23, " \
        " %24, %25, %26, %27, %28, %29, %30, %31}, [%32];" \
        : "=r"((r)[0]),  "=r"((r)[1]),  "=r"((r)[2]),  "=r"((r)[3]), \
          "=r"((r)[4]),  "=r"((r)[5]),  "=r"((r)[6]),  "=r"((r)[7]), \
          "=r"((r)[8]),  "=r"((r)[9]),  "=r"((r)[10]), "=r"((r)[11]), \
          "=r"((r)[12]), "=r"((r)[13]), "=r"((r)[14]), "=r"((r)[15]), \
          "=r"((r)[16]), "=r"((r)[17]), "=r"((r)[18]), "=r"((r)[19]), \
          "=r"((r)[20]), "=r"((r)[21]), "=r"((r)[22]), "=r"((r)[23]), \
          "=r"((r)[24]), "=r"((r)[25]), "=r"((r)[26]), "=r"((r)[27]), \
          "=r"((r)[28]), "=r"((r)[29]), "=r"((r)[30]), "=r"((r)[31]) \
        : "r"(tmem_addr))

// SW128 SMEM descriptor (LBO=1, SBO=64, version=1, layout=SW128)
__device__ __forceinline__ uint64_t make_desc(uint32_t addr) {
    const uint64_t base = (uint64_t(2) << 61) | (uint64_t(1) << 46)
                        | (uint64_t(64) << 32) | (uint64_t(1) << 16);
    return base | ((uint64_t)(addr >> 4) & 0x3FFF);
}

// bf16 SS MMA, cg1: D[M=128, N=128] += A[M,K=16] * B[N,K=16]^T
#define MMA_IDESC 0x8200490u
__device__ __forceinline__ void mma_bf16_ss(uint32_t d, uint64_t ad, uint64_t bd, uint32_t en) {
    asm volatile(
        "{\n\t.reg .pred p;\n\tsetp.ne.u32 p, %5, 0;\n\t"
        "tcgen05.mma.cta_group::1.kind::f16 [%0], %1, %2, %3, {%4, %4, %4, %4}, p;\n\t}"
        :: "r"(d), "l"(ad), "l"(bd), "r"(MMA_IDESC), "r"(0u), "r"(en) : "memory");
}
#endif  // HAS_TC

// gemmtc smem layout (bytes) — DOUBLE-buffered (R9-proven)
#define SM_TMEM   0
#define SM_MBAR   16           // 2 mbarriers @16, @24
#define SM_XS     64           // fp32 staging: 64 x 132 floats = 33792 B
#define SM_TILES  34816        // 1024-aligned; per buffer: AHI,ALO,BHI,BLO @16KB
#define SM_BUFSZ  65536
#define SM_TOTAL  (SM_TILES + 2 * SM_BUFSZ)   // 165888 B

// gemmtc2 smem layout: B resident (2 chunks), A double-buffered (2 chunks each)
#define SM2_B     1024         // 2 x 32KB = [1024, 66560)
#define SM2_A     66560        // 2 x 65536 = [66560, 197632); XS aliases here
#define SM2_ABUF  65536
#define SM2_TOTAL 197632

// truncation-based hi/lo bf16 split, packed pairs via PRMT
__device__ __forceinline__ uint32_t prmt_hi(uint32_t u0, uint32_t u1) {
    uint32_t r;
    asm("prmt.b32 %0, %1, %2, 0x7632;" : "=r"(r) : "r"(u0), "r"(u1));
    return r;
}
__device__ __forceinline__ void split2(float x0, float x1, uint32_t& hp, uint32_t& lp) {
    uint32_t u0 = __float_as_uint(x0), u1 = __float_as_uint(x1);
    hp = prmt_hi(u0, u1);
    float l0 = x0 - __uint_as_float(u0 & 0xFFFF0000u);
    float l1 = x1 - __uint_as_float(u1 & 0xFFFF0000u);
    lp = prmt_hi(__float_as_uint(l0), __float_as_uint(l1));
}

// ---------------- merged weight pre-tiler: all 7 weights in ONE launch ----------------
__global__ void wtileall(const float* __restrict__ a1q, const float* __restrict__ a2q,
                         const float* __restrict__ a1kv, const float* __restrict__ a2kv,
                         const float* __restrict__ cv1, const float* __restrict__ fpi,
                         const float* __restrict__ fpo, uint8_t* __restrict__ tiles)
{
    int t = blockIdx.x;   // 0..33
    const float* W; int Cout, Cin, base;
    if (t < 2)       { W = a1q;  Cout = C_;    Cin = C_;   base = 0;  }
    else if (t < 4)  { W = a2q;  Cout = C_;    Cin = C_;   base = 2;  }
    else if (t < 8)  { W = a1kv; Cout = C2_;   Cin = C_;   base = 4;  }
    else if (t < 12) { W = a2kv; Cout = C2_;   Cin = C_;   base = 8;  }
    else if (t < 16) { W = cv1;  Cout = C_;    Cin = C2_;  base = 12; }
    else if (t < 28) { W = fpi;  Cout = HID2_; Cin = C_;   base = 16; }
    else             { W = fpo;  Cout = C_;    Cin = HID_; base = 28; }
    int lt = t - base;
    int KchT = (Cin + 63) >> 6;
    int kt = lt % KchT, ot = lt / KchT;
    uint8_t* tb = tiles + (size_t)t * TILE_B;

    const int tid = threadIdx.x;
    int r = tid >> 1;
    int kh = (tid & 1) << 5;
    int o = ot * 128 + r;
    #pragma unroll
    for (int i = 0; i < 8; ++i) {
        int kk = kt * 64 + kh + i * 4;
        float4 v;
        v.x = (o < Cout && kk + 0 < Cin) ? W[(size_t)o * Cin + kk + 0] : 0.f;
        v.y = (o < Cout && kk + 1 < Cin) ? W[(size_t)o * Cin + kk + 1] : 0.f;
        v.z = (o < Cout && kk + 2 < Cin) ? W[(size_t)o * Cin + kk + 2] : 0.f;
        v.w = (o < Cout && kk + 3 < Cin) ? W[(size_t)o * Cin + kk + 3] : 0.f;
        uint32_t hp0, lp0, hp1, lp1;
        split2(v.x, v.y, hp0, lp0);
        split2(v.z, v.w, hp1, lp1);
        uint32_t off = SWZ((uint32_t)(r * 128 + (kh + i * 4) * 2));
        *(uint2*)(tb + off) = make_uint2(hp0, hp1);
        *(uint2*)(tb + 16384 + off) = make_uint2(lp0, lp1);
    }
}

// ---------------- GEMM: Y[b, Yoff+o, p] = sum_c W[o,c] LN?(X[b,c,p]) ----------------
// flags: 1=residual add, 2=nan_to_num, 4=apply LN to X on load
__global__ void __launch_bounds__(256, 1)
gemmtc(const uint8_t* __restrict__ Wt1, const float* __restrict__ X1,
       float* __restrict__ Y1, const float* __restrict__ R1,
       const uint8_t* __restrict__ Wt2, const float* __restrict__ X2,
       float* __restrict__ Y2, const float* __restrict__ R2,
       const float* __restrict__ W1, const float* __restrict__ W2,
       const float* __restrict__ lnMu, const float* __restrict__ lnInv,
       const float* __restrict__ lnW1, const float* __restrict__ lnB1,
       const float* __restrict__ lnW2, const float* __restrict__ lnB2,
       int Cout, int Cin, int XCtot, int YCtot, int Yoff1, int Yoff2,
       int flags, int WtTilesPerB, int WstrideB)
{
    extern __shared__ __align__(1024) char smem[];

    const int bz = blockIdx.z;
    const int pth = bz >= B_;
    const int b = pth ? bz - B_ : bz;
    const int o0 = blockIdx.y * 128;
    const int p0 = blockIdx.x * 128;
    const float* Xb = (pth ? X2 : X1) + (size_t)b * XCtot * N_;
    float* Y = pth ? Y2 : Y1;
    const float* R = pth ? R2 : R1;
    const float* lnW = pth ? lnW2 : lnW1;
    const float* lnB = pth ? lnB2 : lnB1;
    const int Yoff = pth ? Yoff2 : Yoff1;
    const int lnOn = flags & 4;
    const int tid = threadIdx.x;
    const int nch = (Cin + 63) >> 6;   // == KchT

#if HAS_TC && defined(__CUDA_ARCH__)
    // ================= tcgen05 path (sm_103a cubin) =================
    const uint8_t* Wtb = (pth ? Wt2 : Wt1) + (size_t)b * WtTilesPerB * TILE_B;
    const uint32_t sb = smem_u32(smem);
    const int wid = tid >> 5;

    if (tid == 0) {
        MBARRIER_INIT(sb + SM_MBAR, 1);
        MBARRIER_INIT(sb + SM_MBAR + 8, 1);
    }
    if (wid == 0) TCGEN05_ALLOC(sb + SM_TMEM, 128);
    __syncthreads();
    uint32_t tmem;
    asm volatile("ld.shared.b32 %0, [%1];" : "=r"(tmem) : "r"(sb + SM_TMEM));

    int ph0 = 0, ph1 = 0;
    uint32_t en = 0;
    float* xs = (float*)(smem + SM_XS);

    for (int ch = 0; ch < nch; ++ch) {
        const int bf = ch & 1;
        const int k0 = ch << 6;
        if (ch >= 2) {
            if (bf == 0) { MBARRIER_WAIT_PARITY(sb + SM_MBAR, ph0); ph0 ^= 1; }
            else         { MBARRIER_WAIT_PARITY(sb + SM_MBAR + 8, ph1); ph1 ^= 1; }
        }
        char* abase = smem + SM_TILES + bf * SM_BUFSZ;   // AHI (+16K ALO)
        char* bbase = abase + 32768;                     // BHI
        char* blbase = abase + 49152;                    // BLO

        // ---- stage A: straight copy of pre-swizzled hi/lo tile (32KB) ----
        {
            const uint4* src = (const uint4*)(Wtb + ((size_t)(blockIdx.y * nch + ch)) * TILE_B);
            uint4* dst = (uint4*)abase;
            #pragma unroll
            for (int i = 0; i < 8; ++i)
                dst[tid + 256 * i] = src[tid + 256 * i];
        }

        // ---- stage B phase 1: X [64 k][128 p] fp32 -> Xs (LN applied) ----
        {
            int kr = tid >> 2;
            int pc = (tid & 3) << 5;
            int kk = k0 + kr;
            float* xrow = xs + kr * 132 + pc;
            if (kk < Cin) {
                const float* src = Xb + (size_t)kk * N_ + p0 + pc;
                if (lnOn) {
                    float wv = lnW[kk], bv = lnB[kk];
                    #pragma unroll
                    for (int i = 0; i < 8; ++i) {
                        float4 v = *(const float4*)&src[i * 4];
                        float4 m  = *(const float4*)&lnMu[(size_t)bz * N_ + p0 + pc + i * 4];
                        float4 iv = *(const float4*)&lnInv[(size_t)bz * N_ + p0 + pc + i * 4];
                        v.x = (v.x - m.x) * iv.x * wv + bv;
                        v.y = (v.y - m.y) * iv.y * wv + bv;
                        v.z = (v.z - m.z) * iv.z * wv + bv;
                        v.w = (v.w - m.w) * iv.w * wv + bv;
                        *(float4*)&xrow[i * 4] = v;
                    }
                } else {
                    #pragma unroll
                    for (int i = 0; i < 8; ++i)
                        *(float4*)&xrow[i * 4] = *(const float4*)&src[i * 4];
                }
            } else {
                #pragma unroll
                for (int i = 0; i < 8; ++i)
                    *(float4*)&xrow[i * 4] = make_float4(0.f, 0.f, 0.f, 0.f);
            }
        }
        __syncthreads();

        // ---- stage B phase 2: transpose + convert -> B[n][k] hi/lo bf16 SW128 ----
        {
            int n = tid & 127;
            int half = tid >> 7;
            #pragma unroll
            for (int g = 0; g < 4; ++g) {
                uint32_t hw[4], lw[4];
                #pragma unroll
                for (int q = 0; q < 4; ++q) {
                    int k1 = half * 32 + g * 8 + q * 2;
                    split2(xs[(k1 + 0) * 132 + n], xs[(k1 + 1) * 132 + n], hw[q], lw[q]);
                }
                uint32_t off = SWZ((uint32_t)(n * 128 + half * 64 + g * 16));
                *(uint4*)(bbase + off) = make_uint4(hw[0], hw[1], hw[2], hw[3]);
                *(uint4*)(blbase + off) = make_uint4(lw[0], lw[1], lw[2], lw[3]);
            }
        }
        FENCE_ASYNC_SHARED();
        __syncthreads();

        // ---- issue MMAs for this chunk ----
        if (tid == 0) {
            uint64_t ah = make_desc(sb + SM_TILES + bf * SM_BUFSZ);
            uint64_t al = ah + (16384 >> 4);
            uint64_t bh = ah + (32768 >> 4);
            uint64_t bl = ah + (49152 >> 4);
            #pragma unroll
            for (int s = 0; s < 4; ++s) {
                uint64_t ofs = s * 2;
                mma_bf16_ss(tmem, ah + ofs, bh + ofs, en); en = 1;
                mma_bf16_ss(tmem, ah + ofs, bl + ofs, 1);
                mma_bf16_ss(tmem, al + ofs, bh + ofs, 1);
            }
            TCGEN05_COMMIT(sb + SM_MBAR + bf * 8);
        }
    }

    // ---- drain ----
    { MBARRIER_WAIT_PARITY(sb + SM_MBAR, ph0); }
    if (nch >= 2) { MBARRIER_WAIT_PARITY(sb + SM_MBAR + 8, ph1); }
    TCGEN05_FENCE_AFTER();

    // ---- epilogue: warps 0-3 read TMEM D and store ----
    const int doResid = flags & 1, doFinal = flags & 2;
    if (tid < 128) {
        int w = tid >> 5, l = tid & 31;
        int o = o0 + w * 32 + l;
        #pragma unroll
        for (int g = 0; g < 4; ++g) {
            uint32_t dr[32];
            TCGEN05_LD_32X32B_X32(dr, tmem + g * 32);
            TCGEN05_WAIT_LD();
            if (o < Cout) {
                size_t ybase = ((size_t)b * YCtot + Yoff + o) * N_ + p0 + g * 32;
                size_t rbase = ((size_t)b * Cout + o) * N_ + p0 + g * 32;
                #pragma unroll
                for (int q = 0; q < 8; ++q) {
                    float v0 = __uint_as_float(dr[q * 4 + 0]);
                    float v1 = __uint_as_float(dr[q * 4 + 1]);
                    float v2 = __uint_as_float(dr[q * 4 + 2]);
                    float v3 = __uint_as_float(dr[q * 4 + 3]);
                    if (doResid) {
                        float4 r4 = *(const float4*)&R[rbase + q * 4];
                        v0 += r4.x; v1 += r4.y; v2 += r4.z; v3 += r4.w;
                    }
                    if (doFinal) {
                        v0 = isfinite(v0) ? v0 : 1e-5f;
                        v1 = isfinite(v1) ? v1 : 1e-5f;
                        v2 = isfinite(v2) ? v2 : 1e-5f;
                        v3 = isfinite(v3) ? v3 : 1e-5f;
                    }
                    *(float4*)&Y[ybase + q * 4] = make_float4(v0, v1, v2, v3);
                }
            }
        }
        TCGEN05_FENCE_BEFORE();
    }

    __syncthreads();
    if (tid == 0) { MBARRIER_INVAL(sb + SM_MBAR); MBARRIER_INVAL(sb + SM_MBAR + 8); }
    __syncthreads();
    if (wid == 0) {
        TCGEN05_RELINQUISH();
        TCGEN05_DEALLOC(tmem, 128);
    }
#else
    // ================= FFMA2 fallback (compute_103 PTX pass) =================
    const float* Wb = (pth ? W2 : W1) + (size_t)b * WstrideB;
    float2 (*Ws2)[16][128] = (float2(*)[16][128])(smem);            // 32KB
    float  (*Xs)[16][128]  = (float(*)[16][128])(smem + 32768);     // 16KB

    const int tx = tid & 15, ty = tid >> 4;
    unsigned long long acc2[8][4];
    #pragma unroll
    for (int i = 0; i < 8; ++i)
        #pragma unroll
        for (int j = 0; j < 4; ++j) acc2[i][j] = 0ULL;

    const int ktiles = (Cin + 15) >> 4;
    for (int kt = 0; kt < ktiles; ++kt) {
        int buf = kt & 1;
        int k0 = kt * 16;
        #pragma unroll
        for (int u = 0; u < 2; ++u) {
            int e4 = tid + 256 * u;
            int row = e4 & 127, kq = e4 >> 7;
            int o = o0 + row;
            #pragma unroll
            for (int t = 0; t < 4; ++t) {
                int kk = k0 + kq * 4 + t;
                float w = (o < Cout && kk < Cin) ? Wb[(size_t)o * Cin + kk] : 0.f;
                Ws2[buf][kq * 4 + t][row] = make_float2(w, w);
            }
        }
        #pragma unroll
        for (int u = 0; u < 2; ++u) {
            int e = tid + 256 * u;
            int row = e >> 5, cq = e & 31;
            int kk = k0 + row;
            float4 v = (kk < Cin) ? *(const float4*)&Xb[(size_t)kk * N_ + p0 + cq * 4]
                                  : make_float4(0.f, 0.f, 0.f, 0.f);
            if (lnOn && kk < Cin) {
                int pix = p0 + cq * 4;
                float4 m  = *(const float4*)&lnMu[(size_t)bz * N_ + pix];
                float4 iv = *(const float4*)&lnInv[(size_t)bz * N_ + pix];
                float wv = lnW[kk], bv = lnB[kk];
                v.x = (v.x - m.x) * iv.x * wv + bv;
                v.y = (v.y - m.y) * iv.y * wv + bv;
                v.z = (v.z - m.z) * iv.z * wv + bv;
                v.w = (v.w - m.w) * iv.w * wv + bv;
            }
            *(float4*)&Xs[buf][row][cq * 4] = v;
        }
        __syncthreads();
        #pragma unroll
        for (int k = 0; k < 16; ++k) {
            ulonglong2 q0 = *(const ulonglong2*)&Xs[buf][k][tx * 4];
            ulonglong2 q1 = *(const ulonglong2*)&Xs[buf][k][64 + tx * 4];
            unsigned long long bb0 = q0.x, bb1 = q0.y, bb2 = q1.x, bb3 = q1.y;
            const ulonglong2* wrow = (const ulonglong2*)&Ws2[buf][k][ty * 8];
            ulonglong2 w01 = wrow[0], w23 = wrow[1], w45 = wrow[2], w67 = wrow[3];
            unsigned long long av[8] = {w01.x, w01.y, w23.x, w23.y,
                                        w45.x, w45.y, w67.x, w67.y};
            #pragma unroll
            for (int i = 0; i < 8; ++i) {
                FMA2(acc2[i][0], av[i], bb0);
                FMA2(acc2[i][1], av[i], bb1);
                FMA2(acc2[i][2], av[i], bb2);
                FMA2(acc2[i][3], av[i], bb3);
            }
        }
        __syncthreads();
    }

    const int doResid = flags & 1, doFinal = flags & 2;
    #pragma unroll
    for (int i = 0; i < 8; ++i) {
        int o = o0 + ty * 8 + i;
        if (o >= Cout) continue;
        size_t ybase0 = ((size_t)b * YCtot + Yoff + o) * N_ + p0 + tx * 4;
        float v[8];
        #pragma unroll
        for (int j = 0; j < 4; ++j) UNPK2(v[2 * j], v[2 * j + 1], acc2[i][j]);
        if (doResid) {
            size_t rbase = ((size_t)b * Cout + o) * N_ + p0 + tx * 4;
            float4 r0 = *(const float4*)&R[rbase];
            float4 r1 = *(const float4*)&R[rbase + 64];
            v[0] += r0.x; v[1] += r0.y; v[2] += r0.z; v[3] += r0.w;
            v[4] += r1.x; v[5] += r1.y; v[6] += r1.z; v[7] += r1.w;
        }
        if (doFinal) {
            #pragma unroll
            for (int j = 0; j < 8; ++j) v[j] = isfinite(v[j]) ? v[j] : 1e-5f;
        }
        *(float4*)&Y[ybase0]      = make_float4(v[0], v[1], v[2], v[3]);
        *(float4*)&Y[ybase0 + 64] = make_float4(v[4], v[5], v[6], v[7]);
    }
#endif
}

// ---------------- multi-o-tile GEMM (Cin=128, nch=2): B staged ONCE, A looped --------
// flags: 4=apply LN to X on load (no residual/final variants needed here)
__global__ void __launch_bounds__(256, 1)
gemmtc2(const uint8_t* __restrict__ Wt1, const float* __restrict__ X1, float* __restrict__ Y1,
        const uint8_t* __restrict__ Wt2, const float* __restrict__ X2, float* __restrict__ Y2,
        const float* __restrict__ W1, const float* __restrict__ W2,
        const float* __restrict__ lnMu, const float* __restrict__ lnInv,
        const float* __restrict__ lnW1, const float* __restrict__ lnB1,
        const float* __restrict__ lnW2, const float* __restrict__ lnB2,
        int Cout, int XCtot, int YCtot, int flags, int nOt)
{
    extern __shared__ __align__(1024) char smem[];
    const int bz = blockIdx.z;
    const int pth = bz >= B_;
    const int b = pth ? bz - B_ : bz;
    const int p0 = blockIdx.x * 128;
    const float* Xb = (pth ? X2 : X1) + (size_t)b * XCtot * N_;
    float* Y = pth ? Y2 : Y1;
    const float* lnW = pth ? lnW2 : lnW1;
    const float* lnB = pth ? lnB2 : lnB1;
    const int lnOn = flags & 4;
    const int tid = threadIdx.x;

#if HAS_TC && defined(__CUDA_ARCH__)
    const uint8_t* Wtb = pth ? Wt2 : Wt1;
    const uint32_t sb = smem_u32(smem);
    const int wid = tid >> 5;

    if (tid == 0) {
        MBARRIER_INIT(sb + SM_MBAR, 1);
        MBARRIER_INIT(sb + SM_MBAR + 8, 1);
    }
    if (wid == 0) TCGEN05_ALLOC(sb + SM_TMEM, 512);
    __syncthreads();
    uint32_t tmem;
    asm volatile("ld.shared.b32 %0, [%1];" : "=r"(tmem) : "r"(sb + SM_TMEM));

    float* xs = (float*)(smem + SM2_A);   // aliases A region (used before A copies)

    // ---- stage B for BOTH chunks once ----
    for (int ch = 0; ch < 2; ++ch) {
        const int k0 = ch << 6;
        char* bbase = smem + SM2_B + ch * 32768;
        char* blbase = bbase + 16384;
        {
            int kr = tid >> 2;
            int pc = (tid & 3) << 5;
            int kk = k0 + kr;
            float* xrow = xs + kr * 132 + pc;
            const float* src = Xb + (size_t)kk * N_ + p0 + pc;
            if (lnOn) {
                float wv = lnW[kk], bv = lnB[kk];
                #pragma unroll
                for (int i = 0; i < 8; ++i) {
                    float4 v = *(const float4*)&src[i * 4];
                    float4 m  = *(const float4*)&lnMu[(size_t)bz * N_ + p0 + pc + i * 4];
                    float4 iv = *(const float4*)&lnInv[(size_t)bz * N_ + p0 + pc + i * 4];
                    v.x = (v.x - m.x) * iv.x * wv + bv;
                    v.y = (v.y - m.y) * iv.y * wv + bv;
                    v.z = (v.z - m.z) * iv.z * wv + bv;
                    v.w = (v.w - m.w) * iv.w * wv + bv;
                    *(float4*)&xrow[i * 4] = v;
                }
            } else {
                #pragma unroll
                for (int i = 0; i < 8; ++i)
                    *(float4*)&xrow[i * 4] = *(const float4*)&src[i * 4];
            }
        }
        __syncthreads();
        {
            int n = tid & 127;
            int half = tid >> 7;
            #pragma unroll
            for (int g = 0; g < 4; ++g) {
                uint32_t hw[4], lw[4];
                #pragma unroll
                for (int q = 0; q < 4; ++q) {
                    int k1 = half * 32 + g * 8 + q * 2;
                    split2(xs[(k1 + 0) * 132 + n], xs[(k1 + 1) * 132 + n], hw[q], lw[q]);
                }
                uint32_t off = SWZ((uint32_t)(n * 128 + half * 64 + g * 16));
                *(uint4*)(bbase + off) = make_uint4(hw[0], hw[1], hw[2], hw[3]);
                *(uint4*)(blbase + off) = make_uint4(lw[0], lw[1], lw[2], lw[3]);
            }
        }
        __syncthreads();   // xs reused next ch
    }

    // ---- loop output tiles: double-buffered A copy + MMAs ----
    int phA0 = 0, phA1 = 0;
    for (int ot = 0; ot < nOt; ++ot) {
        const int buf = ot & 1;
        if (ot >= 2) {
            if (buf == 0) { MBARRIER_WAIT_PARITY(sb + SM_MBAR, phA0); phA0 ^= 1; }
            else          { MBARRIER_WAIT_PARITY(sb + SM_MBAR + 8, phA1); phA1 ^= 1; }
        }
        // copy A tiles for both chunks (64KB)
        {
            int otg = blockIdx.y * nOt + ot;
            const uint4* src = (const uint4*)(Wtb + (size_t)(otg * 2) * TILE_B);
            uint4* dst = (uint4*)(smem + SM2_A + buf * SM2_ABUF);
            #pragma unroll
            for (int i = 0; i < 16; ++i)
                dst[tid + 256 * i] = src[tid + 256 * i];
        }
        FENCE_ASYNC_SHARED();
        __syncthreads();
        if (tid == 0) {
            uint32_t en = 0;
            uint32_t d = tmem + ot * 128;
            #pragma unroll
            for (int ch = 0; ch < 2; ++ch) {
                uint64_t ah = make_desc(sb + SM2_A + buf * SM2_ABUF + ch * 32768);
                uint64_t al = ah + (16384 >> 4);
                uint64_t bh = make_desc(sb + SM2_B + ch * 32768);
                uint64_t bl = bh + (16384 >> 4);
                #pragma unroll
                for (int s = 0; s < 4; ++s) {
                    uint64_t ofs = s * 2;
                    mma_bf16_ss(d, ah + ofs, bh + ofs, en); en = 1;
                    mma_bf16_ss(d, ah + ofs, bl + ofs, 1);
                    mma_bf16_ss(d, al + ofs, bh + ofs, 1);
                }
            }
            TCGEN05_COMMIT(sb + SM_MBAR + buf * 8);
        }
    }

    // ---- drain ----
    {
        int lastb = (nOt - 1) & 1;
        if (lastb == 0) { MBARRIER_WAIT_PARITY(sb + SM_MBAR, phA0); }
        else            { MBARRIER_WAIT_PARITY(sb + SM_MBAR + 8, phA1); }
        if (nOt >= 2) {
            int prevb = (nOt - 2) & 1;
            if (prevb == 0) { MBARRIER_WAIT_PARITY(sb + SM_MBAR, phA0); }
            else            { MBARRIER_WAIT_PARITY(sb + SM_MBAR + 8, phA1); }
        }
    }
    TCGEN05_FENCE_AFTER();

    // ---- epilogue ----
    if (tid < 128) {
        int w = tid >> 5, l = tid & 31;
        for (int ot = 0; ot < nOt; ++ot) {
            int o = (blockIdx.y * nOt + ot) * 128 + w * 32 + l;
            #pragma unroll
            for (int g = 0; g < 4; ++g) {
                uint32_t dr[32];
                TCGEN05_LD_32X32B_X32(dr, tmem + ot * 128 + g * 32);
                TCGEN05_WAIT_LD();
                if (o < Cout) {
                    size_t ybase = ((size_t)b * YCtot + o) * N_ + p0 + g * 32;
                    #pragma unroll
                    for (int q = 0; q < 8; ++q) {
                        *(float4*)&Y[ybase + q * 4] = make_float4(
                            __uint_as_float(dr[q * 4 + 0]), __uint_as_float(dr[q * 4 + 1]),
                            __uint_as_float(dr[q * 4 + 2]), __uint_as_float(dr[q * 4 + 3]));
                    }
                }
            }
        }
        TCGEN05_FENCE_BEFORE();
    }

    __syncthreads();
    if (tid == 0) { MBARRIER_INVAL(sb + SM_MBAR); MBARRIER_INVAL(sb + SM_MBAR + 8); }
    __syncthreads();
    if (wid == 0) {
        TCGEN05_RELINQUISH();
        TCGEN05_DEALLOC(tmem, 512);
    }
#else
    // ================= FFMA2 fallback (compute_103 PTX pass) =================
    const float* Wb = pth ? W2 : W1;
    float2 (*Ws2)[16][128] = (float2(*)[16][128])(smem);
    float  (*Xs)[16][128]  = (float(*)[16][128])(smem + 32768);
    const int tx = tid & 15, ty = tid >> 4;

    for (int ot = 0; ot < nOt; ++ot) {
        const int o0 = (blockIdx.y * nOt + ot) * 128;
        unsigned long long acc2[8][4];
        #pragma unroll
        for (int i = 0; i < 8; ++i)
            #pragma unroll
            for (int j = 0; j < 4; ++j) acc2[i][j] = 0ULL;

        for (int kt = 0; kt < 8; ++kt) {
            int buf = kt & 1;
            int k0 = kt * 16;
            #pragma unroll
            for (int u = 0; u < 2; ++u) {
                int e4 = tid + 256 * u;
                int row = e4 & 127, kq = e4 >> 7;
                int o = o0 + row;
                #pragma unroll
                for (int t = 0; t < 4; ++t) {
                    int kk = k0 + kq * 4 + t;
                    float w = (o < Cout) ? Wb[(size_t)o * C_ + kk] : 0.f;
                    Ws2[buf][kq * 4 + t][row] = make_float2(w, w);
                }
            }
            #pragma unroll
            for (int u = 0; u < 2; ++u) {
                int e = tid + 256 * u;
                int row = e >> 5, cq = e & 31;
                int kk = k0 + row;
                float4 v = *(const float4*)&Xb[(size_t)kk * N_ + p0 + cq * 4];
                if (lnOn) {
                    int pix = p0 + cq * 4;
                    float4 m  = *(const float4*)&lnMu[(size_t)bz * N_ + pix];
                    float4 iv = *(const float4*)&lnInv[(size_t)bz * N_ + pix];
                    float wv = lnW[kk], bv = lnB[kk];
                    v.x = (v.x - m.x) * iv.x * wv + bv;
                    v.y = (v.y - m.y) * iv.y * wv + bv;
                    v.z = (v.z - m.z) * iv.z * wv + bv;
                    v.w = (v.w - m.w) * iv.w * wv + bv;
                }
                *(float4*)&Xs[buf][row][cq * 4] = v;
            }
            __syncthreads();
            #pragma unroll
            for (int k = 0; k < 16; ++k) {
                ulonglong2 q0 = *(const ulonglong2*)&Xs[buf][k][tx * 4];
                ulonglong2 q1 = *(const ulonglong2*)&Xs[buf][k][64 + tx * 4];
                unsigned long long bb0 = q0.x, bb1 = q0.y, bb2 = q1.x, bb3 = q1.y;
                const ulonglong2* wrow = (const ulonglong2*)&Ws2[buf][k][ty * 8];
                ulonglong2 w01 = wrow[0], w23 = wrow[1], w45 = wrow[2], w67 = wrow[3];
                unsigned long long av[8] = {w01.x, w01.y, w23.x, w23.y,
                                            w45.x, w45.y, w67.x, w67.y};
                #pragma unroll
                for (int i = 0; i < 8; ++i) {
                    FMA2(acc2[i][0], av[i], bb0);
                    FMA2(acc2[i][1], av[i], bb1);
                    FMA2(acc2[i][2], av[i], bb2);
                    FMA2(acc2[i][3], av[i], bb3);
                }
            }
            __syncthreads();
        }

        #pragma unroll
        for (int i = 0; i < 8; ++i) {
            int o = o0 + ty * 8 + i;
            if (o >= Cout) continue;
            size_t ybase0 = ((size_t)b * YCtot + o) * N_ + p0 + tx * 4;
            float v[8];
            #pragma unroll
            for (int j = 0; j < 4; ++j) UNPK2(v[2 * j], v[2 * j + 1], acc2[i][j]);
            *(float4*)&Y[ybase0]      = make_float4(v[0], v[1], v[2], v[3]);
            *(float4*)&Y[ybase0 + 64] = make_float4(v[4], v[5], v[6], v[7]);
        }
        __syncthreads();
    }
#endif
}

// ---------------- per-pixel LN stats, both paths in one launch ----------------
__global__ void lnstats2k(const float* __restrict__ X1, const float* __restrict__ X2,
                          float* __restrict__ mu, float* __restrict__ inv)
{
    int p = blockIdx.x * 256 + threadIdx.x;
    int zc = blockIdx.y;
    int pth = zc >= B_;
    int b = pth ? zc - B_ : zc;
    const float* xb = (pth ? X2 : X1) + (size_t)b * C_ * N_ + p;
    float s = 0.f, ss = 0.f;
    #pragma unroll 4
    for (int c = 0; c < C_; ++c) {
        float v = xb[(size_t)c * N_];
        s += v; ss += v * v;
    }
    float m = s * (1.f / C_);
    float var = ss * (1.f / C_) - m * m;
    mu[(size_t)zc * N_ + p] = m;
    inv[(size_t)zc * N_ + p] = rsqrtf(var + 1e-5f);
}

// ---------------- fused: x_out = fuse*ca + origin ; write x_out + LN stats ----------------
__global__ void scaleaddstatsk(const float* __restrict__ fuse, const float* __restrict__ cas,
                               const float* __restrict__ origin, float* __restrict__ Y,
                               float* __restrict__ mu, float* __restrict__ inv)
{
    int p = blockIdx.x * 256 + threadIdx.x;
    int b = blockIdx.y;
    __shared__ float sc[C_];
    for (int i = threadIdx.x; i < C_; i += 256) sc[i] = cas[b * C_ + i];
    __syncthreads();
    const size_t base = (size_t)b * C_ * N_ + p;
    float s = 0.f, ss = 0.f;
    #pragma unroll 4
    for (int c = 0; c < C_; ++c) {
        float v = fuse[base + (size_t)c * N_] * sc[c] + origin[base + (size_t)c * N_];
        Y[base + (size_t)c * N_] = v;
        s += v; ss += v * v;
    }
    float m = s * (1.f / C_);
    float var = ss * (1.f / C_) - m * m;
    mu[b * N_ + p] = m;
    inv[b * N_ + p] = rsqrtf(var + 1e-5f);
}

// ---------------- depthwise 3x3 for kv only (2C channels), both paths ----------------
__global__ void dwkvk(const float* __restrict__ kX1, const float* __restrict__ kX2,
                      const float* __restrict__ kW1, const float* __restrict__ kW2,
                      float* __restrict__ kY1, float* __restrict__ kY2)
{
    int c = blockIdx.y;
    int zc = blockIdx.z;
    int pth = zc >= B_;
    int b = pth ? zc - B_ : zc;
    const float* xb = (pth ? kX2 : kX1) + ((size_t)b * C2_ + c) * N_;
    const float* Wd = (pth ? kW2 : kW1);
    float* yb = (pth ? kY2 : kY1) + ((size_t)b * C2_ + c) * N_;

    int y0 = blockIdx.x * 8;
    int tid = threadIdx.x;
    __shared__ float t[10][128];
    for (int i = tid; i < 320; i += 256) {
        int r = i >> 5, xq = i & 31;
        int yy = y0 - 1 + r;
        float4 v = make_float4(0.f, 0.f, 0.f, 0.f);
        if (yy >= 0 && yy < Hh_) v = *(const float4*)&xb[yy * 128 + xq * 4];
        *(float4*)&t[r][xq * 4] = v;
    }
    float w[9];
    #pragma unroll
    for (int q = 0; q < 9; ++q) w[q] = Wd[c * 9 + q];
    __syncthreads();
    int r = tid >> 5;
    int lx = tid & 31;
    float* yo = yb + (y0 + r) * 128;
    #pragma unroll
    for (int u = 0; u < 4; ++u) {
        int x = u * 32 + lx;
        float s = 0.f;
        #pragma unroll
        for (int dy = 0; dy < 3; ++dy) {
            const float* row = t[r + dy];
            float m  = row[x];
            float l  = (x > 0)   ? row[x - 1] : 0.f;
            float rr = (x < 127) ? row[x + 1] : 0.f;
            s += l * w[dy * 3] + m * w[dy * 3 + 1] + rr * w[dy * 3 + 2];
        }
        yo[x] = s;
    }
}

// ---------------- fused FFN dwconv(680) + gelu-gate -> 340 (smem-tiled) ----------------
__global__ void dwgatek(const float* __restrict__ X, const float* __restrict__ Wd,
                        float* __restrict__ Y)
{
    int c = blockIdx.y, b = blockIdx.z;
    int y0 = blockIdx.x * 8;
    int tid = threadIdx.x;
    const float* x1b = X + ((size_t)b * HID2_ + c) * N_;
    const float* x2b = X + ((size_t)b * HID2_ + c + HID_) * N_;
    __shared__ float t1[10][128];
    __shared__ float t2[10][128];
    for (int i = tid; i < 320; i += 256) {
        int r = i >> 5, xq = i & 31;
        int yy = y0 - 1 + r;
        float4 v1 = make_float4(0.f, 0.f, 0.f, 0.f);
        float4 v2 = v1;
        if (yy >= 0 && yy < Hh_) {
            v1 = *(const float4*)&x1b[yy * 128 + xq * 4];
            v2 = *(const float4*)&x2b[yy * 128 + xq * 4];
        }
        *(float4*)&t1[r][xq * 4] = v1;
        *(float4*)&t2[r][xq * 4] = v2;
    }
    float w1[9], w2[9];
    #pragma unroll
    for (int q = 0; q < 9; ++q) { w1[q] = Wd[c * 9 + q]; w2[q] = Wd[(c + HID_) * 9 + q]; }
    __syncthreads();
    int r = tid >> 5;
    int lx = tid & 31;
    float* yo = Y + ((size_t)b * HID_ + c) * N_ + (y0 + r) * 128;
    #pragma unroll
    for (int u = 0; u < 4; ++u) {
        int x = u * 32 + lx;
        float s1 = 0.f, s2 = 0.f;
        #pragma unroll
        for (int dy = 0; dy < 3; ++dy) {
            const float* r1 = t1[r + dy];
            const float* r2 = t2[r + dy];
            float m1  = r1[x],  m2  = r2[x];
            float l1  = (x > 0)   ? r1[x - 1] : 0.f;
            float l2  = (x > 0)   ? r2[x - 1] : 0.f;
            float rr1 = (x < 127) ? r1[x + 1] : 0.f;
            float rr2 = (x < 127) ? r2[x + 1] : 0.f;
            s1 += l1 * w1[dy * 3] + m1 * w1[dy * 3 + 1] + rr1 * w1[dy * 3 + 2];
            s2 += l2 * w2[dy * 3] + m2 * w2[dy * 3 + 1] + rr2 * w2[dy * 3 + 2];
        }
        float ge = 0.5f * s1 * (1.f + erff(s1 * 0.70710678118654752f));
        yo[x] = ge * s2;
    }
}

// ---------------- FUSED q-dwconv + attention partials (per chunk of 8 image rows) ---------
__global__ void attnfusek(const float* __restrict__ Q1, const float* __restrict__ Q2,
                          const float* __restrict__ dw1, const float* __restrict__ dw2,
                          const float* __restrict__ KV1, const float* __restrict__ KV2,
                          float* __restrict__ part)
{
    int chunk = blockIdx.x, h = blockIdx.y;
    int zc = blockIdx.z;
    int pth = zc >= B_;
    int b = pth ? zc - B_ : zc;
    const float* qb = (pth ? Q2 : Q1)  + ((size_t)b * C_  + h * CH_) * N_;
    const float* kb = (pth ? KV2 : KV1) + ((size_t)b * C2_ + h * CH_) * N_;
    const float* wd = (pth ? dw2 : dw1) + h * CH_ * 9;

    __shared__ float qrow[3][16][132];
    __shared__ float qs[16][132];
    __shared__ float ks[16][132];
    __shared__ float wdw[16][9];
    __shared__ float qqp[256], kkp[256];

    int tid = threadIdx.x;
    if (tid < 144) wdw[tid / 9][tid % 9] = wd[tid];

    const int ch = tid >> 4;
    const int grp = tid & 15;
    const int x0 = grp * 8;
    const int y0 = chunk * 8;

    #pragma unroll
    for (int pr = 0; pr < 2; ++pr) {
        int g = y0 - 1 + pr;
        int slot = (g + 1) % 3;
        float4 v0 = make_float4(0.f, 0.f, 0.f, 0.f), v1 = v0;
        if (g >= 0 && g < Hh_) {
            v0 = *(const float4*)&qb[(size_t)ch * N_ + g * 128 + x0];
            v1 = *(const float4*)&qb[(size_t)ch * N_ + g * 128 + x0 + 4];
        }
        *(float4*)&qrow[slot][ch][x0] = v0;
        *(float4*)&qrow[slot][ch][x0 + 4] = v1;
    }

    float acc[16];
    #pragma unroll
    for (int j = 0; j < 16; ++j) acc[j] = 0.f;
    float qq = 0.f, kk = 0.f;

    for (int r = 0; r < 8; ++r) {
        int y = y0 + r;
        {
            int g = y + 1;
            int slot = (g + 1) % 3;
            float4 v0 = make_float4(0.f, 0.f, 0.f, 0.f), v1 = v0;
            if (g < Hh_) {
                v0 = *(const float4*)&qb[(size_t)ch * N_ + g * 128 + x0];
                v1 = *(const float4*)&qb[(size_t)ch * N_ + g * 128 + x0 + 4];
            }
            *(float4*)&qrow[slot][ch][x0] = v0;
            *(float4*)&qrow[slot][ch][x0 + 4] = v1;
            float4 k0 = *(const float4*)&kb[(size_t)ch * N_ + y * 128 + x0];
            float4 k1 = *(const float4*)&kb[(size_t)ch * N_ + y * 128 + x0 + 4];
            *(float4*)&ks[ch][x0] = k0;
            *(float4*)&ks[ch][x0 + 4] = k1;
            kk += k0.x * k0.x + k0.y * k0.y + k0.z * k0.z + k0.w * k0.w;
            kk += k1.x * k1.x + k1.y * k1.y + k1.z * k1.z + k1.w * k1.w;
        }
        __syncthreads();
        {
            const float* r0 = qrow[(y)     % 3][ch];
            const float* r1 = qrow[(y + 1) % 3][ch];
            const float* r2 = qrow[(y + 2) % 3][ch];
            const float* w = wdw[ch];
            #pragma unroll
            for (int t = 0; t < 8; ++t) {
                int x = x0 + t;
                float l0 = (x > 0)   ? r0[x - 1] : 0.f;
                float l1 = (x > 0)   ? r1[x - 1] : 0.f;
                float l2 = (x > 0)   ? r2[x - 1] : 0.f;
                float rr0 = (x < 127) ? r0[x + 1] : 0.f;
                float rr1 = (x < 127) ? r1[x + 1] : 0.f;
                float rr2 = (x < 127) ? r2[x + 1] : 0.f;
                float o = l0 * w[0] + r0[x] * w[1] + rr0 * w[2]
                        + l1 * w[3] + r1[x] * w[4] + rr1 * w[5]
                        + l2 * w[6] + r2[x] * w[7] + rr2 * w[8];
                qs[ch][x] = o;
                qq += o * o;
            }
        }
        __syncthreads();
        {
            int i = tid & 15, s = tid >> 4;
            #pragma unroll
            for (int t = 0; t < 8; ++t) {
                float qv = qs[i][s * 8 + t];
                #pragma unroll
                for (int j = 0; j < 16; ++j) acc[j] += qv * ks[j][s * 8 + t];
            }
        }
        __syncthreads();
    }

    qqp[tid] = qq;
    kkp[tid] = kk;
    float* smg = &qrow[0][0][0];
    {
        int i = tid & 15, s = tid >> 4;
        #pragma unroll
        for (int j = 0; j < 16; ++j) smg[s * 256 + i * 16 + j] = acc[j];
    }
    __syncthreads();

    float* pb = part + (((size_t)zc * HEADS_ + h) * NCHUNK_ + chunk) * 288;
    int i2 = tid >> 4, j2 = tid & 15;
    float a = 0.f;
    #pragma unroll
    for (int s2 = 0; s2 < 16; ++s2) a += smg[s2 * 256 + i2 * 16 + j2];
    pb[i2 * 16 + j2] = a;
    if (tid < 16) {
        float t0 = 0.f;
        #pragma unroll
        for (int g = 0; g < 16; ++g) t0 += qqp[tid * 16 + g];
        pb[256 + tid] = t0;
    } else if (tid < 32) {
        int j = tid - 16;
        float t0 = 0.f;
        #pragma unroll
        for (int g = 0; g < 16; ++g) t0 += kkp[j * 16 + g];
        pb[272 + j] = t0;
    }
}

// ---------------- attention finalize, both paths ----------------
__global__ void attnfink(const float* __restrict__ part, const float* __restrict__ temp1,
                         const float* __restrict__ temp2, float* __restrict__ attnOut)
{
    int h = blockIdx.x;
    int zc = blockIdx.y;
    int pth = zc >= B_;
    const float* temp = pth ? temp2 : temp1;
    const float* pb = part + ((size_t)zc * HEADS_ + h) * NCHUNK_ * 288;
    __shared__ float qqs[16], kks[16];
    int tid = threadIdx.x;

    float a = 0.f;
    #pragma unroll
    for (int c = 0; c < NCHUNK_; ++c) a += pb[c * 288 + tid];

    if (tid < 16) {
        float t0 = 0.f;
        #pragma unroll
        for (int c = 0; c < NCHUNK_; ++c) t0 += pb[c * 288 + 256 + tid];
        qqs[tid] = fmaxf(sqrtf(t0), 1e-12f);
    } else if (tid < 32) {
        int j = tid - 16;
        float t0 = 0.f;
        #pragma unroll
        for (int c = 0; c < NCHUNK_; ++c) t0 += pb[c * 288 + 272 + j];
        kks[j] = fmaxf(sqrtf(t0), 1e-12f);
    }
    __syncthreads();

    int i2 = tid >> 4, j2 = tid & 15;
    a = a / (qqs[i2] * kks[j2]) * temp[h];

    unsigned mask = 0xFFFFFFFFu;
    float mx = a;
    for (int w = 8; w > 0; w >>= 1) mx = fmaxf(mx, __shfl_xor_sync(mask, mx, w, 16));
    float e = expf(a - mx);
    float ssum = e;
    for (int w = 8; w > 0; w >>= 1) ssum += __shfl_xor_sync(mask, ssum, w, 16);
    attnOut[((size_t)zc * HEADS_ + h) * 256 + i2 * 16 + j2] = e / ssum;
}

// ---------------- M[zc] = po @ blockdiag(attn[zc]); fp32 + pre-swizzled tiles ----------------
__global__ void poattnk(const float* __restrict__ po1, const float* __restrict__ po2,
                        const float* __restrict__ attn, float* __restrict__ M,
                        uint8_t* __restrict__ MT)
{
    int zc = blockIdx.x;
    const float* po = (zc >= B_) ? po2 : po1;
    uint8_t* mt = MT + (size_t)zc * 2 * TILE_B;
    __shared__ float at[HEADS_ * 256];
    for (int i = threadIdx.x; i < HEADS_ * 256; i += 256)
        at[i] = attn[(size_t)zc * HEADS_ * 256 + i];
    __syncthreads();
    for (int idx2 = threadIdx.x; idx2 < C_ * 64; idx2 += 256) {
        int o = idx2 >> 6, j2 = idx2 & 63;
        int cj = 2 * j2;
        int h = cj >> 4;
        int jj = cj & 15;
        float s0 = 0.f, s1 = 0.f;
        #pragma unroll
        for (int i = 0; i < 16; ++i) {
            float pv = po[o * C_ + h * 16 + i];
            s0 += pv * at[h * 256 + i * 16 + jj];
            s1 += pv * at[h * 256 + i * 16 + jj + 1];
        }
        M[((size_t)zc * C_ + o) * C_ + cj] = s0;
        M[((size_t)zc * C_ + o) * C_ + cj + 1] = s1;
        uint32_t hp, lp;
        split2(s0, s1, hp, lp);
        int chk = cj >> 6;
        uint32_t off = SWZ((uint32_t)(o * 128 + (cj & 63) * 2));
        *(uint32_t*)(mt + chk * TILE_B + off) = hp;
        *(uint32_t*)(mt + chk * TILE_B + 16384 + off) = lp;
    }
}

// ---------------- global average pool per (b,c) ----------------
__global__ void capoolk(const float* __restrict__ X, float* __restrict__ pool)
{
    int c = blockIdx.x, b = blockIdx.y;
    const float* xb = X + ((size_t)b * C_ + c) * N_;
    float s = 0.f;
    for (int n = threadIdx.x * 4; n < N_; n += 1024) {
        float4 v = *(const float4*)&xb[n];
        s += v.x + v.y + v.z + v.w;
    }
    __shared__ float red[256];
    red[threadIdx.x] = s; __syncthreads();
    for (int st = 128; st > 0; st >>= 1) {
        if (threadIdx.x < st) red[threadIdx.x] += red[threadIdx.x + st];
        __syncthreads();
    }
    if (threadIdx.x == 0) pool[b * C_ + c] = red[0] * (1.f / N_);
}

// ---------------- CA: relu FC (128->8) + sigmoid FC (8->128) ----------------
__global__ void cafck(const float* __restrict__ pool,
                      const float* __restrict__ w1, const float* __restrict__ b1,
                      const float* __restrict__ w2, const float* __restrict__ b2,
                      float* __restrict__ cas)
{
    int b = blockIdx.x, t = threadIdx.x;
    __shared__ float pl[C_];
    __shared__ float hid[8];
    pl[t] = pool[b * C_ + t];
    __syncthreads();
    if (t < 8) {
        float s = b1[t];
        #pragma unroll 4
        for (int c = 0; c < C_; ++c) s += w1[t * C_ + c] * pl[c];
        hid[t] = fmaxf(s, 0.f);
    }
    __syncthreads();
    float s = b2[t];
    #pragma unroll
    for (int r = 0; r < 8; ++r) s += w2[t * 8 + r] * hid[r];
    cas[b * C_ + t] = 1.f / (1.f + expf(-s));
}

// ---------------- host ----------------
extern "C" void kernel_launch(void* const* d_in, const int* in_sizes, int n_in,
                              void* d_out, int out_size)
{
    (void)in_sizes; (void)n_in; (void)out_size;
    const float* origin  = (const float*)d_in[0];
    const float* low     = (const float*)d_in[1];
    const float* high    = (const float*)d_in[2];
    const float* norm1_w = (const float*)d_in[3];
    const float* norm1_b = (const float*)d_in[4];
    const float* norm_1_w= (const float*)d_in[5];
    const float* norm_1_b= (const float*)d_in[6];
    const float* norm2_w = (const float*)d_in[7];
    const float* norm2_b = (const float*)d_in[8];
    const float* a1_q    = (const float*)d_in[9];
    const float* a1_qdw  = (const float*)d_in[10];
    const float* a1_kv   = (const float*)d_in[11];
    const float* a1_kvdw = (const float*)d_in[12];
    const float* a1_po   = (const float*)d_in[13];
    const float* a1_temp = (const float*)d_in[14];
    const float* a2_q    = (const float*)d_in[15];
    const float* a2_qdw  = (const float*)d_in[16];
    const float* a2_kv   = (const float*)d_in[17];
    const float* a2_kvdw = (const float*)d_in[18];
    const float* a2_po   = (const float*)d_in[19];
    const float* a2_temp = (const float*)d_in[20];
    const float* conv1_w = (const float*)d_in[21];
    const float* ca1_w   = (const float*)d_in[22];
    const float* ca1_b   = (const float*)d_in[23];
    const float* ca2_w   = (const float*)d_in[24];
    const float* ca2_b   = (const float*)d_in[25];
    const float* ffn_pi  = (const float*)d_in[26];
    const float* ffn_dw  = (const float*)d_in[27];
    const float* ffn_po  = (const float*)d_in[28];
    float* out = (float*)d_out;

    float *bufCb, *bufCc, *buf2Ca, *buf2Cb, *buf2Cc, *bufHa, *bufHb, *xout;
    float *mu, *inv, *attnp, *attnw, *Mw, *pool, *cas;
    uint8_t *wt, *MwT;
    cudaGetSymbolAddress((void**)&bufCb, g_bufCb);
    cudaGetSymbolAddress((void**)&bufCc, g_bufCc);
    cudaGetSymbolAddress((void**)&buf2Ca, g_buf2Ca);
    cudaGetSymbolAddress((void**)&buf2Cb, g_buf2Cb);
    cudaGetSymbolAddress((void**)&buf2Cc, g_buf2Cc);
    cudaGetSymbolAddress((void**)&bufHa, g_bufHa);
    cudaGetSymbolAddress((void**)&bufHb, g_bufHb);
    cudaGetSymbolAddress((void**)&xout, g_xout);
    cudaGetSymbolAddress((void**)&mu, g_mu);
    cudaGetSymbolAddress((void**)&inv, g_inv);
    cudaGetSymbolAddress((void**)&attnp, g_attnp);
    cudaGetSymbolAddress((void**)&attnw, g_attnw);
    cudaGetSymbolAddress((void**)&Mw, g_Mw);
    cudaGetSymbolAddress((void**)&pool, g_pool);
    cudaGetSymbolAddress((void**)&cas, g_cas);
    cudaGetSymbolAddress((void**)&wt, g_wt);
    cudaGetSymbolAddress((void**)&MwT, g_MwT);

    static int smem_set = 0;
    if (!smem_set) {
        cudaFuncSetAttribute(gemmtc, cudaFuncAttributeMaxDynamicSharedMemorySize, SM_TOTAL);
        cudaFuncSetAttribute(gemmtc2, cudaFuncAttributeMaxDynamicSharedMemorySize, SM2_TOTAL);
        smem_set = 1;
    }

    // tile offsets (in tiles of TILE_B bytes) — must match wtileall bases
    uint8_t* t_a1q  = wt;                 // 2 tiles
    uint8_t* t_a2q  = wt + 2  * TILE_B;   // 2
    uint8_t* t_a1kv = wt + 4  * TILE_B;   // 4
    uint8_t* t_a2kv = wt + 8  * TILE_B;   // 4
    uint8_t* t_cv1  = wt + 12 * TILE_B;   // 4
    uint8_t* t_fpi  = wt + 16 * TILE_B;   // 12
    uint8_t* t_fpo  = wt + 28 * TILE_B;   // 6

    dim3 tb(256);
    // ===== weight pre-tiling: ONE launch =====
    wtileall<<<dim3(34), tb>>>(a1_q, a2_q, a1_kv, a2_kv, conv1_w, ffn_pi, ffn_po, wt);

    dim3 gLN2(N_ / 256, 2 * B_);
    dim3 gLN(N_ / 256, B_);
    dim3 gQ(N_ / 128, 1, 2 * B_);
    dim3 gKV2(N_ / 128, 1, 2 * B_);
    dim3 gMv(N_ / 128, 1, 2 * B_);
    dim3 gG_C(N_ / 128, 1, B_);
    dim3 gFpi(N_ / 128, 2, B_);
    dim3 gRow(C_, B_);
    dim3 gAttnP(NCHUNK_, HEADS_, 2 * B_);
    dim3 gAttnF(HEADS_, 2 * B_);
    dim3 gDWkv(Hh_ / 8, C2_, 2 * B_);
    dim3 gDW_H(Hh_ / 8, HID_, B_);

    // ===== both attention paths, merged launches =====
    gemmtc<<<gQ, tb, SM_TOTAL>>>(t_a1q, high, bufCb, nullptr,
                                 t_a2q, low, bufCc, nullptr,
                                 a1_q, a2_q,
                                 nullptr, nullptr, nullptr, nullptr, nullptr, nullptr,
                                 C_, C_, C_, C_, 0, 0, 0, 0, 0);
    lnstats2k<<<gLN2, tb>>>(low, high, mu, inv);
    gemmtc2<<<gKV2, tb, SM2_TOTAL>>>(t_a1kv, low, buf2Ca,
                                     t_a2kv, high, buf2Cb,
                                     a1_kv, a2_kv,
                                     mu, inv, norm1_w, norm1_b, norm_1_w, norm_1_b,
                                     C2_, C_, C2_, 4, 2);
    dwkvk<<<gDWkv, tb>>>(buf2Ca, buf2Cb, a1_kvdw, a2_kvdw, buf2Cc, bufHa);
    attnfusek<<<gAttnP, tb>>>(bufCb, bufCc, a1_qdw, a2_qdw, buf2Cc, bufHa, attnp);
    attnfink<<<gAttnF, tb>>>(attnp, a1_temp, a2_temp, attnw);
    poattnk<<<dim3(2 * B_), tb>>>(a1_po, a2_po, attnw, Mw, MwT);
    gemmtc<<<gMv, tb, SM_TOTAL>>>(MwT, buf2Cc + (size_t)C_ * N_, buf2Ca, low,
                                  MwT + (size_t)B_ * 2 * TILE_B, bufHa + (size_t)C_ * N_, buf2Ca, high,
                                  Mw, Mw + (size_t)B_ * C_ * C_,
                                  nullptr, nullptr, nullptr, nullptr, nullptr, nullptr,
                                  C_, C_, C2_, C2_, 0, C_, 1, 2, C_ * C_);

    // ===== fuse: conv1(concat) -> CA -> + origin, fused with norm2 stats =====
    gemmtc<<<gG_C, tb, SM_TOTAL>>>(t_cv1, buf2Ca, bufCb, nullptr,
                                   t_cv1, buf2Ca, bufCb, nullptr,
                                   conv1_w, conv1_w,
                                   nullptr, nullptr, nullptr, nullptr, nullptr, nullptr,
                                   C_, C2_, C2_, C_, 0, 0, 0, 0, 0);
    capoolk<<<gRow, tb>>>(bufCb, pool);
    cafck<<<dim3(B_), dim3(128)>>>(pool, ca1_w, ca1_b, ca2_w, ca2_b, cas);
    scaleaddstatsk<<<gLN, tb>>>(bufCb, cas, origin, xout, mu, inv);

    // ===== FFN with residual =====
    gemmtc2<<<gFpi, tb, SM2_TOTAL>>>(t_fpi, xout, bufHa,
                                     t_fpi, xout, bufHa,
                                     ffn_pi, ffn_pi,
                                     mu, inv, norm2_w, norm2_b, norm2_w, norm2_b,
                                     HID2_, C_, HID2_, 4, 3);
    dwgatek<<<gDW_H, tb>>>(bufHa, ffn_dw, bufHb);
    gemmtc<<<gG_C, tb, SM_TOTAL>>>(t_fpo, bufHb, out, xout,
                                   t_fpo, bufHb, out, xout,
                                   ffn_po, ffn_po,
                                   nullptr, nullptr, nullptr, nullptr, nullptr, nullptr,
                                   C_, HID_, HID_, C_, 0, 0, 3, 0, 0);
}

// round 17
// speedup vs baseline: 1.7559x; 1.1610x over previous
#include <cuda_runtime.h>
#include <cuda_bf16.h>
#include <math.h>
#include <stdint.h>

#define B_    8
#define C_    128
#define Hh_   128
#define Ww_   128
#define N_    16384      // H*W
#define HEADS_ 8
#define CH_   16         // C/HEADS
#define HID_  340
#define HID2_ 680
#define C2_   256
#define NCHUNK_ 16
#define CHUNKN_ (N_ / NCHUNK_)   // 1024
#define TILE_B 32768             // one pre-swizzled W tile: 16KB hi + 16KB lo

// ---------------- static scratch (no allocations allowed) ----------------
__device__ float g_bufCb[(size_t)B_ * C_ * N_];   // qpre path1 / conv1 out
__device__ float g_bufCc[(size_t)B_ * C_ * N_];   // qpre path2
__device__ float g_buf2Ca[(size_t)B_ * C2_ * N_]; // kvpre path1 / concat out
__device__ float g_buf2Cb[(size_t)B_ * C2_ * N_]; // kvpre path2
__device__ float g_buf2Cc[(size_t)B_ * C2_ * N_]; // kvdw path1
__device__ float g_bufHa[(size_t)B_ * HID2_ * N_];// kvdw path2 (front 2C) / ffn hidden
__device__ float g_bufHb[(size_t)B_ * HID_ * N_]; // gated
__device__ float g_xout[(size_t)B_ * C_ * N_];
__device__ float g_mu[2 * B_ * N_];
__device__ float g_inv[2 * B_ * N_];
__device__ float g_attnp[2 * B_ * HEADS_ * NCHUNK_ * 288];
__device__ float g_attnw[2 * B_ * HEADS_ * CH_ * CH_];
__device__ float g_Mw[2 * B_ * C_ * C_];
__device__ float g_pool[B_ * C_];
__device__ float g_cas[B_ * C_];
// pre-swizzled weight tiles: 34 static + 32 for Mw
__device__ __align__(16) uint8_t g_wt[34 * TILE_B];
__device__ __align__(16) uint8_t g_MwT[32 * TILE_B];

// packed f32x2 helpers (fallback path)
#define FMA2(d, a, b) asm("fma.rn.f32x2 %0, %1, %2, %0;" : "+l"(d) : "l"(a), "l"(b))
#define UNPK2(lo, hi, s) asm("mov.b64 {%0, %1}, %2;" : "=f"(lo), "=f"(hi) : "l"(s))

// ---------------- PTX helpers ----------------
__device__ __forceinline__ uint32_t smem_u32(const void* p) {
    uint32_t a;
    asm("{ .reg .u64 t; cvta.to.shared.u64 t, %1; cvt.u32.u64 %0, t; }" : "=r"(a) : "l"(p));
    return a;
}
#define SWZ(o) ((o) ^ (((o) >> 3) & 0x70))

#if defined(__CUDA_ARCH_FEAT_SM103_ALL) || !defined(__CUDA_ARCH__)
#define HAS_TC 1
#else
#define HAS_TC 0
#endif

#define MBARRIER_INIT(addr, cnt) \
    asm volatile("mbarrier.init.shared.b64 [%0], %1;" :: "r"((uint32_t)(addr)), "r"((uint32_t)(cnt)) : "memory")
#define MBARRIER_INVAL(addr) \
    asm volatile("mbarrier.inval.shared.b64 [%0];" :: "r"((uint32_t)(addr)) : "memory")
#define MBARRIER_WAIT_PARITY(mbar_smem_addr, phase_parity) do { \
    uint32_t _mbar = (uint32_t)(mbar_smem_addr); \
    uint32_t _parity = (uint32_t)(phase_parity); \
    uint32_t _done; \
    asm volatile("{\n\t.reg .pred p;\n\t" \
        "mbarrier.try_wait.parity.acquire.cta.shared::cta.b64 p, [%1], %2;\n\t" \
        "selp.b32 %0, 1, 0, p;\n\t}" : "=r"(_done) : "r"(_mbar), "r"(_parity) : "memory"); \
    if (!_done) { \
        asm volatile("{\n\t.reg .pred P1;\n\t" \
            "WAIT_LOOP_%=:\n\t" \
            "mbarrier.try_wait.parity.acquire.cta.shared::cta.b64 P1, [%0], %1, 0x989680;\n\t" \
            "@P1 bra.uni WAIT_DONE_%=;\n\t" \
            "bra.uni WAIT_LOOP_%=;\n\t" \
            "WAIT_DONE_%=:\n\t}" :: "r"(_mbar), "r"(_parity) : "memory"); \
    } \
} while (0)

#if HAS_TC
#define TCGEN05_ALLOC(smem_result_addr, nCols) \
    asm volatile("tcgen05.alloc.cta_group::1.sync.aligned.shared::cta.b32 [%0], %1;" \
        :: "r"((uint32_t)(smem_result_addr)), "r"((uint32_t)(nCols)) : "memory")
#define TCGEN05_DEALLOC(tmem_addr, nCols) \
    asm volatile("tcgen05.dealloc.cta_group::1.sync.aligned.b32 %0, %1;" :: "r"(tmem_addr), "r"((uint32_t)(nCols)))
#define TCGEN05_RELINQUISH() \
    asm volatile("tcgen05.relinquish_alloc_permit.cta_group::1.sync.aligned;")
#define TCGEN05_COMMIT(mbar_smem_addr) \
    asm volatile("tcgen05.commit.cta_group::1.mbarrier::arrive::one.shared::cluster.b64 [%0];" \
        :: "r"((uint32_t)(mbar_smem_addr)) : "memory")
#define TCGEN05_FENCE_AFTER() asm volatile("tcgen05.fence::after_thread_sync;" ::: "memory")
#define TCGEN05_FENCE_BEFORE() asm volatile("tcgen05.fence::before_thread_sync;" ::: "memory")
#define TCGEN05_WAIT_LD() asm volatile("tcgen05.wait::ld.sync.aligned;" ::: "memory")
#define FENCE_ASYNC_SHARED() asm volatile("fence.proxy.async.shared::cta;" ::: "memory")

#define TCGEN05_LD_32X32B_X32(r, tmem_addr) \
    asm volatile( \
        "tcgen05.ld.sync.aligned.32x32b.x32.b32 " \
        "{%0, %1, %2, %3, %4, %5, %6, %7, " \
        " %8, %9, %10, %11, %12, %13, %14, %15, " \
        " %16, %17, %18, %19, %20, %21, %22, %23, " \
        " %24, %25, %26, %27, %28, %29, %30, %31}, [%32];" \
        : "=r"((r)[0]),  "=r"((r)[1]),  "=r"((r)[2]),  "=r"((r)[3]), \
          "=r"((r)[4]),  "=r"((r)[5]),  "=r"((r)[6]),  "=r"((r)[7]), \
          "=r"((r)[8]),  "=r"((r)[9]),  "=r"((r)[10]), "=r"((r)[11]), \
          "=r"((r)[12]), "=r"((r)[13]), "=r"((r)[14]), "=r"((r)[15]), \
          "=r"((r)[16]), "=r"((r)[17]), "=r"((r)[18]), "=r"((r)[19]), \
          "=r"((r)[20]), "=r"((r)[21]), "=r"((r)[22]), "=r"((r)[23]), \
          "=r"((r)[24]), "=r"((r)[25]), "=r"((r)[26]), "=r"((r)[27]), \
          "=r"((r)[28]), "=r"((r)[29]), "=r"((r)[30]), "=r"((r)[31]) \
        : "r"(tmem_addr))

// SW128 SMEM descriptor (LBO=1, SBO=64, version=1, layout=SW128)
__device__ __forceinline__ uint64_t make_desc(uint32_t addr) {
    const uint64_t base = (uint64_t(2) << 61) | (uint64_t(1) << 46)
                        | (uint64_t(64) << 32) | (uint64_t(1) << 16);
    return base | ((uint64_t)(addr >> 4) & 0x3FFF);
}

// bf16 SS MMA, cg1: D[M=128, N=128] += A[M,K=16] * B[N,K=16]^T
#define MMA_IDESC 0x8200490u
__device__ __forceinline__ void mma_bf16_ss(uint32_t d, uint64_t ad, uint64_t bd, uint32_t en) {
    asm volatile(
        "{\n\t.reg .pred p;\n\tsetp.ne.u32 p, %5, 0;\n\t"
        "tcgen05.mma.cta_group::1.kind::f16 [%0], %1, %2, %3, {%4, %4, %4, %4}, p;\n\t}"
        :: "r"(d), "l"(ad), "l"(bd), "r"(MMA_IDESC), "r"(0u), "r"(en) : "memory");
}
#endif  // HAS_TC

// gemmtc smem layout (bytes) — DOUBLE-buffered, direct staging (no xs)
#define SM_TMEM   0
#define SM_MBAR   16           // 2 mbarriers @16, @24
#define SM_TILES  1024         // per buffer: AHI,ALO,BHI,BLO @16KB
#define SM_BUFSZ  65536
#define SM_TOTAL  (SM_TILES + 2 * SM_BUFSZ)   // 132096 B

// gemmtc2 smem layout: B resident (2 chunks), A double-buffered
#define SM2_B     1024         // 2 x 32KB = [1024, 66560)
#define SM2_A     66560        // 2 x 65536
#define SM2_ABUF  65536
#define SM2_TOTAL 197632

// truncation-based hi/lo bf16 split, packed pairs via PRMT
__device__ __forceinline__ uint32_t prmt_hi(uint32_t u0, uint32_t u1) {
    uint32_t r;
    asm("prmt.b32 %0, %1, %2, 0x7632;" : "=r"(r) : "r"(u0), "r"(u1));
    return r;
}
__device__ __forceinline__ void split2(float x0, float x1, uint32_t& hp, uint32_t& lp) {
    uint32_t u0 = __float_as_uint(x0), u1 = __float_as_uint(x1);
    hp = prmt_hi(u0, u1);
    float l0 = x0 - __uint_as_float(u0 & 0xFFFF0000u);
    float l1 = x1 - __uint_as_float(u1 & 0xFFFF0000u);
    lp = prmt_hi(__float_as_uint(l0), __float_as_uint(l1));
}

// direct B-staging: thread (n, half) converts k-range [half*32, half*32+32) at column n
__device__ __forceinline__ void stageB_direct(
    const float* __restrict__ Xb, int k0, int Cin, int p0, int n, int half,
    int lnOn, float mun, float ivn,
    const float* __restrict__ lnW, const float* __restrict__ lnB,
    char* bbase, char* blbase)
{
    #pragma unroll
    for (int g = 0; g < 4; ++g) {
        uint32_t hw[4], lw[4];
        #pragma unroll
        for (int q = 0; q < 4; ++q) {
            int k1 = half * 32 + g * 8 + q * 2;
            int kkA = k0 + k1, kkB = kkA + 1;
            float a = (kkA < Cin) ? Xb[(size_t)kkA * N_ + p0 + n] : 0.f;
            float c = (kkB < Cin) ? Xb[(size_t)kkB * N_ + p0 + n] : 0.f;
            if (lnOn) {
                if (kkA < Cin) a = (a - mun) * ivn * lnW[kkA] + lnB[kkA];
                if (kkB < Cin) c = (c - mun) * ivn * lnW[kkB] + lnB[kkB];
            }
            split2(a, c, hw[q], lw[q]);
        }
        uint32_t off = SWZ((uint32_t)(n * 128 + half * 64 + g * 16));
        *(uint4*)(bbase + off) = make_uint4(hw[0], hw[1], hw[2], hw[3]);
        *(uint4*)(blbase + off) = make_uint4(lw[0], lw[1], lw[2], lw[3]);
    }
}

// ---------------- merged weight pre-tiler: all 7 weights in ONE launch ----------------
__global__ void wtileall(const float* __restrict__ a1q, const float* __restrict__ a2q,
                         const float* __restrict__ a1kv, const float* __restrict__ a2kv,
                         const float* __restrict__ cv1, const float* __restrict__ fpi,
                         const float* __restrict__ fpo, uint8_t* __restrict__ tiles)
{
    int t = blockIdx.x;   // 0..33
    const float* W; int Cout, Cin, base;
    if (t < 2)       { W = a1q;  Cout = C_;    Cin = C_;   base = 0;  }
    else if (t < 4)  { W = a2q;  Cout = C_;    Cin = C_;   base = 2;  }
    else if (t < 8)  { W = a1kv; Cout = C2_;   Cin = C_;   base = 4;  }
    else if (t < 12) { W = a2kv; Cout = C2_;   Cin = C_;   base = 8;  }
    else if (t < 16) { W = cv1;  Cout = C_;    Cin = C2_;  base = 12; }
    else if (t < 28) { W = fpi;  Cout = HID2_; Cin = C_;   base = 16; }
    else             { W = fpo;  Cout = C_;    Cin = HID_; base = 28; }
    int lt = t - base;
    int KchT = (Cin + 63) >> 6;
    int kt = lt % KchT, ot = lt / KchT;
    uint8_t* tb = tiles + (size_t)t * TILE_B;

    const int tid = threadIdx.x;
    int r = tid >> 1;
    int kh = (tid & 1) << 5;
    int o = ot * 128 + r;
    #pragma unroll
    for (int i = 0; i < 8; ++i) {
        int kk = kt * 64 + kh + i * 4;
        float4 v;
        v.x = (o < Cout && kk + 0 < Cin) ? W[(size_t)o * Cin + kk + 0] : 0.f;
        v.y = (o < Cout && kk + 1 < Cin) ? W[(size_t)o * Cin + kk + 1] : 0.f;
        v.z = (o < Cout && kk + 2 < Cin) ? W[(size_t)o * Cin + kk + 2] : 0.f;
        v.w = (o < Cout && kk + 3 < Cin) ? W[(size_t)o * Cin + kk + 3] : 0.f;
        uint32_t hp0, lp0, hp1, lp1;
        split2(v.x, v.y, hp0, lp0);
        split2(v.z, v.w, hp1, lp1);
        uint32_t off = SWZ((uint32_t)(r * 128 + (kh + i * 4) * 2));
        *(uint2*)(tb + off) = make_uint2(hp0, hp1);
        *(uint2*)(tb + 16384 + off) = make_uint2(lp0, lp1);
    }
}

// ---------------- GEMM: Y[b, Yoff+o, p] = sum_c W[o,c] LN?(X[b,c,p]) ----------------
// flags: 1=residual add, 2=nan_to_num, 4=apply LN to X on load
__global__ void __launch_bounds__(256, 1)
gemmtc(const uint8_t* __restrict__ Wt1, const float* __restrict__ X1,
       float* __restrict__ Y1, const float* __restrict__ R1,
       const uint8_t* __restrict__ Wt2, const float* __restrict__ X2,
       float* __restrict__ Y2, const float* __restrict__ R2,
       const float* __restrict__ W1, const float* __restrict__ W2,
       const float* __restrict__ lnMu, const float* __restrict__ lnInv,
       const float* __restrict__ lnW1, const float* __restrict__ lnB1,
       const float* __restrict__ lnW2, const float* __restrict__ lnB2,
       int Cout, int Cin, int XCtot, int YCtot, int Yoff1, int Yoff2,
       int flags, int WtTilesPerB, int WstrideB)
{
    extern __shared__ __align__(1024) char smem[];

    const int bz = blockIdx.z;
    const int pth = bz >= B_;
    const int b = pth ? bz - B_ : bz;
    const int o0 = blockIdx.y * 128;
    const int p0 = blockIdx.x * 128;
    const float* Xb = (pth ? X2 : X1) + (size_t)b * XCtot * N_;
    float* Y = pth ? Y2 : Y1;
    const float* R = pth ? R2 : R1;
    const float* lnW = pth ? lnW2 : lnW1;
    const float* lnB = pth ? lnB2 : lnB1;
    const int Yoff = pth ? Yoff2 : Yoff1;
    const int lnOn = flags & 4;
    const int tid = threadIdx.x;
    const int nch = (Cin + 63) >> 6;   // == KchT

#if HAS_TC && defined(__CUDA_ARCH__)
    // ================= tcgen05 path (sm_103a cubin) =================
    const uint8_t* Wtb = (pth ? Wt2 : Wt1) + (size_t)b * WtTilesPerB * TILE_B;
    const uint32_t sb = smem_u32(smem);
    const int wid = tid >> 5;

    if (tid == 0) {
        MBARRIER_INIT(sb + SM_MBAR, 1);
        MBARRIER_INIT(sb + SM_MBAR + 8, 1);
    }
    if (wid == 0) TCGEN05_ALLOC(sb + SM_TMEM, 128);
    __syncthreads();
    uint32_t tmem;
    asm volatile("ld.shared.b32 %0, [%1];" : "=r"(tmem) : "r"(sb + SM_TMEM));

    int ph0 = 0, ph1 = 0;
    uint32_t en = 0;

    const int n = tid & 127, half = tid >> 7;
    float mun = 0.f, ivn = 1.f;
    if (lnOn) {
        mun = lnMu[(size_t)bz * N_ + p0 + n];
        ivn = lnInv[(size_t)bz * N_ + p0 + n];
    }

    for (int ch = 0; ch < nch; ++ch) {
        const int bf = ch & 1;
        const int k0 = ch << 6;
        if (ch >= 2) {
            if (bf == 0) { MBARRIER_WAIT_PARITY(sb + SM_MBAR, ph0); ph0 ^= 1; }
            else         { MBARRIER_WAIT_PARITY(sb + SM_MBAR + 8, ph1); ph1 ^= 1; }
        }
        char* abase = smem + SM_TILES + bf * SM_BUFSZ;   // AHI (+16K ALO)
        char* bbase = abase + 32768;                     // BHI
        char* blbase = abase + 49152;                    // BLO

        // ---- stage A: straight copy of pre-swizzled hi/lo tile (32KB) ----
        {
            const uint4* src = (const uint4*)(Wtb + ((size_t)(blockIdx.y * nch + ch)) * TILE_B);
            uint4* dst = (uint4*)abase;
            #pragma unroll
            for (int i = 0; i < 8; ++i)
                dst[tid + 256 * i] = src[tid + 256 * i];
        }

        // ---- stage B: direct global -> split -> swizzled smem ----
        stageB_direct(Xb, k0, Cin, p0, n, half, lnOn, mun, ivn, lnW, lnB, bbase, blbase);

        FENCE_ASYNC_SHARED();
        __syncthreads();

        // ---- issue MMAs for this chunk ----
        if (tid == 0) {
            uint64_t ah = make_desc(sb + SM_TILES + bf * SM_BUFSZ);
            uint64_t al = ah + (16384 >> 4);
            uint64_t bh = ah + (32768 >> 4);
            uint64_t bl = ah + (49152 >> 4);
            #pragma unroll
            for (int s = 0; s < 4; ++s) {
                uint64_t ofs = s * 2;
                mma_bf16_ss(tmem, ah + ofs, bh + ofs, en); en = 1;
                mma_bf16_ss(tmem, ah + ofs, bl + ofs, 1);
                mma_bf16_ss(tmem, al + ofs, bh + ofs, 1);
            }
            TCGEN05_COMMIT(sb + SM_MBAR + bf * 8);
        }
    }

    // ---- drain ----
    { MBARRIER_WAIT_PARITY(sb + SM_MBAR, ph0); }
    if (nch >= 2) { MBARRIER_WAIT_PARITY(sb + SM_MBAR + 8, ph1); }
    TCGEN05_FENCE_AFTER();

    // ---- epilogue: warps 0-3 read TMEM D and store ----
    const int doResid = flags & 1, doFinal = flags & 2;
    if (tid < 128) {
        int w = tid >> 5, l = tid & 31;
        int o = o0 + w * 32 + l;
        #pragma unroll
        for (int g = 0; g < 4; ++g) {
            uint32_t dr[32];
            TCGEN05_LD_32X32B_X32(dr, tmem + g * 32);
            TCGEN05_WAIT_LD();
            if (o < Cout) {
                size_t ybase = ((size_t)b * YCtot + Yoff + o) * N_ + p0 + g * 32;
                size_t rbase = ((size_t)b * Cout + o) * N_ + p0 + g * 32;
                #pragma unroll
                for (int q = 0; q < 8; ++q) {
                    float v0 = __uint_as_float(dr[q * 4 + 0]);
                    float v1 = __uint_as_float(dr[q * 4 + 1]);
                    float v2 = __uint_as_float(dr[q * 4 + 2]);
                    float v3 = __uint_as_float(dr[q * 4 + 3]);
                    if (doResid) {
                        float4 r4 = *(const float4*)&R[rbase + q * 4];
                        v0 += r4.x; v1 += r4.y; v2 += r4.z; v3 += r4.w;
                    }
                    if (doFinal) {
                        v0 = isfinite(v0) ? v0 : 1e-5f;
                        v1 = isfinite(v1) ? v1 : 1e-5f;
                        v2 = isfinite(v2) ? v2 : 1e-5f;
                        v3 = isfinite(v3) ? v3 : 1e-5f;
                    }
                    *(float4*)&Y[ybase + q * 4] = make_float4(v0, v1, v2, v3);
                }
            }
        }
        TCGEN05_FENCE_BEFORE();
    }

    __syncthreads();
    if (tid == 0) { MBARRIER_INVAL(sb + SM_MBAR); MBARRIER_INVAL(sb + SM_MBAR + 8); }
    __syncthreads();
    if (wid == 0) {
        TCGEN05_RELINQUISH();
        TCGEN05_DEALLOC(tmem, 128);
    }
#else
    // ================= FFMA2 fallback (compute_103 PTX pass) =================
    const float* Wb = (pth ? W2 : W1) + (size_t)b * WstrideB;
    float2 (*Ws2)[16][128] = (float2(*)[16][128])(smem);            // 32KB
    float  (*Xs)[16][128]  = (float(*)[16][128])(smem + 32768);     // 16KB

    const int tx = tid & 15, ty = tid >> 4;
    unsigned long long acc2[8][4];
    #pragma unroll
    for (int i = 0; i < 8; ++i)
        #pragma unroll
        for (int j = 0; j < 4; ++j) acc2[i][j] = 0ULL;

    const int ktiles = (Cin + 15) >> 4;
    for (int kt = 0; kt < ktiles; ++kt) {
        int buf = kt & 1;
        int k0 = kt * 16;
        #pragma unroll
        for (int u = 0; u < 2; ++u) {
            int e4 = tid + 256 * u;
            int row = e4 & 127, kq = e4 >> 7;
            int o = o0 + row;
            #pragma unroll
            for (int t = 0; t < 4; ++t) {
                int kk = k0 + kq * 4 + t;
                float w = (o < Cout && kk < Cin) ? Wb[(size_t)o * Cin + kk] : 0.f;
                Ws2[buf][kq * 4 + t][row] = make_float2(w, w);
            }
        }
        #pragma unroll
        for (int u = 0; u < 2; ++u) {
            int e = tid + 256 * u;
            int row = e >> 5, cq = e & 31;
            int kk = k0 + row;
            float4 v = (kk < Cin) ? *(const float4*)&Xb[(size_t)kk * N_ + p0 + cq * 4]
                                  : make_float4(0.f, 0.f, 0.f, 0.f);
            if (lnOn && kk < Cin) {
                int pix = p0 + cq * 4;
                float4 m  = *(const float4*)&lnMu[(size_t)bz * N_ + pix];
                float4 iv = *(const float4*)&lnInv[(size_t)bz * N_ + pix];
                float wv = lnW[kk], bv = lnB[kk];
                v.x = (v.x - m.x) * iv.x * wv + bv;
                v.y = (v.y - m.y) * iv.y * wv + bv;
                v.z = (v.z - m.z) * iv.z * wv + bv;
                v.w = (v.w - m.w) * iv.w * wv + bv;
            }
            *(float4*)&Xs[buf][row][cq * 4] = v;
        }
        __syncthreads();
        #pragma unroll
        for (int k = 0; k < 16; ++k) {
            ulonglong2 q0 = *(const ulonglong2*)&Xs[buf][k][tx * 4];
            ulonglong2 q1 = *(const ulonglong2*)&Xs[buf][k][64 + tx * 4];
            unsigned long long bb0 = q0.x, bb1 = q0.y, bb2 = q1.x, bb3 = q1.y;
            const ulonglong2* wrow = (const ulonglong2*)&Ws2[buf][k][ty * 8];
            ulonglong2 w01 = wrow[0], w23 = wrow[1], w45 = wrow[2], w67 = wrow[3];
            unsigned long long av[8] = {w01.x, w01.y, w23.x, w23.y,
                                        w45.x, w45.y, w67.x, w67.y};
            #pragma unroll
            for (int i = 0; i < 8; ++i) {
                FMA2(acc2[i][0], av[i], bb0);
                FMA2(acc2[i][1], av[i], bb1);
                FMA2(acc2[i][2], av[i], bb2);
                FMA2(acc2[i][3], av[i], bb3);
            }
        }
        __syncthreads();
    }

    const int doResid = flags & 1, doFinal = flags & 2;
    #pragma unroll
    for (int i = 0; i < 8; ++i) {
        int o = o0 + ty * 8 + i;
        if (o >= Cout) continue;
        size_t ybase0 = ((size_t)b * YCtot + Yoff + o) * N_ + p0 + tx * 4;
        float v[8];
        #pragma unroll
        for (int j = 0; j < 4; ++j) UNPK2(v[2 * j], v[2 * j + 1], acc2[i][j]);
        if (doResid) {
            size_t rbase = ((size_t)b * Cout + o) * N_ + p0 + tx * 4;
            float4 r0 = *(const float4*)&R[rbase];
            float4 r1 = *(const float4*)&R[rbase + 64];
            v[0] += r0.x; v[1] += r0.y; v[2] += r0.z; v[3] += r0.w;
            v[4] += r1.x; v[5] += r1.y; v[6] += r1.z; v[7] += r1.w;
        }
        if (doFinal) {
            #pragma unroll
            for (int j = 0; j < 8; ++j) v[j] = isfinite(v[j]) ? v[j] : 1e-5f;
        }
        *(float4*)&Y[ybase0]      = make_float4(v[0], v[1], v[2], v[3]);
        *(float4*)&Y[ybase0 + 64] = make_float4(v[4], v[5], v[6], v[7]);
    }
#endif
}

// ---------------- multi-o-tile GEMM (Cin=128, nch=2): B staged ONCE, A looped --------
__global__ void __launch_bounds__(256, 1)
gemmtc2(const uint8_t* __restrict__ Wt1, const float* __restrict__ X1, float* __restrict__ Y1,
        const uint8_t* __restrict__ Wt2, const float* __restrict__ X2, float* __restrict__ Y2,
        const float* __restrict__ W1, const float* __restrict__ W2,
        const float* __restrict__ lnMu, const float* __restrict__ lnInv,
        const float* __restrict__ lnW1, const float* __restrict__ lnB1,
        const float* __restrict__ lnW2, const float* __restrict__ lnB2,
        int Cout, int XCtot, int YCtot, int flags, int nOt)
{
    extern __shared__ __align__(1024) char smem[];
    const int bz = blockIdx.z;
    const int pth = bz >= B_;
    const int b = pth ? bz - B_ : bz;
    const int p0 = blockIdx.x * 128;
    const float* Xb = (pth ? X2 : X1) + (size_t)b * XCtot * N_;
    float* Y = pth ? Y2 : Y1;
    const float* lnW = pth ? lnW2 : lnW1;
    const float* lnB = pth ? lnB2 : lnB1;
    const int lnOn = flags & 4;
    const int tid = threadIdx.x;

#if HAS_TC && defined(__CUDA_ARCH__)
    const uint8_t* Wtb = pth ? Wt2 : Wt1;
    const uint32_t sb = smem_u32(smem);
    const int wid = tid >> 5;

    if (tid == 0) {
        MBARRIER_INIT(sb + SM_MBAR, 1);
        MBARRIER_INIT(sb + SM_MBAR + 8, 1);
    }
    if (wid == 0) TCGEN05_ALLOC(sb + SM_TMEM, 512);
    __syncthreads();
    uint32_t tmem;
    asm volatile("ld.shared.b32 %0, [%1];" : "=r"(tmem) : "r"(sb + SM_TMEM));

    // ---- stage B for BOTH chunks once (direct) ----
    {
        const int n = tid & 127, half = tid >> 7;
        float mun = 0.f, ivn = 1.f;
        if (lnOn) {
            mun = lnMu[(size_t)bz * N_ + p0 + n];
            ivn = lnInv[(size_t)bz * N_ + p0 + n];
        }
        #pragma unroll
        for (int ch = 0; ch < 2; ++ch) {
            char* bbase = smem + SM2_B + ch * 32768;
            stageB_direct(Xb, ch << 6, C_, p0, n, half, lnOn, mun, ivn, lnW, lnB,
                          bbase, bbase + 16384);
        }
    }

    // ---- loop output tiles: double-buffered A copy + MMAs ----
    int phA0 = 0, phA1 = 0;
    for (int ot = 0; ot < nOt; ++ot) {
        const int buf = ot & 1;
        if (ot >= 2) {
            if (buf == 0) { MBARRIER_WAIT_PARITY(sb + SM_MBAR, phA0); phA0 ^= 1; }
            else          { MBARRIER_WAIT_PARITY(sb + SM_MBAR + 8, phA1); phA1 ^= 1; }
        }
        {
            int otg = blockIdx.y * nOt + ot;
            const uint4* src = (const uint4*)(Wtb + (size_t)(otg * 2) * TILE_B);
            uint4* dst = (uint4*)(smem + SM2_A + buf * SM2_ABUF);
            #pragma unroll
            for (int i = 0; i < 16; ++i)
                dst[tid + 256 * i] = src[tid + 256 * i];
        }
        FENCE_ASYNC_SHARED();
        __syncthreads();
        if (tid == 0) {
            uint32_t en = 0;
            uint32_t d = tmem + ot * 128;
            #pragma unroll
            for (int ch = 0; ch < 2; ++ch) {
                uint64_t ah = make_desc(sb + SM2_A + buf * SM2_ABUF + ch * 32768);
                uint64_t al = ah + (16384 >> 4);
                uint64_t bh = make_desc(sb + SM2_B + ch * 32768);
                uint64_t bl = bh + (16384 >> 4);
                #pragma unroll
                for (int s = 0; s < 4; ++s) {
                    uint64_t ofs = s * 2;
                    mma_bf16_ss(d, ah + ofs, bh + ofs, en); en = 1;
                    mma_bf16_ss(d, ah + ofs, bl + ofs, 1);
                    mma_bf16_ss(d, al + ofs, bh + ofs, 1);
                }
            }
            TCGEN05_COMMIT(sb + SM_MBAR + buf * 8);
        }
    }

    // ---- drain ----
    {
        int lastb = (nOt - 1) & 1;
        if (lastb == 0) { MBARRIER_WAIT_PARITY(sb + SM_MBAR, phA0); }
        else            { MBARRIER_WAIT_PARITY(sb + SM_MBAR + 8, phA1); }
        if (nOt >= 2) {
            int prevb = (nOt - 2) & 1;
            if (prevb == 0) { MBARRIER_WAIT_PARITY(sb + SM_MBAR, phA0); }
            else            { MBARRIER_WAIT_PARITY(sb + SM_MBAR + 8, phA1); }
        }
    }
    TCGEN05_FENCE_AFTER();

    // ---- epilogue ----
    if (tid < 128) {
        int w = tid >> 5, l = tid & 31;
        for (int ot = 0; ot < nOt; ++ot) {
            int o = (blockIdx.y * nOt + ot) * 128 + w * 32 + l;
            #pragma unroll
            for (int g = 0; g < 4; ++g) {
                uint32_t dr[32];
                TCGEN05_LD_32X32B_X32(dr, tmem + ot * 128 + g * 32);
                TCGEN05_WAIT_LD();
                if (o < Cout) {
                    size_t ybase = ((size_t)b * YCtot + o) * N_ + p0 + g * 32;
                    #pragma unroll
                    for (int q = 0; q < 8; ++q) {
                        *(float4*)&Y[ybase + q * 4] = make_float4(
                            __uint_as_float(dr[q * 4 + 0]), __uint_as_float(dr[q * 4 + 1]),
                            __uint_as_float(dr[q * 4 + 2]), __uint_as_float(dr[q * 4 + 3]));
                    }
                }
            }
        }
        TCGEN05_FENCE_BEFORE();
    }

    __syncthreads();
    if (tid == 0) { MBARRIER_INVAL(sb + SM_MBAR); MBARRIER_INVAL(sb + SM_MBAR + 8); }
    __syncthreads();
    if (wid == 0) {
        TCGEN05_RELINQUISH();
        TCGEN05_DEALLOC(tmem, 512);
    }
#else
    // ================= FFMA2 fallback (compute_103 PTX pass) =================
    const float* Wb = pth ? W2 : W1;
    float2 (*Ws2)[16][128] = (float2(*)[16][128])(smem);
    float  (*Xs)[16][128]  = (float(*)[16][128])(smem + 32768);
    const int tx = tid & 15, ty = tid >> 4;

    for (int ot = 0; ot < nOt; ++ot) {
        const int o0 = (blockIdx.y * nOt + ot) * 128;
        unsigned long long acc2[8][4];
        #pragma unroll
        for (int i = 0; i < 8; ++i)
            #pragma unroll
            for (int j = 0; j < 4; ++j) acc2[i][j] = 0ULL;

        for (int kt = 0; kt < 8; ++kt) {
            int buf = kt & 1;
            int k0 = kt * 16;
            #pragma unroll
            for (int u = 0; u < 2; ++u) {
                int e4 = tid + 256 * u;
                int row = e4 & 127, kq = e4 >> 7;
                int o = o0 + row;
                #pragma unroll
                for (int t = 0; t < 4; ++t) {
                    int kk = k0 + kq * 4 + t;
                    float w = (o < Cout) ? Wb[(size_t)o * C_ + kk] : 0.f;
                    Ws2[buf][kq * 4 + t][row] = make_float2(w, w);
                }
            }
            #pragma unroll
            for (int u = 0; u < 2; ++u) {
                int e = tid + 256 * u;
                int row = e >> 5, cq = e & 31;
                int kk = k0 + row;
                float4 v = *(const float4*)&Xb[(size_t)kk * N_ + p0 + cq * 4];
                if (lnOn) {
                    int pix = p0 + cq * 4;
                    float4 m  = *(const float4*)&lnMu[(size_t)bz * N_ + pix];
                    float4 iv = *(const float4*)&lnInv[(size_t)bz * N_ + pix];
                    float wv = lnW[kk], bv = lnB[kk];
                    v.x = (v.x - m.x) * iv.x * wv + bv;
                    v.y = (v.y - m.y) * iv.y * wv + bv;
                    v.z = (v.z - m.z) * iv.z * wv + bv;
                    v.w = (v.w - m.w) * iv.w * wv + bv;
                }
                *(float4*)&Xs[buf][row][cq * 4] = v;
            }
            __syncthreads();
            #pragma unroll
            for (int k = 0; k < 16; ++k) {
                ulonglong2 q0 = *(const ulonglong2*)&Xs[buf][k][tx * 4];
                ulonglong2 q1 = *(const ulonglong2*)&Xs[buf][k][64 + tx * 4];
                unsigned long long bb0 = q0.x, bb1 = q0.y, bb2 = q1.x, bb3 = q1.y;
                const ulonglong2* wrow = (const ulonglong2*)&Ws2[buf][k][ty * 8];
                ulonglong2 w01 = wrow[0], w23 = wrow[1], w45 = wrow[2], w67 = wrow[3];
                unsigned long long av[8] = {w01.x, w01.y, w23.x, w23.y,
                                            w45.x, w45.y, w67.x, w67.y};
                #pragma unroll
                for (int i = 0; i < 8; ++i) {
                    FMA2(acc2[i][0], av[i], bb0);
                    FMA2(acc2[i][1], av[i], bb1);
                    FMA2(acc2[i][2], av[i], bb2);
                    FMA2(acc2[i][3], av[i], bb3);
                }
            }
            __syncthreads();
        }

        #pragma unroll
        for (int i = 0; i < 8; ++i) {
            int o = o0 + ty * 8 + i;
            if (o >= Cout) continue;
            size_t ybase0 = ((size_t)b * YCtot + o) * N_ + p0 + tx * 4;
            float v[8];
            #pragma unroll
            for (int j = 0; j < 4; ++j) UNPK2(v[2 * j], v[2 * j + 1], acc2[i][j]);
            *(float4*)&Y[ybase0]      = make_float4(v[0], v[1], v[2], v[3]);
            *(float4*)&Y[ybase0 + 64] = make_float4(v[4], v[5], v[6], v[7]);
        }
        __syncthreads();
    }
#endif
}

// ---------------- per-pixel LN stats, both paths in one launch ----------------
__global__ void lnstats2k(const float* __restrict__ X1, const float* __restrict__ X2,
                          float* __restrict__ mu, float* __restrict__ inv)
{
    int p = blockIdx.x * 256 + threadIdx.x;
    int zc = blockIdx.y;
    int pth = zc >= B_;
    int b = pth ? zc - B_ : zc;
    const float* xb = (pth ? X2 : X1) + (size_t)b * C_ * N_ + p;
    float s = 0.f, ss = 0.f;
    #pragma unroll 4
    for (int c = 0; c < C_; ++c) {
        float v = xb[(size_t)c * N_];
        s += v; ss += v * v;
    }
    float m = s * (1.f / C_);
    float var = ss * (1.f / C_) - m * m;
    mu[(size_t)zc * N_ + p] = m;
    inv[(size_t)zc * N_ + p] = rsqrtf(var + 1e-5f);
}

// ---------------- fused: x_out = fuse*ca + origin ; write x_out + LN stats ----------------
__global__ void scaleaddstatsk(const float* __restrict__ fuse, const float* __restrict__ cas,
                               const float* __restrict__ origin, float* __restrict__ Y,
                               float* __restrict__ mu, float* __restrict__ inv)
{
    int p = blockIdx.x * 256 + threadIdx.x;
    int b = blockIdx.y;
    __shared__ float sc[C_];
    for (int i = threadIdx.x; i < C_; i += 256) sc[i] = cas[b * C_ + i];
    __syncthreads();
    const size_t base = (size_t)b * C_ * N_ + p;
    float s = 0.f, ss = 0.f;
    #pragma unroll 4
    for (int c = 0; c < C_; ++c) {
        float v = fuse[base + (size_t)c * N_] * sc[c] + origin[base + (size_t)c * N_];
        Y[base + (size_t)c * N_] = v;
        s += v; ss += v * v;
    }
    float m = s * (1.f / C_);
    float var = ss * (1.f / C_) - m * m;
    mu[b * N_ + p] = m;
    inv[b * N_ + p] = rsqrtf(var + 1e-5f);
}

// ---------------- depthwise 3x3 for kv only (2C channels), both paths ----------------
__global__ void dwkvk(const float* __restrict__ kX1, const float* __restrict__ kX2,
                      const float* __restrict__ kW1, const float* __restrict__ kW2,
                      float* __restrict__ kY1, float* __restrict__ kY2)
{
    int c = blockIdx.y;
    int zc = blockIdx.z;
    int pth = zc >= B_;
    int b = pth ? zc - B_ : zc;
    const float* xb = (pth ? kX2 : kX1) + ((size_t)b * C2_ + c) * N_;
    const float* Wd = (pth ? kW2 : kW1);
    float* yb = (pth ? kY2 : kY1) + ((size_t)b * C2_ + c) * N_;

    int y0 = blockIdx.x * 8;
    int tid = threadIdx.x;
    __shared__ float t[10][128];
    for (int i = tid; i < 320; i += 256) {
        int r = i >> 5, xq = i & 31;
        int yy = y0 - 1 + r;
        float4 v = make_float4(0.f, 0.f, 0.f, 0.f);
        if (yy >= 0 && yy < Hh_) v = *(const float4*)&xb[yy * 128 + xq * 4];
        *(float4*)&t[r][xq * 4] = v;
    }
    float w[9];
    #pragma unroll
    for (int q = 0; q < 9; ++q) w[q] = Wd[c * 9 + q];
    __syncthreads();
    int r = tid >> 5;
    int lx = tid & 31;
    float* yo = yb + (y0 + r) * 128;
    #pragma unroll
    for (int u = 0; u < 4; ++u) {
        int x = u * 32 + lx;
        float s = 0.f;
        #pragma unroll
        for (int dy = 0; dy < 3; ++dy) {
            const float* row = t[r + dy];
            float m  = row[x];
            float l  = (x > 0)   ? row[x - 1] : 0.f;
            float rr = (x < 127) ? row[x + 1] : 0.f;
            s += l * w[dy * 3] + m * w[dy * 3 + 1] + rr * w[dy * 3 + 2];
        }
        yo[x] = s;
    }
}

// ---------------- fused FFN dwconv(680) + gelu-gate -> 340 (smem-tiled) ----------------
__global__ void dwgatek(const float* __restrict__ X, const float* __restrict__ Wd,
                        float* __restrict__ Y)
{
    int c = blockIdx.y, b = blockIdx.z;
    int y0 = blockIdx.x * 8;
    int tid = threadIdx.x;
    const float* x1b = X + ((size_t)b * HID2_ + c) * N_;
    const float* x2b = X + ((size_t)b * HID2_ + c + HID_) * N_;
    __shared__ float t1[10][128];
    __shared__ float t2[10][128];
    for (int i = tid; i < 320; i += 256) {
        int r = i >> 5, xq = i & 31;
        int yy = y0 - 1 + r;
        float4 v1 = make_float4(0.f, 0.f, 0.f, 0.f);
        float4 v2 = v1;
        if (yy >= 0 && yy < Hh_) {
            v1 = *(const float4*)&x1b[yy * 128 + xq * 4];
            v2 = *(const float4*)&x2b[yy * 128 + xq * 4];
        }
        *(float4*)&t1[r][xq * 4] = v1;
        *(float4*)&t2[r][xq * 4] = v2;
    }
    float w1[9], w2[9];
    #pragma unroll
    for (int q = 0; q < 9; ++q) { w1[q] = Wd[c * 9 + q]; w2[q] = Wd[(c + HID_) * 9 + q]; }
    __syncthreads();
    int r = tid >> 5;
    int lx = tid & 31;
    float* yo = Y + ((size_t)b * HID_ + c) * N_ + (y0 + r) * 128;
    #pragma unroll
    for (int u = 0; u < 4; ++u) {
        int x = u * 32 + lx;
        float s1 = 0.f, s2 = 0.f;
        #pragma unroll
        for (int dy = 0; dy < 3; ++dy) {
            const float* r1 = t1[r + dy];
            const float* r2 = t2[r + dy];
            float m1  = r1[x],  m2  = r2[x];
            float l1  = (x > 0)   ? r1[x - 1] : 0.f;
            float l2  = (x > 0)   ? r2[x - 1] : 0.f;
            float rr1 = (x < 127) ? r1[x + 1] : 0.f;
            float rr2 = (x < 127) ? r2[x + 1] : 0.f;
            s1 += l1 * w1[dy * 3] + m1 * w1[dy * 3 + 1] + rr1 * w1[dy * 3 + 2];
            s2 += l2 * w2[dy * 3] + m2 * w2[dy * 3 + 1] + rr2 * w2[dy * 3 + 2];
        }
        float ge = 0.5f * s1 * (1.f + erff(s1 * 0.70710678118654752f));
        yo[x] = ge * s2;
    }
}

// ---------------- FUSED q-dwconv + attention partials (per chunk of 8 image rows) ---------
__global__ void attnfusek(const float* __restrict__ Q1, const float* __restrict__ Q2,
                          const float* __restrict__ dw1, const float* __restrict__ dw2,
                          const float* __restrict__ KV1, const float* __restrict__ KV2,
                          float* __restrict__ part)
{
    int chunk = blockIdx.x, h = blockIdx.y;
    int zc = blockIdx.z;
    int pth = zc >= B_;
    int b = pth ? zc - B_ : zc;
    const float* qb = (pth ? Q2 : Q1)  + ((size_t)b * C_  + h * CH_) * N_;
    const float* kb = (pth ? KV2 : KV1) + ((size_t)b * C2_ + h * CH_) * N_;
    const float* wd = (pth ? dw2 : dw1) + h * CH_ * 9;

    __shared__ float qrow[3][16][132];
    __shared__ float qs[16][132];
    __shared__ float ks[16][132];
    __shared__ float wdw[16][9];
    __shared__ float qqp[256], kkp[256];

    int tid = threadIdx.x;
    if (tid < 144) wdw[tid / 9][tid % 9] = wd[tid];

    const int ch = tid >> 4;
    const int grp = tid & 15;
    const int x0 = grp * 8;
    const int y0 = chunk * 8;

    #pragma unroll
    for (int pr = 0; pr < 2; ++pr) {
        int g = y0 - 1 + pr;
        int slot = (g + 1) % 3;
        float4 v0 = make_float4(0.f, 0.f, 0.f, 0.f), v1 = v0;
        if (g >= 0 && g < Hh_) {
            v0 = *(const float4*)&qb[(size_t)ch * N_ + g * 128 + x0];
            v1 = *(const float4*)&qb[(size_t)ch * N_ + g * 128 + x0 + 4];
        }
        *(float4*)&qrow[slot][ch][x0] = v0;
        *(float4*)&qrow[slot][ch][x0 + 4] = v1;
    }

    float acc[16];
    #pragma unroll
    for (int j = 0; j < 16; ++j) acc[j] = 0.f;
    float qq = 0.f, kk = 0.f;

    for (int r = 0; r < 8; ++r) {
        int y = y0 + r;
        {
            int g = y + 1;
            int slot = (g + 1) % 3;
            float4 v0 = make_float4(0.f, 0.f, 0.f, 0.f), v1 = v0;
            if (g < Hh_) {
                v0 = *(const float4*)&qb[(size_t)ch * N_ + g * 128 + x0];
                v1 = *(const float4*)&qb[(size_t)ch * N_ + g * 128 + x0 + 4];
            }
            *(float4*)&qrow[slot][ch][x0] = v0;
            *(float4*)&qrow[slot][ch][x0 + 4] = v1;
            float4 k0 = *(const float4*)&kb[(size_t)ch * N_ + y * 128 + x0];
            float4 k1 = *(const float4*)&kb[(size_t)ch * N_ + y * 128 + x0 + 4];
            *(float4*)&ks[ch][x0] = k0;
            *(float4*)&ks[ch][x0 + 4] = k1;
            kk += k0.x * k0.x + k0.y * k0.y + k0.z * k0.z + k0.w * k0.w;
            kk += k1.x * k1.x + k1.y * k1.y + k1.z * k1.z + k1.w * k1.w;
        }
        __syncthreads();
        {
            const float* r0 = qrow[(y)     % 3][ch];
            const float* r1 = qrow[(y + 1) % 3][ch];
            const float* r2 = qrow[(y + 2) % 3][ch];
            const float* w = wdw[ch];
            #pragma unroll
            for (int t = 0; t < 8; ++t) {
                int x = x0 + t;
                float l0 = (x > 0)   ? r0[x - 1] : 0.f;
                float l1 = (x > 0)   ? r1[x - 1] : 0.f;
                float l2 = (x > 0)   ? r2[x - 1] : 0.f;
                float rr0 = (x < 127) ? r0[x + 1] : 0.f;
                float rr1 = (x < 127) ? r1[x + 1] : 0.f;
                float rr2 = (x < 127) ? r2[x + 1] : 0.f;
                float o = l0 * w[0] + r0[x] * w[1] + rr0 * w[2]
                        + l1 * w[3] + r1[x] * w[4] + rr1 * w[5]
                        + l2 * w[6] + r2[x] * w[7] + rr2 * w[8];
                qs[ch][x] = o;
                qq += o * o;
            }
        }
        __syncthreads();
        {
            int i = tid & 15, s = tid >> 4;
            #pragma unroll
            for (int t = 0; t < 8; ++t) {
                float qv = qs[i][s * 8 + t];
                #pragma unroll
                for (int j = 0; j < 16; ++j) acc[j] += qv * ks[j][s * 8 + t];
            }
        }
        __syncthreads();
    }

    qqp[tid] = qq;
    kkp[tid] = kk;
    float* smg = &qrow[0][0][0];
    {
        int i = tid & 15, s = tid >> 4;
        #pragma unroll
        for (int j = 0; j < 16; ++j) smg[s * 256 + i * 16 + j] = acc[j];
    }
    __syncthreads();

    float* pb = part + (((size_t)zc * HEADS_ + h) * NCHUNK_ + chunk) * 288;
    int i2 = tid >> 4, j2 = tid & 15;
    float a = 0.f;
    #pragma unroll
    for (int s2 = 0; s2 < 16; ++s2) a += smg[s2 * 256 + i2 * 16 + j2];
    pb[i2 * 16 + j2] = a;
    if (tid < 16) {
        float t0 = 0.f;
        #pragma unroll
        for (int g = 0; g < 16; ++g) t0 += qqp[tid * 16 + g];
        pb[256 + tid] = t0;
    } else if (tid < 32) {
        int j = tid - 16;
        float t0 = 0.f;
        #pragma unroll
        for (int g = 0; g < 16; ++g) t0 += kkp[j * 16 + g];
        pb[272 + j] = t0;
    }
}

// ---------------- attention finalize, both paths ----------------
__global__ void attnfink(const float* __restrict__ part, const float* __restrict__ temp1,
                         const float* __restrict__ temp2, float* __restrict__ attnOut)
{
    int h = blockIdx.x;
    int zc = blockIdx.y;
    int pth = zc >= B_;
    const float* temp = pth ? temp2 : temp1;
    const float* pb = part + ((size_t)zc * HEADS_ + h) * NCHUNK_ * 288;
    __shared__ float qqs[16], kks[16];
    int tid = threadIdx.x;

    float a = 0.f;
    #pragma unroll
    for (int c = 0; c < NCHUNK_; ++c) a += pb[c * 288 + tid];

    if (tid < 16) {
        float t0 = 0.f;
        #pragma unroll
        for (int c = 0; c < NCHUNK_; ++c) t0 += pb[c * 288 + 256 + tid];
        qqs[tid] = fmaxf(sqrtf(t0), 1e-12f);
    } else if (tid < 32) {
        int j = tid - 16;
        float t0 = 0.f;
        #pragma unroll
        for (int c = 0; c < NCHUNK_; ++c) t0 += pb[c * 288 + 272 + j];
        kks[j] = fmaxf(sqrtf(t0), 1e-12f);
    }
    __syncthreads();

    int i2 = tid >> 4, j2 = tid & 15;
    a = a / (qqs[i2] * kks[j2]) * temp[h];

    unsigned mask = 0xFFFFFFFFu;
    float mx = a;
    for (int w = 8; w > 0; w >>= 1) mx = fmaxf(mx, __shfl_xor_sync(mask, mx, w, 16));
    float e = expf(a - mx);
    float ssum = e;
    for (int w = 8; w > 0; w >>= 1) ssum += __shfl_xor_sync(mask, ssum, w, 16);
    attnOut[((size_t)zc * HEADS_ + h) * 256 + i2 * 16 + j2] = e / ssum;
}

// ---------------- M[zc] = po @ blockdiag(attn[zc]); fp32 + pre-swizzled tiles ----------------
__global__ void poattnk(const float* __restrict__ po1, const float* __restrict__ po2,
                        const float* __restrict__ attn, float* __restrict__ M,
                        uint8_t* __restrict__ MT)
{
    int zc = blockIdx.x;
    const float* po = (zc >= B_) ? po2 : po1;
    uint8_t* mt = MT + (size_t)zc * 2 * TILE_B;
    __shared__ float at[HEADS_ * 256];
    for (int i = threadIdx.x; i < HEADS_ * 256; i += 256)
        at[i] = attn[(size_t)zc * HEADS_ * 256 + i];
    __syncthreads();
    for (int idx2 = threadIdx.x; idx2 < C_ * 64; idx2 += 256) {
        int o = idx2 >> 6, j2 = idx2 & 63;
        int cj = 2 * j2;
        int h = cj >> 4;
        int jj = cj & 15;
        float s0 = 0.f, s1 = 0.f;
        #pragma unroll
        for (int i = 0; i < 16; ++i) {
            float pv = po[o * C_ + h * 16 + i];
            s0 += pv * at[h * 256 + i * 16 + jj];
            s1 += pv * at[h * 256 + i * 16 + jj + 1];
        }
        M[((size_t)zc * C_ + o) * C_ + cj] = s0;
        M[((size_t)zc * C_ + o) * C_ + cj + 1] = s1;
        uint32_t hp, lp;
        split2(s0, s1, hp, lp);
        int chk = cj >> 6;
        uint32_t off = SWZ((uint32_t)(o * 128 + (cj & 63) * 2));
        *(uint32_t*)(mt + chk * TILE_B + off) = hp;
        *(uint32_t*)(mt + chk * TILE_B + 16384 + off) = lp;
    }
}

// ---------------- global average pool per (b,c) ----------------
__global__ void capoolk(const float* __restrict__ X, float* __restrict__ pool)
{
    int c = blockIdx.x, b = blockIdx.y;
    const float* xb = X + ((size_t)b * C_ + c) * N_;
    float s = 0.f;
    for (int n = threadIdx.x * 4; n < N_; n += 1024) {
        float4 v = *(const float4*)&xb[n];
        s += v.x + v.y + v.z + v.w;
    }
    __shared__ float red[256];
    red[threadIdx.x] = s; __syncthreads();
    for (int st = 128; st > 0; st >>= 1) {
        if (threadIdx.x < st) red[threadIdx.x] += red[threadIdx.x + st];
        __syncthreads();
    }
    if (threadIdx.x == 0) pool[b * C_ + c] = red[0] * (1.f / N_);
}

// ---------------- CA: relu FC (128->8) + sigmoid FC (8->128) ----------------
__global__ void cafck(const float* __restrict__ pool,
                      const float* __restrict__ w1, const float* __restrict__ b1,
                      const float* __restrict__ w2, const float* __restrict__ b2,
                      float* __restrict__ cas)
{
    int b = blockIdx.x, t = threadIdx.x;
    __shared__ float pl[C_];
    __shared__ float hid[8];
    pl[t] = pool[b * C_ + t];
    __syncthreads();
    if (t < 8) {
        float s = b1[t];
        #pragma unroll 4
        for (int c = 0; c < C_; ++c) s += w1[t * C_ + c] * pl[c];
        hid[t] = fmaxf(s, 0.f);
    }
    __syncthreads();
    float s = b2[t];
    #pragma unroll
    for (int r = 0; r < 8; ++r) s += w2[t * 8 + r] * hid[r];
    cas[b * C_ + t] = 1.f / (1.f + expf(-s));
}

// ---------------- host ----------------
extern "C" void kernel_launch(void* const* d_in, const int* in_sizes, int n_in,
                              void* d_out, int out_size)
{
    (void)in_sizes; (void)n_in; (void)out_size;
    const float* origin  = (const float*)d_in[0];
    const float* low     = (const float*)d_in[1];
    const float* high    = (const float*)d_in[2];
    const float* norm1_w = (const float*)d_in[3];
    const float* norm1_b = (const float*)d_in[4];
    const float* norm_1_w= (const float*)d_in[5];
    const float* norm_1_b= (const float*)d_in[6];
    const float* norm2_w = (const float*)d_in[7];
    const float* norm2_b = (const float*)d_in[8];
    const float* a1_q    = (const float*)d_in[9];
    const float* a1_qdw  = (const float*)d_in[10];
    const float* a1_kv   = (const float*)d_in[11];
    const float* a1_kvdw = (const float*)d_in[12];
    const float* a1_po   = (const float*)d_in[13];
    const float* a1_temp = (const float*)d_in[14];
    const float* a2_q    = (const float*)d_in[15];
    const float* a2_qdw  = (const float*)d_in[16];
    const float* a2_kv   = (const float*)d_in[17];
    const float* a2_kvdw = (const float*)d_in[18];
    const float* a2_po   = (const float*)d_in[19];
    const float* a2_temp = (const float*)d_in[20];
    const float* conv1_w = (const float*)d_in[21];
    const float* ca1_w   = (const float*)d_in[22];
    const float* ca1_b   = (const float*)d_in[23];
    const float* ca2_w   = (const float*)d_in[24];
    const float* ca2_b   = (const float*)d_in[25];
    const float* ffn_pi  = (const float*)d_in[26];
    const float* ffn_dw  = (const float*)d_in[27];
    const float* ffn_po  = (const float*)d_in[28];
    float* out = (float*)d_out;

    float *bufCb, *bufCc, *buf2Ca, *buf2Cb, *buf2Cc, *bufHa, *bufHb, *xout;
    float *mu, *inv, *attnp, *attnw, *Mw, *pool, *cas;
    uint8_t *wt, *MwT;
    cudaGetSymbolAddress((void**)&bufCb, g_bufCb);
    cudaGetSymbolAddress((void**)&bufCc, g_bufCc);
    cudaGetSymbolAddress((void**)&buf2Ca, g_buf2Ca);
    cudaGetSymbolAddress((void**)&buf2Cb, g_buf2Cb);
    cudaGetSymbolAddress((void**)&buf2Cc, g_buf2Cc);
    cudaGetSymbolAddress((void**)&bufHa, g_bufHa);
    cudaGetSymbolAddress((void**)&bufHb, g_bufHb);
    cudaGetSymbolAddress((void**)&xout, g_xout);
    cudaGetSymbolAddress((void**)&mu, g_mu);
    cudaGetSymbolAddress((void**)&inv, g_inv);
    cudaGetSymbolAddress((void**)&attnp, g_attnp);
    cudaGetSymbolAddress((void**)&attnw, g_attnw);
    cudaGetSymbolAddress((void**)&Mw, g_Mw);
    cudaGetSymbolAddress((void**)&pool, g_pool);
    cudaGetSymbolAddress((void**)&cas, g_cas);
    cudaGetSymbolAddress((void**)&wt, g_wt);
    cudaGetSymbolAddress((void**)&MwT, g_MwT);

    static int smem_set = 0;
    if (!smem_set) {
        cudaFuncSetAttribute(gemmtc, cudaFuncAttributeMaxDynamicSharedMemorySize, SM_TOTAL);
        cudaFuncSetAttribute(gemmtc2, cudaFuncAttributeMaxDynamicSharedMemorySize, SM2_TOTAL);
        smem_set = 1;
    }

    // tile offsets (in tiles of TILE_B bytes) — must match wtileall bases
    uint8_t* t_a1q  = wt;                 // 2 tiles
    uint8_t* t_a2q  = wt + 2  * TILE_B;   // 2
    uint8_t* t_a1kv = wt + 4  * TILE_B;   // 4
    uint8_t* t_a2kv = wt + 8  * TILE_B;   // 4
    uint8_t* t_cv1  = wt + 12 * TILE_B;   // 4
    uint8_t* t_fpi  = wt + 16 * TILE_B;   // 12
    uint8_t* t_fpo  = wt + 28 * TILE_B;   // 6

    dim3 tb(256);
    // ===== weight pre-tiling: ONE launch =====
    wtileall<<<dim3(34), tb>>>(a1_q, a2_q, a1_kv, a2_kv, conv1_w, ffn_pi, ffn_po, wt);

    dim3 gLN2(N_ / 256, 2 * B_);
    dim3 gLN(N_ / 256, B_);
    dim3 gQ(N_ / 128, 1, 2 * B_);
    dim3 gKV2(N_ / 128, 1, 2 * B_);
    dim3 gMv(N_ / 128, 1, 2 * B_);
    dim3 gG_C(N_ / 128, 1, B_);
    dim3 gFpi(N_ / 128, 2, B_);
    dim3 gRow(C_, B_);
    dim3 gAttnP(NCHUNK_, HEADS_, 2 * B_);
    dim3 gAttnF(HEADS_, 2 * B_);
    dim3 gDWkv(Hh_ / 8, C2_, 2 * B_);
    dim3 gDW_H(Hh_ / 8, HID_, B_);

    // ===== both attention paths, merged launches =====
    gemmtc<<<gQ, tb, SM_TOTAL>>>(t_a1q, high, bufCb, nullptr,
                                 t_a2q, low, bufCc, nullptr,
                                 a1_q, a2_q,
                                 nullptr, nullptr, nullptr, nullptr, nullptr, nullptr,
                                 C_, C_, C_, C_, 0, 0, 0, 0, 0);
    lnstats2k<<<gLN2, tb>>>(low, high, mu, inv);
    gemmtc2<<<gKV2, tb, SM2_TOTAL>>>(t_a1kv, low, buf2Ca,
                                     t_a2kv, high, buf2Cb,
                                     a1_kv, a2_kv,
                                     mu, inv, norm1_w, norm1_b, norm_1_w, norm_1_b,
                                     C2_, C_, C2_, 4, 2);
    dwkvk<<<gDWkv, tb>>>(buf2Ca, buf2Cb, a1_kvdw, a2_kvdw, buf2Cc, bufHa);
    attnfusek<<<gAttnP, tb>>>(bufCb, bufCc, a1_qdw, a2_qdw, buf2Cc, bufHa, attnp);
    attnfink<<<gAttnF, tb>>>(attnp, a1_temp, a2_temp, attnw);
    poattnk<<<dim3(2 * B_), tb>>>(a1_po, a2_po, attnw, Mw, MwT);
    gemmtc<<<gMv, tb, SM_TOTAL>>>(MwT, buf2Cc + (size_t)C_ * N_, buf2Ca, low,
                                  MwT + (size_t)B_ * 2 * TILE_B, bufHa + (size_t)C_ * N_, buf2Ca, high,
                                  Mw, Mw + (size_t)B_ * C_ * C_,
                                  nullptr, nullptr, nullptr, nullptr, nullptr, nullptr,
                                  C_, C_, C2_, C2_, 0, C_, 1, 2, C_ * C_);

    // ===== fuse: conv1(concat) -> CA -> + origin, fused with norm2 stats =====
    gemmtc<<<gG_C, tb, SM_TOTAL>>>(t_cv1, buf2Ca, bufCb, nullptr,
                                   t_cv1, buf2Ca, bufCb, nullptr,
                                   conv1_w, conv1_w,
                                   nullptr, nullptr, nullptr, nullptr, nullptr, nullptr,
                                   C_, C2_, C2_, C_, 0, 0, 0, 0, 0);
    capoolk<<<gRow, tb>>>(bufCb, pool);
    cafck<<<dim3(B_), dim3(128)>>>(pool, ca1_w, ca1_b, ca2_w, ca2_b, cas);
    scaleaddstatsk<<<gLN, tb>>>(bufCb, cas, origin, xout, mu, inv);

    // ===== FFN with residual =====
    gemmtc2<<<gFpi, tb, SM2_TOTAL>>>(t_fpi, xout, bufHa,
                                     t_fpi, xout, bufHa,
                                     ffn_pi, ffn_pi,
                                     mu, inv, norm2_w, norm2_b, norm2_w, norm2_b,
                                     HID2_, C_, HID2_, 4, 3);
    dwgatek<<<gDW_H, tb>>>(bufHa, ffn_dw, bufHb);
    gemmtc<<<gG_C, tb, SM_TOTAL>>>(t_fpo, bufHb, out, xout,
                                   t_fpo, bufHb, out, xout,
                                   ffn_po, ffn_po,
                                   nullptr, nullptr, nullptr, nullptr, nullptr, nullptr,
                                   C_, HID_, HID_, C_, 0, 0, 3, 0, 0);
}